// round 1
// baseline (speedup 1.0000x reference)
#include <cuda_runtime.h>
#include <math.h>

#define D_MODEL 1024
#define NH      16
#define DK      64
#define DFF     4096
#define BATCH   2
#define SEQ     2048
#define MROWS   (BATCH*SEQ)   // 4096

// ---------------- scratch (device globals; no allocation allowed) ----------
__device__ float g_xln [MROWS*D_MODEL];
__device__ float g_q   [MROWS*D_MODEL];
__device__ float g_k   [MROWS*D_MODEL];
__device__ float g_v   [MROWS*D_MODEL];
__device__ float g_ctx [MROWS*D_MODEL];
__device__ float g_out1[MROWS*D_MODEL];
__device__ float g_x2  [MROWS*D_MODEL];
__device__ float g_ffh [MROWS*DFF];

// ---------------- LayerNorm (torch semantics: ddof=1, eps added to std) ----
__global__ void __launch_bounds__(256) ln_kernel(
    const float* __restrict__ x, float* __restrict__ y,
    const float* __restrict__ alpha, const float* __restrict__ beta)
{
    int row = blockIdx.x;
    const float4* xr = (const float4*)(x + (size_t)row * D_MODEL);
    float4 v = xr[threadIdx.x];
    float s  = v.x + v.y + v.z + v.w;
    float sq = v.x*v.x + v.y*v.y + v.z*v.z + v.w*v.w;

    __shared__ float red[18];
    #pragma unroll
    for (int o = 16; o; o >>= 1) {
        s  += __shfl_xor_sync(0xffffffffu, s,  o);
        sq += __shfl_xor_sync(0xffffffffu, sq, o);
    }
    int w = threadIdx.x >> 5;
    if ((threadIdx.x & 31) == 0) { red[w] = s; red[8 + w] = sq; }
    __syncthreads();
    if (threadIdx.x == 0) {
        float ts = 0.f, tq = 0.f;
        #pragma unroll
        for (int i = 0; i < 8; i++) { ts += red[i]; tq += red[8 + i]; }
        red[16] = ts; red[17] = tq;
    }
    __syncthreads();
    float ts = red[16], tq = red[17];

    float mean = ts * (1.0f / D_MODEL);
    float var  = (tq - ts * mean) * (1.0f / (D_MODEL - 1));
    var = fmaxf(var, 0.0f);
    float denom = sqrtf(var) + 1e-6f;
    float a  = alpha[0], be = beta[0];
    float r  = a / denom;

    float4 o;
    o.x = (v.x - mean) * r + be;
    o.y = (v.y - mean) * r + be;
    o.z = (v.z - mean) * r + be;
    o.w = (v.w - mean) * r + be;
    ((float4*)(y + (size_t)row * D_MODEL))[threadIdx.x] = o;
}

// ---------------- SGEMM: C[M,N] = A[M,K] * B[N,K]^T  (+ epilogue) ----------
// EPI: 0 = none, 1 = bias+relu, 2 = bias+residual, 3 = residual
#define BM 128
#define BN 128
#define BK 16

template<int EPI>
__global__ void __launch_bounds__(256) sgemm_abt(
    const float* __restrict__ A, const float* __restrict__ B,
    float* __restrict__ C, const float* __restrict__ bias,
    const float* __restrict__ res, int M, int N, int K)
{
    __shared__ float As[BK][BM + 4];
    __shared__ float Bs[BK][BN + 4];

    int tid = threadIdx.x;
    int tx  = tid & 15, ty = tid >> 4;
    int rowBase = blockIdx.y * BM;
    int colBase = blockIdx.x * BN;

    float acc[8][8];
    #pragma unroll
    for (int i = 0; i < 8; i++)
        #pragma unroll
        for (int j = 0; j < 8; j++) acc[i][j] = 0.f;

    int lr  = tid >> 2;          // 0..63
    int lc4 = (tid & 3) * 4;     // 0,4,8,12
    const float* Aptr = A + (size_t)(rowBase + lr) * K + lc4;
    const float* Bptr = B + (size_t)(colBase + lr) * K + lc4;

    for (int k0 = 0; k0 < K; k0 += BK) {
        float4 a0 = *(const float4*)(Aptr);
        float4 a1 = *(const float4*)(Aptr + (size_t)64 * K);
        float4 b0 = *(const float4*)(Bptr);
        float4 b1 = *(const float4*)(Bptr + (size_t)64 * K);
        __syncthreads();
        As[lc4+0][lr] = a0.x; As[lc4+1][lr] = a0.y; As[lc4+2][lr] = a0.z; As[lc4+3][lr] = a0.w;
        As[lc4+0][lr+64] = a1.x; As[lc4+1][lr+64] = a1.y; As[lc4+2][lr+64] = a1.z; As[lc4+3][lr+64] = a1.w;
        Bs[lc4+0][lr] = b0.x; Bs[lc4+1][lr] = b0.y; Bs[lc4+2][lr] = b0.z; Bs[lc4+3][lr] = b0.w;
        Bs[lc4+0][lr+64] = b1.x; Bs[lc4+1][lr+64] = b1.y; Bs[lc4+2][lr+64] = b1.z; Bs[lc4+3][lr+64] = b1.w;
        __syncthreads();

        #pragma unroll
        for (int kk = 0; kk < BK; kk++) {
            float ra[8], rb[8];
            *(float4*)(ra)     = *(const float4*)&As[kk][ty * 8];
            *(float4*)(ra + 4) = *(const float4*)&As[kk][ty * 8 + 4];
            *(float4*)(rb)     = *(const float4*)&Bs[kk][tx * 8];
            *(float4*)(rb + 4) = *(const float4*)&Bs[kk][tx * 8 + 4];
            #pragma unroll
            for (int i = 0; i < 8; i++)
                #pragma unroll
                for (int j = 0; j < 8; j++)
                    acc[i][j] += ra[i] * rb[j];
        }
        Aptr += BK;
        Bptr += BK;
    }

    int row0 = rowBase + ty * 8;
    int col0 = colBase + tx * 8;
    #pragma unroll
    for (int i = 0; i < 8; i++) {
        int row = row0 + i;
        #pragma unroll
        for (int jj = 0; jj < 2; jj++) {
            int col = col0 + jj * 4;
            float4 o;
            o.x = acc[i][jj*4+0]; o.y = acc[i][jj*4+1];
            o.z = acc[i][jj*4+2]; o.w = acc[i][jj*4+3];
            if (EPI == 1) {
                float4 bi = *(const float4*)&bias[col];
                o.x = fmaxf(o.x + bi.x, 0.f); o.y = fmaxf(o.y + bi.y, 0.f);
                o.z = fmaxf(o.z + bi.z, 0.f); o.w = fmaxf(o.w + bi.w, 0.f);
            } else if (EPI == 2) {
                float4 bi = *(const float4*)&bias[col];
                float4 rr = *(const float4*)&res[(size_t)row * N + col];
                o.x += bi.x + rr.x; o.y += bi.y + rr.y;
                o.z += bi.z + rr.z; o.w += bi.w + rr.w;
            } else if (EPI == 3) {
                float4 rr = *(const float4*)&res[(size_t)row * N + col];
                o.x += rr.x; o.y += rr.y; o.z += rr.z; o.w += rr.w;
            }
            *(float4*)&C[(size_t)row * N + col] = o;
        }
    }
}

// ---------------- Fused flash attention (fp32, 64x64 tiles) ---------------
#define APITCH 68

__global__ void __launch_bounds__(256) attn_kernel(
    const float* __restrict__ q, const float* __restrict__ k,
    const float* __restrict__ v, const int* __restrict__ mask,
    float* __restrict__ ctx)
{
    extern __shared__ float sm[];
    float* Qs = sm;                    // [64][APITCH]  q rows x d
    float* Kt = Qs + 64 * APITCH;      // [64][APITCH]  d x kv (transposed)
    float* Vs = Kt + 64 * APITCH;      // [64][APITCH]  kv x d
    float* Ps = Vs + 64 * APITCH;      // [64][APITCH]  q x kv probs
    int*   ms = (int*)(Ps + 64 * APITCH); // [64] mask

    int tid = threadIdx.x;
    int tx  = tid & 15, ty = tid >> 4;
    int qt = blockIdx.x, h = blockIdx.y, b = blockIdx.z;
    int qbase = qt * 64;

    const float* qp = q + (size_t)(b * SEQ) * D_MODEL + h * DK;
    const float* kp = k + (size_t)(b * SEQ) * D_MODEL + h * DK;
    const float* vp = v + (size_t)(b * SEQ) * D_MODEL + h * DK;
    const int* maskb = mask + b * SEQ;

    // load Q tile
    #pragma unroll
    for (int t = 0; t < 4; t++) {
        int f = tid + t * 256;          // 0..1023 float4 slots
        int r = f >> 4, c4 = (f & 15) * 4;
        float4 val = *(const float4*)(qp + (size_t)(qbase + r) * D_MODEL + c4);
        *(float4*)&Qs[r * APITCH + c4] = val;
    }

    float m_i[4], l_i[4], acc[4][4];
    #pragma unroll
    for (int i = 0; i < 4; i++) {
        m_i[i] = -1e30f; l_i[i] = 0.f;
        #pragma unroll
        for (int j = 0; j < 4; j++) acc[i][j] = 0.f;
    }

    for (int kt = 0; kt < SEQ / 64; kt++) {
        __syncthreads();   // protect Kt/Vs/Ps from previous iteration's readers
        int kvbase = kt * 64;
        #pragma unroll
        for (int t = 0; t < 4; t++) {
            int f = tid + t * 256;
            int r = f >> 4, c4 = (f & 15) * 4;
            float4 kv4 = *(const float4*)(kp + (size_t)(kvbase + r) * D_MODEL + c4);
            Kt[(c4 + 0) * APITCH + r] = kv4.x;
            Kt[(c4 + 1) * APITCH + r] = kv4.y;
            Kt[(c4 + 2) * APITCH + r] = kv4.z;
            Kt[(c4 + 3) * APITCH + r] = kv4.w;
            float4 vv4 = *(const float4*)(vp + (size_t)(kvbase + r) * D_MODEL + c4);
            *(float4*)&Vs[r * APITCH + c4] = vv4;
        }
        if (tid < 64) ms[tid] = maskb[kvbase + tid];
        __syncthreads();

        // scores: s[i][j] = sum_d Q[ty*4+i][d] * K[tx*4+j][d]
        float s4[4][4];
        #pragma unroll
        for (int i = 0; i < 4; i++)
            #pragma unroll
            for (int j = 0; j < 4; j++) s4[i][j] = 0.f;

        #pragma unroll 8
        for (int d = 0; d < 64; d++) {
            float a0 = Qs[(ty * 4 + 0) * APITCH + d];
            float a1 = Qs[(ty * 4 + 1) * APITCH + d];
            float a2 = Qs[(ty * 4 + 2) * APITCH + d];
            float a3 = Qs[(ty * 4 + 3) * APITCH + d];
            float4 bq = *(const float4*)&Kt[d * APITCH + tx * 4];
            s4[0][0] += a0 * bq.x; s4[0][1] += a0 * bq.y; s4[0][2] += a0 * bq.z; s4[0][3] += a0 * bq.w;
            s4[1][0] += a1 * bq.x; s4[1][1] += a1 * bq.y; s4[1][2] += a1 * bq.z; s4[1][3] += a1 * bq.w;
            s4[2][0] += a2 * bq.x; s4[2][1] += a2 * bq.y; s4[2][2] += a2 * bq.z; s4[2][3] += a2 * bq.w;
            s4[3][0] += a3 * bq.x; s4[3][1] += a3 * bq.y; s4[3][2] += a3 * bq.z; s4[3][3] += a3 * bq.w;
        }

        // mask + scale (replacement semantics like the reference)
        int mc0 = ms[tx * 4 + 0], mc1 = ms[tx * 4 + 1];
        int mc2 = ms[tx * 4 + 2], mc3 = ms[tx * 4 + 3];
        #pragma unroll
        for (int i = 0; i < 4; i++) {
            s4[i][0] = (mc0 == 0) ? -1e9f : s4[i][0] * 0.125f;
            s4[i][1] = (mc1 == 0) ? -1e9f : s4[i][1] * 0.125f;
            s4[i][2] = (mc2 == 0) ? -1e9f : s4[i][2] * 0.125f;
            s4[i][3] = (mc3 == 0) ? -1e9f : s4[i][3] * 0.125f;
        }

        // online softmax: reductions over the 16 tx lanes (contiguous in warp)
        #pragma unroll
        for (int i = 0; i < 4; i++) {
            float mx = fmaxf(fmaxf(s4[i][0], s4[i][1]), fmaxf(s4[i][2], s4[i][3]));
            #pragma unroll
            for (int o = 1; o < 16; o <<= 1)
                mx = fmaxf(mx, __shfl_xor_sync(0xffffffffu, mx, o));
            float mnew = fmaxf(m_i[i], mx);
            float p0 = __expf(s4[i][0] - mnew);
            float p1 = __expf(s4[i][1] - mnew);
            float p2 = __expf(s4[i][2] - mnew);
            float p3 = __expf(s4[i][3] - mnew);
            float ssum = p0 + p1 + p2 + p3;
            #pragma unroll
            for (int o = 1; o < 16; o <<= 1)
                ssum += __shfl_xor_sync(0xffffffffu, ssum, o);
            float sc = __expf(m_i[i] - mnew);
            l_i[i] = l_i[i] * sc + ssum;
            m_i[i] = mnew;
            acc[i][0] *= sc; acc[i][1] *= sc; acc[i][2] *= sc; acc[i][3] *= sc;
            *(float4*)&Ps[(ty * 4 + i) * APITCH + tx * 4] = make_float4(p0, p1, p2, p3);
        }
        __syncthreads();

        // PV: acc[i][j] += sum_kk P[ty*4+i][kk] * V[kk][tx*4+j]
        #pragma unroll 8
        for (int kk = 0; kk < 64; kk++) {
            float4 vb = *(const float4*)&Vs[kk * APITCH + tx * 4];
            float p0 = Ps[(ty * 4 + 0) * APITCH + kk];
            float p1 = Ps[(ty * 4 + 1) * APITCH + kk];
            float p2 = Ps[(ty * 4 + 2) * APITCH + kk];
            float p3 = Ps[(ty * 4 + 3) * APITCH + kk];
            acc[0][0] += p0 * vb.x; acc[0][1] += p0 * vb.y; acc[0][2] += p0 * vb.z; acc[0][3] += p0 * vb.w;
            acc[1][0] += p1 * vb.x; acc[1][1] += p1 * vb.y; acc[1][2] += p1 * vb.z; acc[1][3] += p1 * vb.w;
            acc[2][0] += p2 * vb.x; acc[2][1] += p2 * vb.y; acc[2][2] += p2 * vb.z; acc[2][3] += p2 * vb.w;
            acc[3][0] += p3 * vb.x; acc[3][1] += p3 * vb.y; acc[3][2] += p3 * vb.z; acc[3][3] += p3 * vb.w;
        }
    }

    // finalize: divide by l, write ctx[b, qbase+r, h*64 + c]
    float* op = ctx + (size_t)(b * SEQ + qbase) * D_MODEL + h * DK;
    #pragma unroll
    for (int i = 0; i < 4; i++) {
        float inv = 1.0f / l_i[i];
        float4 o;
        o.x = acc[i][0] * inv; o.y = acc[i][1] * inv;
        o.z = acc[i][2] * inv; o.w = acc[i][3] * inv;
        *(float4*)(op + (size_t)(ty * 4 + i) * D_MODEL + tx * 4) = o;
    }
}

// ---------------- launch ---------------------------------------------------
extern "C" void kernel_launch(void* const* d_in, const int* in_sizes, int n_in,
                              void* d_out, int out_size)
{
    const float* src  = (const float*)d_in[0];
    const int*   mask = (const int*)  d_in[1];
    const float* wq   = (const float*)d_in[2];
    const float* wk   = (const float*)d_in[3];
    const float* wv   = (const float*)d_in[4];
    const float* wo   = (const float*)d_in[5];
    const float* w1   = (const float*)d_in[6];
    const float* b1   = (const float*)d_in[7];
    const float* w2   = (const float*)d_in[8];
    const float* b2   = (const float*)d_in[9];
    const float* a1   = (const float*)d_in[10];
    const float* be1  = (const float*)d_in[11];
    const float* a2   = (const float*)d_in[12];
    const float* be2  = (const float*)d_in[13];
    float* out = (float*)d_out;

    float *xln, *qb, *kb, *vb, *ctx, *out1, *x2, *ffh;
    cudaGetSymbolAddress((void**)&xln,  g_xln);
    cudaGetSymbolAddress((void**)&qb,   g_q);
    cudaGetSymbolAddress((void**)&kb,   g_k);
    cudaGetSymbolAddress((void**)&vb,   g_v);
    cudaGetSymbolAddress((void**)&ctx,  g_ctx);
    cudaGetSymbolAddress((void**)&out1, g_out1);
    cudaGetSymbolAddress((void**)&x2,   g_x2);
    cudaGetSymbolAddress((void**)&ffh,  g_ffh);

    // 1) LN1
    ln_kernel<<<MROWS, 256>>>(src, xln, a1, be1);

    // 2) QKV projections: [4096,1024] x [1024,1024]^T
    dim3 gp(D_MODEL / BN, MROWS / BM);
    sgemm_abt<0><<<gp, 256>>>(xln, wq, qb, nullptr, nullptr, MROWS, D_MODEL, D_MODEL);
    sgemm_abt<0><<<gp, 256>>>(xln, wk, kb, nullptr, nullptr, MROWS, D_MODEL, D_MODEL);
    sgemm_abt<0><<<gp, 256>>>(xln, wv, vb, nullptr, nullptr, MROWS, D_MODEL, D_MODEL);

    // 3) fused attention
    int smem_bytes = 4 * 64 * APITCH * (int)sizeof(float) + 64 * (int)sizeof(int);
    cudaFuncSetAttribute(attn_kernel, cudaFuncAttributeMaxDynamicSharedMemorySize, smem_bytes);
    attn_kernel<<<dim3(SEQ / 64, NH, BATCH), 256, smem_bytes>>>(qb, kb, vb, mask, ctx);

    // 4) output projection + residual: out1 = src + ctx @ wo^T
    sgemm_abt<3><<<gp, 256>>>(ctx, wo, out1, nullptr, src, MROWS, D_MODEL, D_MODEL);

    // 5) LN2
    ln_kernel<<<MROWS, 256>>>(out1, x2, a2, be2);

    // 6) FFN up: ffh = relu(x2 @ w1^T + b1)   [4096,4096]
    dim3 gf1(DFF / BN, MROWS / BM);
    sgemm_abt<1><<<gf1, 256>>>(x2, w1, ffh, b1, nullptr, MROWS, DFF, D_MODEL);

    // 7) FFN down + residual: out = out1 + ffh @ w2^T + b2
    sgemm_abt<2><<<gp, 256>>>(ffh, w2, out, b2, out1, MROWS, D_MODEL, DFF);
}

// round 4
// speedup vs baseline: 1.6489x; 1.6489x over previous
#include <cuda_runtime.h>
#include <math.h>
#include <stdint.h>

#define D_MODEL 1024
#define NH      16
#define DK      64
#define DFF     4096
#define BATCH   2
#define SEQ     2048
#define MROWS   (BATCH*SEQ)   // 4096

// ---------------- scratch (device globals; no allocation allowed) ----------
__device__ float g_xln [MROWS*D_MODEL];
__device__ float g_q   [MROWS*D_MODEL];
__device__ float g_k   [MROWS*D_MODEL];
__device__ float g_v   [MROWS*D_MODEL];
__device__ float g_ctx [MROWS*D_MODEL];
__device__ float g_out1[MROWS*D_MODEL];
__device__ float g_x2  [MROWS*D_MODEL];
__device__ float g_ffh [MROWS*DFF];

// ---------------- helpers --------------------------------------------------
static __device__ __forceinline__ uint32_t f2tf(float f) {
    uint32_t u;
    asm("cvt.rna.tf32.f32 %0, %1;" : "=r"(u) : "f"(f));
    return u;
}

static __device__ __forceinline__ void mma_tf32(
    float& c0, float& c1, float& c2, float& c3,
    uint32_t a0, uint32_t a1, uint32_t a2, uint32_t a3,
    uint32_t b0, uint32_t b1)
{
    asm volatile(
        "mma.sync.aligned.m16n8k8.row.col.f32.tf32.tf32.f32 "
        "{%0,%1,%2,%3}, {%4,%5,%6,%7}, {%8,%9}, {%0,%1,%2,%3};"
        : "+f"(c0), "+f"(c1), "+f"(c2), "+f"(c3)
        : "r"(a0), "r"(a1), "r"(a2), "r"(a3), "r"(b0), "r"(b1));
}

// ======================= Tensor-core TF32 GEMM ============================
// C[M,N] = A[M,K] * B[N,K]^T  with fused epilogue.
// Tile: 128x128x32. 8 warps in 2(m) x 4(n); warp tile 64x32.
// EPI: 0 = none, 1 = bias+relu, 2 = bias+residual, 3 = residual
#define GBM 128
#define GBN 128
#define GBK 32
#define PITCH 36
#define TILE_FLOATS (GBM * PITCH)                 // one A (or B) buffer
#define GEMM_SMEM   (4 * TILE_FLOATS * 4)         // A0,A1,B0,B1 = 73728 B

template<int EPI>
__global__ void __launch_bounds__(256, 1) tcgemm(
    const float* __restrict__ A,
    const float* __restrict__ B0, const float* __restrict__ B1, const float* __restrict__ B2,
    float* __restrict__ C0, float* __restrict__ C1, float* __restrict__ C2,
    const float* __restrict__ bias, const float* __restrict__ res,
    int M, int N, int K)
{
    extern __shared__ float sm[];
    float* Abuf[2] = { sm,                  sm + TILE_FLOATS };
    float* Bbuf[2] = { sm + 2*TILE_FLOATS, sm + 3*TILE_FLOATS };

    const float* Bm = B0; float* Cm = C0;
    if (blockIdx.z == 1) { Bm = B1; Cm = C1; }
    else if (blockIdx.z == 2) { Bm = B2; Cm = C2; }

    int tid  = threadIdx.x;
    int lane = tid & 31, wid = tid >> 5;
    int warp_m = (wid >> 2) * 64;     // 0 or 64
    int warp_n = (wid & 3) * 32;      // 0,32,64,96
    int rowBase = blockIdx.y * GBM;
    int colBase = blockIdx.x * GBN;
    int r4 = lane >> 2, c4 = lane & 3;

    float acc[4][4][4];
    #pragma unroll
    for (int i = 0; i < 4; i++)
        #pragma unroll
        for (int j = 0; j < 4; j++)
            #pragma unroll
            for (int e = 0; e < 4; e++) acc[i][j][e] = 0.f;

    // staging slots: 4 float4 each for A and B tiles
    int sr[4], sc[4];
    const float* Ag[4]; const float* Bg[4];
    #pragma unroll
    for (int j = 0; j < 4; j++) {
        int slot = tid + 256 * j;
        sr[j] = slot >> 3;            // row 0..127
        sc[j] = (slot & 7) * 4;       // col 0,4,...,28
        Ag[j] = A  + (size_t)(rowBase + sr[j]) * K + sc[j];
        Bg[j] = Bm + (size_t)(colBase + sr[j]) * K + sc[j];
    }

    float4 stA[4], stB[4];
    auto ldg_tile = [&](int k0) {
        #pragma unroll
        for (int j = 0; j < 4; j++) stA[j] = *(const float4*)(Ag[j] + k0);
        #pragma unroll
        for (int j = 0; j < 4; j++) stB[j] = *(const float4*)(Bg[j] + k0);
    };
    auto sts_tile = [&](int b) {
        #pragma unroll
        for (int j = 0; j < 4; j++) {
            float4 v = stA[j], o;
            o.x = __uint_as_float(f2tf(v.x)); o.y = __uint_as_float(f2tf(v.y));
            o.z = __uint_as_float(f2tf(v.z)); o.w = __uint_as_float(f2tf(v.w));
            *(float4*)&Abuf[b][sr[j] * PITCH + sc[j]] = o;
        }
        #pragma unroll
        for (int j = 0; j < 4; j++) {
            float4 v = stB[j], o;
            o.x = __uint_as_float(f2tf(v.x)); o.y = __uint_as_float(f2tf(v.y));
            o.z = __uint_as_float(f2tf(v.z)); o.w = __uint_as_float(f2tf(v.w));
            *(float4*)&Bbuf[b][sr[j] * PITCH + sc[j]] = o;
        }
    };

    int T = K / GBK;
    ldg_tile(0);
    sts_tile(0);
    __syncthreads();

    for (int t = 0; t < T; t++) {
        if (t + 1 < T) ldg_tile((t + 1) * GBK);

        const float* As = Abuf[t & 1];
        const float* Bs = Bbuf[t & 1];
        #pragma unroll
        for (int kk = 0; kk < 4; kk++) {
            int k8 = kk * 8;
            uint32_t af[4][4], bf[4][2];
            #pragma unroll
            for (int i = 0; i < 4; i++) {
                const float* ap = As + (warp_m + i * 16) * PITCH + k8;
                af[i][0] = __float_as_uint(ap[(r4    ) * PITCH + c4    ]);
                af[i][1] = __float_as_uint(ap[(r4 + 8) * PITCH + c4    ]);
                af[i][2] = __float_as_uint(ap[(r4    ) * PITCH + c4 + 4]);
                af[i][3] = __float_as_uint(ap[(r4 + 8) * PITCH + c4 + 4]);
            }
            #pragma unroll
            for (int j = 0; j < 4; j++) {
                const float* bp = Bs + (warp_n + j * 8) * PITCH + k8;
                bf[j][0] = __float_as_uint(bp[r4 * PITCH + c4    ]);
                bf[j][1] = __float_as_uint(bp[r4 * PITCH + c4 + 4]);
            }
            #pragma unroll
            for (int i = 0; i < 4; i++)
                #pragma unroll
                for (int j = 0; j < 4; j++)
                    mma_tf32(acc[i][j][0], acc[i][j][1], acc[i][j][2], acc[i][j][3],
                             af[i][0], af[i][1], af[i][2], af[i][3],
                             bf[j][0], bf[j][1]);
        }

        if (t + 1 < T) sts_tile((t + 1) & 1);
        __syncthreads();
    }

    // epilogue: fragment c0,c1 at (row, col..col+1), c2,c3 at (row+8, col..col+1)
    #pragma unroll
    for (int i = 0; i < 4; i++) {
        int row = rowBase + warp_m + i * 16 + r4;
        #pragma unroll
        for (int j = 0; j < 4; j++) {
            int col = colBase + warp_n + j * 8 + c4 * 2;
            float2 lo = make_float2(acc[i][j][0], acc[i][j][1]);
            float2 hi = make_float2(acc[i][j][2], acc[i][j][3]);
            if (EPI == 1) {
                float2 bi = *(const float2*)&bias[col];
                lo.x = fmaxf(lo.x + bi.x, 0.f); lo.y = fmaxf(lo.y + bi.y, 0.f);
                hi.x = fmaxf(hi.x + bi.x, 0.f); hi.y = fmaxf(hi.y + bi.y, 0.f);
            } else if (EPI == 2) {
                float2 bi = *(const float2*)&bias[col];
                float2 r0 = *(const float2*)&res[(size_t)row * N + col];
                float2 r1 = *(const float2*)&res[(size_t)(row + 8) * N + col];
                lo.x += bi.x + r0.x; lo.y += bi.y + r0.y;
                hi.x += bi.x + r1.x; hi.y += bi.y + r1.y;
            } else if (EPI == 3) {
                float2 r0 = *(const float2*)&res[(size_t)row * N + col];
                float2 r1 = *(const float2*)&res[(size_t)(row + 8) * N + col];
                lo.x += r0.x; lo.y += r0.y;
                hi.x += r1.x; hi.y += r1.y;
            }
            *(float2*)&Cm[(size_t)row * N + col]       = lo;
            *(float2*)&Cm[(size_t)(row + 8) * N + col] = hi;
        }
    }
}

// ---------------- LayerNorm (torch semantics: ddof=1, eps added to std) ----
__global__ void __launch_bounds__(256) ln_kernel(
    const float* __restrict__ x, float* __restrict__ y,
    const float* __restrict__ alpha, const float* __restrict__ beta)
{
    int row = blockIdx.x;
    const float4* xr = (const float4*)(x + (size_t)row * D_MODEL);
    float4 v = xr[threadIdx.x];
    float s  = v.x + v.y + v.z + v.w;
    float sq = v.x*v.x + v.y*v.y + v.z*v.z + v.w*v.w;

    __shared__ float red[18];
    #pragma unroll
    for (int o = 16; o; o >>= 1) {
        s  += __shfl_xor_sync(0xffffffffu, s,  o);
        sq += __shfl_xor_sync(0xffffffffu, sq, o);
    }
    int w = threadIdx.x >> 5;
    if ((threadIdx.x & 31) == 0) { red[w] = s; red[8 + w] = sq; }
    __syncthreads();
    if (threadIdx.x == 0) {
        float ts = 0.f, tq = 0.f;
        #pragma unroll
        for (int i = 0; i < 8; i++) { ts += red[i]; tq += red[8 + i]; }
        red[16] = ts; red[17] = tq;
    }
    __syncthreads();
    float ts = red[16], tq = red[17];

    float mean = ts * (1.0f / D_MODEL);
    float var  = (tq - ts * mean) * (1.0f / (D_MODEL - 1));
    var = fmaxf(var, 0.0f);
    float denom = sqrtf(var) + 1e-6f;
    float a  = alpha[0], be = beta[0];
    float r  = a / denom;

    float4 o;
    o.x = (v.x - mean) * r + be;
    o.y = (v.y - mean) * r + be;
    o.z = (v.z - mean) * r + be;
    o.w = (v.w - mean) * r + be;
    ((float4*)(y + (size_t)row * D_MODEL))[threadIdx.x] = o;
}

// ---------------- Fused flash attention (fp32, 64x64 tiles) ---------------
#define APITCH 68

__global__ void __launch_bounds__(256) attn_kernel(
    const float* __restrict__ q, const float* __restrict__ k,
    const float* __restrict__ v, const int* __restrict__ mask,
    float* __restrict__ ctx)
{
    extern __shared__ float smaf[];
    float* Qs = smaf;
    float* Kt = Qs + 64 * APITCH;
    float* Vs = Kt + 64 * APITCH;
    float* Ps = Vs + 64 * APITCH;
    int*   ms = (int*)(Ps + 64 * APITCH);

    int tid = threadIdx.x;
    int tx  = tid & 15, ty = tid >> 4;
    int qt = blockIdx.x, h = blockIdx.y, b = blockIdx.z;
    int qbase = qt * 64;

    const float* qp = q + (size_t)(b * SEQ) * D_MODEL + h * DK;
    const float* kp = k + (size_t)(b * SEQ) * D_MODEL + h * DK;
    const float* vp = v + (size_t)(b * SEQ) * D_MODEL + h * DK;
    const int* maskb = mask + b * SEQ;

    #pragma unroll
    for (int t = 0; t < 4; t++) {
        int f = tid + t * 256;
        int r = f >> 4, c4 = (f & 15) * 4;
        float4 val = *(const float4*)(qp + (size_t)(qbase + r) * D_MODEL + c4);
        *(float4*)&Qs[r * APITCH + c4] = val;
    }

    float m_i[4], l_i[4], acc[4][4];
    #pragma unroll
    for (int i = 0; i < 4; i++) {
        m_i[i] = -1e30f; l_i[i] = 0.f;
        #pragma unroll
        for (int j = 0; j < 4; j++) acc[i][j] = 0.f;
    }

    for (int kt = 0; kt < SEQ / 64; kt++) {
        __syncthreads();
        int kvbase = kt * 64;
        #pragma unroll
        for (int t = 0; t < 4; t++) {
            int f = tid + t * 256;
            int r = f >> 4, c4 = (f & 15) * 4;
            float4 kv4 = *(const float4*)(kp + (size_t)(kvbase + r) * D_MODEL + c4);
            Kt[(c4 + 0) * APITCH + r] = kv4.x;
            Kt[(c4 + 1) * APITCH + r] = kv4.y;
            Kt[(c4 + 2) * APITCH + r] = kv4.z;
            Kt[(c4 + 3) * APITCH + r] = kv4.w;
            float4 vv4 = *(const float4*)(vp + (size_t)(kvbase + r) * D_MODEL + c4);
            *(float4*)&Vs[r * APITCH + c4] = vv4;
        }
        if (tid < 64) ms[tid] = maskb[kvbase + tid];
        __syncthreads();

        float s4[4][4];
        #pragma unroll
        for (int i = 0; i < 4; i++)
            #pragma unroll
            for (int j = 0; j < 4; j++) s4[i][j] = 0.f;

        #pragma unroll 8
        for (int d = 0; d < 64; d++) {
            float a0 = Qs[(ty * 4 + 0) * APITCH + d];
            float a1 = Qs[(ty * 4 + 1) * APITCH + d];
            float a2 = Qs[(ty * 4 + 2) * APITCH + d];
            float a3 = Qs[(ty * 4 + 3) * APITCH + d];
            float4 bq = *(const float4*)&Kt[d * APITCH + tx * 4];
            s4[0][0] += a0 * bq.x; s4[0][1] += a0 * bq.y; s4[0][2] += a0 * bq.z; s4[0][3] += a0 * bq.w;
            s4[1][0] += a1 * bq.x; s4[1][1] += a1 * bq.y; s4[1][2] += a1 * bq.z; s4[1][3] += a1 * bq.w;
            s4[2][0] += a2 * bq.x; s4[2][1] += a2 * bq.y; s4[2][2] += a2 * bq.z; s4[2][3] += a2 * bq.w;
            s4[3][0] += a3 * bq.x; s4[3][1] += a3 * bq.y; s4[3][2] += a3 * bq.z; s4[3][3] += a3 * bq.w;
        }

        int mc0 = ms[tx * 4 + 0], mc1 = ms[tx * 4 + 1];
        int mc2 = ms[tx * 4 + 2], mc3 = ms[tx * 4 + 3];
        #pragma unroll
        for (int i = 0; i < 4; i++) {
            s4[i][0] = (mc0 == 0) ? -1e9f : s4[i][0] * 0.125f;
            s4[i][1] = (mc1 == 0) ? -1e9f : s4[i][1] * 0.125f;
            s4[i][2] = (mc2 == 0) ? -1e9f : s4[i][2] * 0.125f;
            s4[i][3] = (mc3 == 0) ? -1e9f : s4[i][3] * 0.125f;
        }

        #pragma unroll
        for (int i = 0; i < 4; i++) {
            float mx = fmaxf(fmaxf(s4[i][0], s4[i][1]), fmaxf(s4[i][2], s4[i][3]));
            #pragma unroll
            for (int o = 1; o < 16; o <<= 1)
                mx = fmaxf(mx, __shfl_xor_sync(0xffffffffu, mx, o));
            float mnew = fmaxf(m_i[i], mx);
            float p0 = __expf(s4[i][0] - mnew);
            float p1 = __expf(s4[i][1] - mnew);
            float p2 = __expf(s4[i][2] - mnew);
            float p3 = __expf(s4[i][3] - mnew);
            float ssum = p0 + p1 + p2 + p3;
            #pragma unroll
            for (int o = 1; o < 16; o <<= 1)
                ssum += __shfl_xor_sync(0xffffffffu, ssum, o);
            float sc = __expf(m_i[i] - mnew);
            l_i[i] = l_i[i] * sc + ssum;
            m_i[i] = mnew;
            acc[i][0] *= sc; acc[i][1] *= sc; acc[i][2] *= sc; acc[i][3] *= sc;
            *(float4*)&Ps[(ty * 4 + i) * APITCH + tx * 4] = make_float4(p0, p1, p2, p3);
        }
        __syncthreads();

        #pragma unroll 8
        for (int kk = 0; kk < 64; kk++) {
            float4 vb = *(const float4*)&Vs[kk * APITCH + tx * 4];
            float p0 = Ps[(ty * 4 + 0) * APITCH + kk];
            float p1 = Ps[(ty * 4 + 1) * APITCH + kk];
            float p2 = Ps[(ty * 4 + 2) * APITCH + kk];
            float p3 = Ps[(ty * 4 + 3) * APITCH + kk];
            acc[0][0] += p0 * vb.x; acc[0][1] += p0 * vb.y; acc[0][2] += p0 * vb.z; acc[0][3] += p0 * vb.w;
            acc[1][0] += p1 * vb.x; acc[1][1] += p1 * vb.y; acc[1][2] += p1 * vb.z; acc[1][3] += p1 * vb.w;
            acc[2][0] += p2 * vb.x; acc[2][1] += p2 * vb.y; acc[2][2] += p2 * vb.z; acc[2][3] += p2 * vb.w;
            acc[3][0] += p3 * vb.x; acc[3][1] += p3 * vb.y; acc[3][2] += p3 * vb.z; acc[3][3] += p3 * vb.w;
        }
    }

    float* op = ctx + (size_t)(b * SEQ + qbase) * D_MODEL + h * DK;
    #pragma unroll
    for (int i = 0; i < 4; i++) {
        float inv = 1.0f / l_i[i];
        float4 o;
        o.x = acc[i][0] * inv; o.y = acc[i][1] * inv;
        o.z = acc[i][2] * inv; o.w = acc[i][3] * inv;
        *(float4*)(op + (size_t)(ty * 4 + i) * D_MODEL + tx * 4) = o;
    }
}

// ---------------- launch ---------------------------------------------------
extern "C" void kernel_launch(void* const* d_in, const int* in_sizes, int n_in,
                              void* d_out, int out_size)
{
    const float* src  = (const float*)d_in[0];
    const int*   mask = (const int*)  d_in[1];
    const float* wq   = (const float*)d_in[2];
    const float* wk   = (const float*)d_in[3];
    const float* wv   = (const float*)d_in[4];
    const float* wo   = (const float*)d_in[5];
    const float* w1   = (const float*)d_in[6];
    const float* b1   = (const float*)d_in[7];
    const float* w2   = (const float*)d_in[8];
    const float* b2   = (const float*)d_in[9];
    const float* a1   = (const float*)d_in[10];
    const float* be1  = (const float*)d_in[11];
    const float* a2   = (const float*)d_in[12];
    const float* be2  = (const float*)d_in[13];
    float* out = (float*)d_out;

    float *xln, *qb, *kb, *vb, *ctx, *out1, *x2, *ffh;
    cudaGetSymbolAddress((void**)&xln,  g_xln);
    cudaGetSymbolAddress((void**)&qb,   g_q);
    cudaGetSymbolAddress((void**)&kb,   g_k);
    cudaGetSymbolAddress((void**)&vb,   g_v);
    cudaGetSymbolAddress((void**)&ctx,  g_ctx);
    cudaGetSymbolAddress((void**)&out1, g_out1);
    cudaGetSymbolAddress((void**)&x2,   g_x2);
    cudaGetSymbolAddress((void**)&ffh,  g_ffh);

    int gsm = GEMM_SMEM;
    cudaFuncSetAttribute(tcgemm<0>, cudaFuncAttributeMaxDynamicSharedMemorySize, gsm);
    cudaFuncSetAttribute(tcgemm<1>, cudaFuncAttributeMaxDynamicSharedMemorySize, gsm);
    cudaFuncSetAttribute(tcgemm<2>, cudaFuncAttributeMaxDynamicSharedMemorySize, gsm);
    cudaFuncSetAttribute(tcgemm<3>, cudaFuncAttributeMaxDynamicSharedMemorySize, gsm);

    // 1) LN1
    ln_kernel<<<MROWS, 256>>>(src, xln, a1, be1);

    // 2) QKV projections fused over gridDim.z
    tcgemm<0><<<dim3(D_MODEL/GBN, MROWS/GBM, 3), 256, gsm>>>(
        xln, wq, wk, wv, qb, kb, vb, nullptr, nullptr, MROWS, D_MODEL, D_MODEL);

    // 3) fused attention
    int smem_bytes = 4 * 64 * APITCH * (int)sizeof(float) + 64 * (int)sizeof(int);
    cudaFuncSetAttribute(attn_kernel, cudaFuncAttributeMaxDynamicSharedMemorySize, smem_bytes);
    attn_kernel<<<dim3(SEQ / 64, NH, BATCH), 256, smem_bytes>>>(qb, kb, vb, mask, ctx);

    // 4) output projection + residual: out1 = src + ctx @ wo^T
    tcgemm<3><<<dim3(D_MODEL/GBN, MROWS/GBM, 1), 256, gsm>>>(
        ctx, wo, wo, wo, out1, out1, out1, nullptr, src, MROWS, D_MODEL, D_MODEL);

    // 5) LN2
    ln_kernel<<<MROWS, 256>>>(out1, x2, a2, be2);

    // 6) FFN up: ffh = relu(x2 @ w1^T + b1)
    tcgemm<1><<<dim3(DFF/GBN, MROWS/GBM, 1), 256, gsm>>>(
        x2, w1, w1, w1, ffh, ffh, ffh, b1, nullptr, MROWS, DFF, D_MODEL);

    // 7) FFN down + residual: out = out1 + ffh @ w2^T + b2
    tcgemm<2><<<dim3(D_MODEL/GBN, MROWS/GBM, 1), 256, gsm>>>(
        ffh, w2, w2, w2, out, out, out, b2, out1, MROWS, D_MODEL, DFF);
}

// round 5
// speedup vs baseline: 2.1161x; 1.2833x over previous
#include <cuda_runtime.h>
#include <math.h>
#include <stdint.h>

#define D_MODEL 1024
#define NH      16
#define DK      64
#define DFF     4096
#define BATCH   2
#define SEQ     2048
#define MROWS   (BATCH*SEQ)   // 4096

// ---------------- scratch (device globals; no allocation allowed) ----------
__device__ float g_xln [MROWS*D_MODEL];
__device__ float g_q   [MROWS*D_MODEL];
__device__ float g_k   [MROWS*D_MODEL];
__device__ float g_v   [MROWS*D_MODEL];
__device__ float g_ctx [MROWS*D_MODEL];
__device__ float g_out1[MROWS*D_MODEL];
__device__ float g_x2  [MROWS*D_MODEL];
__device__ float g_ffh [MROWS*DFF];
// tf32-rounded weights
__device__ float g_wqr [D_MODEL*D_MODEL];
__device__ float g_wkr [D_MODEL*D_MODEL];
__device__ float g_wvr [D_MODEL*D_MODEL];
__device__ float g_wor [D_MODEL*D_MODEL];
__device__ float g_w1r [DFF*D_MODEL];
__device__ float g_w2r [D_MODEL*DFF];

// ---------------- helpers --------------------------------------------------
static __device__ __forceinline__ float f2tf(float f) {
    uint32_t u;
    asm("cvt.rna.tf32.f32 %0, %1;" : "=r"(u) : "f"(f));
    return __uint_as_float(u);
}

static __device__ __forceinline__ uint32_t smem_u32(const void* p) {
    uint32_t a;
    asm("{ .reg .u64 t; cvta.to.shared.u64 t, %1; cvt.u32.u64 %0, t; }"
        : "=r"(a) : "l"(p));
    return a;
}

static __device__ __forceinline__ void mma_tf32(
    float& c0, float& c1, float& c2, float& c3,
    uint32_t a0, uint32_t a1, uint32_t a2, uint32_t a3,
    uint32_t b0, uint32_t b1)
{
    asm volatile(
        "mma.sync.aligned.m16n8k8.row.col.f32.tf32.tf32.f32 "
        "{%0,%1,%2,%3}, {%4,%5,%6,%7}, {%8,%9}, {%0,%1,%2,%3};"
        : "+f"(c0), "+f"(c1), "+f"(c2), "+f"(c3)
        : "r"(a0), "r"(a1), "r"(a2), "r"(a3), "r"(b0), "r"(b1));
}

// ---------------- weight pre-rounding --------------------------------------
#define WSEG  (D_MODEL*D_MODEL/4)        // 262144 float4
#define WBIG  (DFF*D_MODEL/4)            // 1048576 float4
#define WTOT  (4*WSEG + 2*WBIG)          // 3145728

__global__ void round_weights(
    const float4* __restrict__ wq, const float4* __restrict__ wk,
    const float4* __restrict__ wv, const float4* __restrict__ wo,
    const float4* __restrict__ w1, const float4* __restrict__ w2,
    float4* __restrict__ wqr, float4* __restrict__ wkr,
    float4* __restrict__ wvr, float4* __restrict__ wor,
    float4* __restrict__ w1r, float4* __restrict__ w2r)
{
    for (int i = blockIdx.x * blockDim.x + threadIdx.x; i < WTOT;
         i += gridDim.x * blockDim.x) {
        const float4* s; float4* d; int off;
        if      (i < 1*WSEG) { s = wq; d = wqr; off = i; }
        else if (i < 2*WSEG) { s = wk; d = wkr; off = i - 1*WSEG; }
        else if (i < 3*WSEG) { s = wv; d = wvr; off = i - 2*WSEG; }
        else if (i < 4*WSEG) { s = wo; d = wor; off = i - 3*WSEG; }
        else if (i < 4*WSEG + WBIG) { s = w1; d = w1r; off = i - 4*WSEG; }
        else                 { s = w2; d = w2r; off = i - 4*WSEG - WBIG; }
        float4 v = s[off];
        v.x = f2tf(v.x); v.y = f2tf(v.y); v.z = f2tf(v.z); v.w = f2tf(v.w);
        d[off] = v;
    }
}

// ======================= Tensor-core TF32 GEMM ============================
// C[M,N] = A[M,K] * B[N,K]^T, inputs pre-rounded to tf32.
// CTA tile 128(M) x 256(N) x 32(K); 8 warps 2x4; warp tile 64x64.
// 3-stage cp.async pipeline.
// EPI: 0 = none, 1 = bias+relu (+round store), 2 = bias+residual, 3 = residual
#define GBM 128
#define GBN 256
#define GBK 32
#define GPITCH 36
#define A_FLOATS (GBM*GPITCH)                 // 4608
#define B_FLOATS (GBN*GPITCH)                 // 9216
#define STG_FLOATS (A_FLOATS + B_FLOATS)      // 13824
#define NSTAGE 3
#define GEMM_SMEM (NSTAGE*STG_FLOATS*4)       // 165888 B

template<int EPI>
__global__ void __launch_bounds__(256, 1) tcgemm(
    const float* __restrict__ A,
    const float* __restrict__ B0, const float* __restrict__ B1, const float* __restrict__ B2,
    float* __restrict__ C0, float* __restrict__ C1, float* __restrict__ C2,
    const float* __restrict__ bias, const float* __restrict__ res,
    int M, int N, int K)
{
    extern __shared__ float sm[];
    uint32_t sbase = smem_u32(sm);

    const float* Bm = B0; float* Cm = C0;
    if (blockIdx.z == 1) { Bm = B1; Cm = C1; }
    else if (blockIdx.z == 2) { Bm = B2; Cm = C2; }

    int tid  = threadIdx.x;
    int lane = tid & 31, wid = tid >> 5;
    int warp_m = (wid >> 2) * 64;          // 0 / 64
    int warp_n = (wid & 3) * 64;           // 0,64,128,192
    int rowBase = blockIdx.y * GBM;
    int colBase = blockIdx.x * GBN;
    int r4 = lane >> 2, c4 = lane & 3;

    // load slots: A 4 x 16B, B 8 x 16B per stage per thread
    const float* Ag[4]; uint32_t aOff[4];
    #pragma unroll
    for (int j = 0; j < 4; j++) {
        int slot = tid + 256 * j;
        int r = slot >> 3, c = (slot & 7) * 4;
        Ag[j] = A + (size_t)(rowBase + r) * K + c;
        aOff[j] = (uint32_t)(r * GPITCH + c) * 4u;
    }
    const float* Bg[8]; uint32_t bOff[8];
    #pragma unroll
    for (int j = 0; j < 8; j++) {
        int slot = tid + 256 * j;
        int r = slot >> 3, c = (slot & 7) * 4;
        Bg[j] = Bm + (size_t)(colBase + r) * K + c;
        bOff[j] = (uint32_t)(r * GPITCH + c) * 4u;
    }

    auto issue_tile = [&](int tt, int stage) {
        int k0 = tt * GBK;
        uint32_t sA = sbase + (uint32_t)stage * (STG_FLOATS * 4u);
        uint32_t sB = sA + A_FLOATS * 4u;
        #pragma unroll
        for (int j = 0; j < 4; j++)
            asm volatile("cp.async.cg.shared.global [%0], [%1], 16;"
                         :: "r"(sA + aOff[j]), "l"(Ag[j] + k0));
        #pragma unroll
        for (int j = 0; j < 8; j++)
            asm volatile("cp.async.cg.shared.global [%0], [%1], 16;"
                         :: "r"(sB + bOff[j]), "l"(Bg[j] + k0));
    };

    float acc[4][8][4];
    #pragma unroll
    for (int i = 0; i < 4; i++)
        #pragma unroll
        for (int j = 0; j < 8; j++)
            #pragma unroll
            for (int e = 0; e < 4; e++) acc[i][j][e] = 0.f;

    int T = K / GBK;
    issue_tile(0, 0);
    asm volatile("cp.async.commit_group;");
    issue_tile(1, 1);
    asm volatile("cp.async.commit_group;");

    int st_c = 0, st_l = 2;
    for (int t = 0; t < T; t++) {
        asm volatile("cp.async.wait_group 1;");
        __syncthreads();

        int nt = t + 2;
        int tt = (nt >= T) ? nt - T : nt;   // wrap: junk prefetch keeps group count invariant
        issue_tile(tt, st_l);
        asm volatile("cp.async.commit_group;");
        st_l = (st_l == 2) ? 0 : st_l + 1;

        const float* As = sm + st_c * STG_FLOATS;
        const float* Bs = As + A_FLOATS;
        st_c = (st_c == 2) ? 0 : st_c + 1;

        #pragma unroll
        for (int kk = 0; kk < 4; kk++) {
            int k8 = kk * 8;
            uint32_t af[4][4], bf[8][2];
            #pragma unroll
            for (int i = 0; i < 4; i++) {
                const float* ap = As + (warp_m + 16 * i) * GPITCH + k8;
                af[i][0] = __float_as_uint(ap[(r4    ) * GPITCH + c4    ]);
                af[i][1] = __float_as_uint(ap[(r4 + 8) * GPITCH + c4    ]);
                af[i][2] = __float_as_uint(ap[(r4    ) * GPITCH + c4 + 4]);
                af[i][3] = __float_as_uint(ap[(r4 + 8) * GPITCH + c4 + 4]);
            }
            #pragma unroll
            for (int j = 0; j < 8; j++) {
                const float* bp = Bs + (warp_n + 8 * j) * GPITCH + k8;
                bf[j][0] = __float_as_uint(bp[r4 * GPITCH + c4    ]);
                bf[j][1] = __float_as_uint(bp[r4 * GPITCH + c4 + 4]);
            }
            #pragma unroll
            for (int i = 0; i < 4; i++)
                #pragma unroll
                for (int j = 0; j < 8; j++)
                    mma_tf32(acc[i][j][0], acc[i][j][1], acc[i][j][2], acc[i][j][3],
                             af[i][0], af[i][1], af[i][2], af[i][3],
                             bf[j][0], bf[j][1]);
        }
    }

    // epilogue
    #pragma unroll
    for (int i = 0; i < 4; i++) {
        int row = rowBase + warp_m + i * 16 + r4;
        #pragma unroll
        for (int j = 0; j < 8; j++) {
            int col = colBase + warp_n + j * 8 + c4 * 2;
            float2 lo = make_float2(acc[i][j][0], acc[i][j][1]);
            float2 hi = make_float2(acc[i][j][2], acc[i][j][3]);
            if (EPI == 1) {
                float2 bi = *(const float2*)&bias[col];
                lo.x = f2tf(fmaxf(lo.x + bi.x, 0.f)); lo.y = f2tf(fmaxf(lo.y + bi.y, 0.f));
                hi.x = f2tf(fmaxf(hi.x + bi.x, 0.f)); hi.y = f2tf(fmaxf(hi.y + bi.y, 0.f));
            } else if (EPI == 2) {
                float2 bi = *(const float2*)&bias[col];
                float2 r0 = *(const float2*)&res[(size_t)row * N + col];
                float2 r1 = *(const float2*)&res[(size_t)(row + 8) * N + col];
                lo.x += bi.x + r0.x; lo.y += bi.y + r0.y;
                hi.x += bi.x + r1.x; hi.y += bi.y + r1.y;
            } else if (EPI == 3) {
                float2 r0 = *(const float2*)&res[(size_t)row * N + col];
                float2 r1 = *(const float2*)&res[(size_t)(row + 8) * N + col];
                lo.x += r0.x; lo.y += r0.y;
                hi.x += r1.x; hi.y += r1.y;
            }
            *(float2*)&Cm[(size_t)row * N + col]       = lo;
            *(float2*)&Cm[(size_t)(row + 8) * N + col] = hi;
        }
    }
}

// ---------------- LayerNorm (torch: ddof=1, eps added to std) --------------
// Output rounded to tf32 (consumed only by tf32 GEMMs).
__global__ void __launch_bounds__(256) ln_kernel(
    const float* __restrict__ x, float* __restrict__ y,
    const float* __restrict__ alpha, const float* __restrict__ beta)
{
    int row = blockIdx.x;
    const float4* xr = (const float4*)(x + (size_t)row * D_MODEL);
    float4 v = xr[threadIdx.x];
    float s  = v.x + v.y + v.z + v.w;
    float sq = v.x*v.x + v.y*v.y + v.z*v.z + v.w*v.w;

    __shared__ float red[18];
    #pragma unroll
    for (int o = 16; o; o >>= 1) {
        s  += __shfl_xor_sync(0xffffffffu, s,  o);
        sq += __shfl_xor_sync(0xffffffffu, sq, o);
    }
    int w = threadIdx.x >> 5;
    if ((threadIdx.x & 31) == 0) { red[w] = s; red[8 + w] = sq; }
    __syncthreads();
    if (threadIdx.x == 0) {
        float ts = 0.f, tq = 0.f;
        #pragma unroll
        for (int i = 0; i < 8; i++) { ts += red[i]; tq += red[8 + i]; }
        red[16] = ts; red[17] = tq;
    }
    __syncthreads();
    float ts = red[16], tq = red[17];

    float mean = ts * (1.0f / D_MODEL);
    float var  = (tq - ts * mean) * (1.0f / (D_MODEL - 1));
    var = fmaxf(var, 0.0f);
    float denom = sqrtf(var) + 1e-6f;
    float a  = alpha[0], be = beta[0];
    float r  = a / denom;

    float4 o;
    o.x = f2tf((v.x - mean) * r + be);
    o.y = f2tf((v.y - mean) * r + be);
    o.z = f2tf((v.z - mean) * r + be);
    o.w = f2tf((v.w - mean) * r + be);
    ((float4*)(y + (size_t)row * D_MODEL))[threadIdx.x] = o;
}

// ---------------- Fused flash attention (fp32, 64x64 tiles) ---------------
#define APITCH 68

__global__ void __launch_bounds__(256) attn_kernel(
    const float* __restrict__ q, const float* __restrict__ k,
    const float* __restrict__ v, const int* __restrict__ mask,
    float* __restrict__ ctx)
{
    extern __shared__ float smaf[];
    float* Qs = smaf;
    float* Kt = Qs + 64 * APITCH;
    float* Vs = Kt + 64 * APITCH;
    float* Ps = Vs + 64 * APITCH;
    int*   ms = (int*)(Ps + 64 * APITCH);

    int tid = threadIdx.x;
    int tx  = tid & 15, ty = tid >> 4;
    int qt = blockIdx.x, h = blockIdx.y, b = blockIdx.z;
    int qbase = qt * 64;

    const float* qp = q + (size_t)(b * SEQ) * D_MODEL + h * DK;
    const float* kp = k + (size_t)(b * SEQ) * D_MODEL + h * DK;
    const float* vp = v + (size_t)(b * SEQ) * D_MODEL + h * DK;
    const int* maskb = mask + b * SEQ;

    #pragma unroll
    for (int t = 0; t < 4; t++) {
        int f = tid + t * 256;
        int r = f >> 4, c4 = (f & 15) * 4;
        float4 val = *(const float4*)(qp + (size_t)(qbase + r) * D_MODEL + c4);
        *(float4*)&Qs[r * APITCH + c4] = val;
    }

    float m_i[4], l_i[4], acc[4][4];
    #pragma unroll
    for (int i = 0; i < 4; i++) {
        m_i[i] = -1e30f; l_i[i] = 0.f;
        #pragma unroll
        for (int j = 0; j < 4; j++) acc[i][j] = 0.f;
    }

    for (int kt = 0; kt < SEQ / 64; kt++) {
        __syncthreads();
        int kvbase = kt * 64;
        #pragma unroll
        for (int t = 0; t < 4; t++) {
            int f = tid + t * 256;
            int r = f >> 4, c4 = (f & 15) * 4;
            float4 kv4 = *(const float4*)(kp + (size_t)(kvbase + r) * D_MODEL + c4);
            Kt[(c4 + 0) * APITCH + r] = kv4.x;
            Kt[(c4 + 1) * APITCH + r] = kv4.y;
            Kt[(c4 + 2) * APITCH + r] = kv4.z;
            Kt[(c4 + 3) * APITCH + r] = kv4.w;
            float4 vv4 = *(const float4*)(vp + (size_t)(kvbase + r) * D_MODEL + c4);
            *(float4*)&Vs[r * APITCH + c4] = vv4;
        }
        if (tid < 64) ms[tid] = maskb[kvbase + tid];
        __syncthreads();

        float s4[4][4];
        #pragma unroll
        for (int i = 0; i < 4; i++)
            #pragma unroll
            for (int j = 0; j < 4; j++) s4[i][j] = 0.f;

        #pragma unroll 8
        for (int d = 0; d < 64; d++) {
            float a0 = Qs[(ty * 4 + 0) * APITCH + d];
            float a1 = Qs[(ty * 4 + 1) * APITCH + d];
            float a2 = Qs[(ty * 4 + 2) * APITCH + d];
            float a3 = Qs[(ty * 4 + 3) * APITCH + d];
            float4 bq = *(const float4*)&Kt[d * APITCH + tx * 4];
            s4[0][0] += a0 * bq.x; s4[0][1] += a0 * bq.y; s4[0][2] += a0 * bq.z; s4[0][3] += a0 * bq.w;
            s4[1][0] += a1 * bq.x; s4[1][1] += a1 * bq.y; s4[1][2] += a1 * bq.z; s4[1][3] += a1 * bq.w;
            s4[2][0] += a2 * bq.x; s4[2][1] += a2 * bq.y; s4[2][2] += a2 * bq.z; s4[2][3] += a2 * bq.w;
            s4[3][0] += a3 * bq.x; s4[3][1] += a3 * bq.y; s4[3][2] += a3 * bq.z; s4[3][3] += a3 * bq.w;
        }

        int mc0 = ms[tx * 4 + 0], mc1 = ms[tx * 4 + 1];
        int mc2 = ms[tx * 4 + 2], mc3 = ms[tx * 4 + 3];
        #pragma unroll
        for (int i = 0; i < 4; i++) {
            s4[i][0] = (mc0 == 0) ? -1e9f : s4[i][0] * 0.125f;
            s4[i][1] = (mc1 == 0) ? -1e9f : s4[i][1] * 0.125f;
            s4[i][2] = (mc2 == 0) ? -1e9f : s4[i][2] * 0.125f;
            s4[i][3] = (mc3 == 0) ? -1e9f : s4[i][3] * 0.125f;
        }

        #pragma unroll
        for (int i = 0; i < 4; i++) {
            float mx = fmaxf(fmaxf(s4[i][0], s4[i][1]), fmaxf(s4[i][2], s4[i][3]));
            #pragma unroll
            for (int o = 1; o < 16; o <<= 1)
                mx = fmaxf(mx, __shfl_xor_sync(0xffffffffu, mx, o));
            float mnew = fmaxf(m_i[i], mx);
            float p0 = __expf(s4[i][0] - mnew);
            float p1 = __expf(s4[i][1] - mnew);
            float p2 = __expf(s4[i][2] - mnew);
            float p3 = __expf(s4[i][3] - mnew);
            float ssum = p0 + p1 + p2 + p3;
            #pragma unroll
            for (int o = 1; o < 16; o <<= 1)
                ssum += __shfl_xor_sync(0xffffffffu, ssum, o);
            float sc = __expf(m_i[i] - mnew);
            l_i[i] = l_i[i] * sc + ssum;
            m_i[i] = mnew;
            acc[i][0] *= sc; acc[i][1] *= sc; acc[i][2] *= sc; acc[i][3] *= sc;
            *(float4*)&Ps[(ty * 4 + i) * APITCH + tx * 4] = make_float4(p0, p1, p2, p3);
        }
        __syncthreads();

        #pragma unroll 8
        for (int kk = 0; kk < 64; kk++) {
            float4 vb = *(const float4*)&Vs[kk * APITCH + tx * 4];
            float p0 = Ps[(ty * 4 + 0) * APITCH + kk];
            float p1 = Ps[(ty * 4 + 1) * APITCH + kk];
            float p2 = Ps[(ty * 4 + 2) * APITCH + kk];
            float p3 = Ps[(ty * 4 + 3) * APITCH + kk];
            acc[0][0] += p0 * vb.x; acc[0][1] += p0 * vb.y; acc[0][2] += p0 * vb.z; acc[0][3] += p0 * vb.w;
            acc[1][0] += p1 * vb.x; acc[1][1] += p1 * vb.y; acc[1][2] += p1 * vb.z; acc[1][3] += p1 * vb.w;
            acc[2][0] += p2 * vb.x; acc[2][1] += p2 * vb.y; acc[2][2] += p2 * vb.z; acc[2][3] += p2 * vb.w;
            acc[3][0] += p3 * vb.x; acc[3][1] += p3 * vb.y; acc[3][2] += p3 * vb.z; acc[3][3] += p3 * vb.w;
        }
    }

    // ctx feeds only the tf32 O-projection: round at store
    float* op = ctx + (size_t)(b * SEQ + qbase) * D_MODEL + h * DK;
    #pragma unroll
    for (int i = 0; i < 4; i++) {
        float inv = 1.0f / l_i[i];
        float4 o;
        o.x = f2tf(acc[i][0] * inv); o.y = f2tf(acc[i][1] * inv);
        o.z = f2tf(acc[i][2] * inv); o.w = f2tf(acc[i][3] * inv);
        *(float4*)(op + (size_t)(ty * 4 + i) * D_MODEL + tx * 4) = o;
    }
}

// ---------------- launch ---------------------------------------------------
extern "C" void kernel_launch(void* const* d_in, const int* in_sizes, int n_in,
                              void* d_out, int out_size)
{
    const float* src  = (const float*)d_in[0];
    const int*   mask = (const int*)  d_in[1];
    const float* wq   = (const float*)d_in[2];
    const float* wk   = (const float*)d_in[3];
    const float* wv   = (const float*)d_in[4];
    const float* wo   = (const float*)d_in[5];
    const float* w1   = (const float*)d_in[6];
    const float* b1   = (const float*)d_in[7];
    const float* w2   = (const float*)d_in[8];
    const float* b2   = (const float*)d_in[9];
    const float* a1   = (const float*)d_in[10];
    const float* be1  = (const float*)d_in[11];
    const float* a2   = (const float*)d_in[12];
    const float* be2  = (const float*)d_in[13];
    float* out = (float*)d_out;

    float *xln, *qb, *kb, *vb, *ctx, *out1, *x2, *ffh;
    float *wqr, *wkr, *wvr, *wor, *w1r, *w2r;
    cudaGetSymbolAddress((void**)&xln,  g_xln);
    cudaGetSymbolAddress((void**)&qb,   g_q);
    cudaGetSymbolAddress((void**)&kb,   g_k);
    cudaGetSymbolAddress((void**)&vb,   g_v);
    cudaGetSymbolAddress((void**)&ctx,  g_ctx);
    cudaGetSymbolAddress((void**)&out1, g_out1);
    cudaGetSymbolAddress((void**)&x2,   g_x2);
    cudaGetSymbolAddress((void**)&ffh,  g_ffh);
    cudaGetSymbolAddress((void**)&wqr,  g_wqr);
    cudaGetSymbolAddress((void**)&wkr,  g_wkr);
    cudaGetSymbolAddress((void**)&wvr,  g_wvr);
    cudaGetSymbolAddress((void**)&wor,  g_wor);
    cudaGetSymbolAddress((void**)&w1r,  g_w1r);
    cudaGetSymbolAddress((void**)&w2r,  g_w2r);

    int gsm = GEMM_SMEM;
    cudaFuncSetAttribute(tcgemm<0>, cudaFuncAttributeMaxDynamicSharedMemorySize, gsm);
    cudaFuncSetAttribute(tcgemm<1>, cudaFuncAttributeMaxDynamicSharedMemorySize, gsm);
    cudaFuncSetAttribute(tcgemm<2>, cudaFuncAttributeMaxDynamicSharedMemorySize, gsm);
    cudaFuncSetAttribute(tcgemm<3>, cudaFuncAttributeMaxDynamicSharedMemorySize, gsm);

    // 0) round weights to tf32
    round_weights<<<2048, 256>>>(
        (const float4*)wq, (const float4*)wk, (const float4*)wv, (const float4*)wo,
        (const float4*)w1, (const float4*)w2,
        (float4*)wqr, (float4*)wkr, (float4*)wvr, (float4*)wor,
        (float4*)w1r, (float4*)w2r);

    // 1) LN1 (tf32-rounded output)
    ln_kernel<<<MROWS, 256>>>(src, xln, a1, be1);

    // 2) QKV projections fused over gridDim.z
    tcgemm<0><<<dim3(D_MODEL/GBN, MROWS/GBM, 3), 256, gsm>>>(
        xln, wqr, wkr, wvr, qb, kb, vb, nullptr, nullptr, MROWS, D_MODEL, D_MODEL);

    // 3) fused attention
    int smem_bytes = 4 * 64 * APITCH * (int)sizeof(float) + 64 * (int)sizeof(int);
    cudaFuncSetAttribute(attn_kernel, cudaFuncAttributeMaxDynamicSharedMemorySize, smem_bytes);
    attn_kernel<<<dim3(SEQ / 64, NH, BATCH), 256, smem_bytes>>>(qb, kb, vb, mask, ctx);

    // 4) output projection + residual: out1 = src + ctx @ wo^T
    tcgemm<3><<<dim3(D_MODEL/GBN, MROWS/GBM, 1), 256, gsm>>>(
        ctx, wor, wor, wor, out1, out1, out1, nullptr, src, MROWS, D_MODEL, D_MODEL);

    // 5) LN2 (tf32-rounded output)
    ln_kernel<<<MROWS, 256>>>(out1, x2, a2, be2);

    // 6) FFN up: ffh = round(relu(x2 @ w1^T + b1))
    tcgemm<1><<<dim3(DFF/GBN, MROWS/GBM, 1), 256, gsm>>>(
        x2, w1r, w1r, w1r, ffh, ffh, ffh, b1, nullptr, MROWS, DFF, D_MODEL);

    // 7) FFN down + residual: out = out1 + ffh @ w2^T + b2
    tcgemm<2><<<dim3(D_MODEL/GBN, MROWS/GBM, 1), 256, gsm>>>(
        ffh, w2r, w2r, w2r, out, out, out, b2, out1, MROWS, D_MODEL, DFF);
}

// round 7
// speedup vs baseline: 3.2550x; 1.5382x over previous
#include <cuda_runtime.h>
#include <math.h>
#include <stdint.h>

#define D_MODEL 1024
#define NH      16
#define DK      64
#define DFF     4096
#define BATCH   2
#define SEQ     2048
#define MROWS   (BATCH*SEQ)   // 4096

// ---------------- scratch (device globals; no allocation allowed) ----------
__device__ float g_xln [MROWS*D_MODEL];
__device__ float g_q   [MROWS*D_MODEL];
__device__ float g_k   [MROWS*D_MODEL];
__device__ float g_v   [MROWS*D_MODEL];
__device__ float g_ctx [MROWS*D_MODEL];
__device__ float g_out1[MROWS*D_MODEL];
__device__ float g_x2  [MROWS*D_MODEL];
__device__ float g_ffh [MROWS*DFF];
// tf32-rounded weights
__device__ float g_wqr [D_MODEL*D_MODEL];
__device__ float g_wkr [D_MODEL*D_MODEL];
__device__ float g_wvr [D_MODEL*D_MODEL];
__device__ float g_wor [D_MODEL*D_MODEL];
__device__ float g_w1r [DFF*D_MODEL];
__device__ float g_w2r [D_MODEL*DFF];

// ---------------- helpers --------------------------------------------------
static __device__ __forceinline__ float f2tf(float f) {
    uint32_t u;
    asm("cvt.rna.tf32.f32 %0, %1;" : "=r"(u) : "f"(f));
    return __uint_as_float(u);
}

static __device__ __forceinline__ uint32_t smem_u32(const void* p) {
    uint32_t a;
    asm("{ .reg .u64 t; cvta.to.shared.u64 t, %1; cvt.u32.u64 %0, t; }"
        : "=r"(a) : "l"(p));
    return a;
}

static __device__ __forceinline__ void mma_tf32(
    float& c0, float& c1, float& c2, float& c3,
    uint32_t a0, uint32_t a1, uint32_t a2, uint32_t a3,
    uint32_t b0, uint32_t b1)
{
    asm volatile(
        "mma.sync.aligned.m16n8k8.row.col.f32.tf32.tf32.f32 "
        "{%0,%1,%2,%3}, {%4,%5,%6,%7}, {%8,%9}, {%0,%1,%2,%3};"
        : "+f"(c0), "+f"(c1), "+f"(c2), "+f"(c3)
        : "r"(a0), "r"(a1), "r"(a2), "r"(a3), "r"(b0), "r"(b1));
}

#define CP_ASYNC16(dst, src) \
    asm volatile("cp.async.cg.shared.global [%0], [%1], 16;" :: "r"(dst), "l"(src))

// ---------------- weight pre-rounding --------------------------------------
#define WSEG  (D_MODEL*D_MODEL/4)
#define WBIG  (DFF*D_MODEL/4)
#define WTOT  (4*WSEG + 2*WBIG)

__global__ void round_weights(
    const float4* __restrict__ wq, const float4* __restrict__ wk,
    const float4* __restrict__ wv, const float4* __restrict__ wo,
    const float4* __restrict__ w1, const float4* __restrict__ w2,
    float4* __restrict__ wqr, float4* __restrict__ wkr,
    float4* __restrict__ wvr, float4* __restrict__ wor,
    float4* __restrict__ w1r, float4* __restrict__ w2r)
{
    for (int i = blockIdx.x * blockDim.x + threadIdx.x; i < WTOT;
         i += gridDim.x * blockDim.x) {
        const float4* s; float4* d; int off;
        if      (i < 1*WSEG) { s = wq; d = wqr; off = i; }
        else if (i < 2*WSEG) { s = wk; d = wkr; off = i - 1*WSEG; }
        else if (i < 3*WSEG) { s = wv; d = wvr; off = i - 2*WSEG; }
        else if (i < 4*WSEG) { s = wo; d = wor; off = i - 3*WSEG; }
        else if (i < 4*WSEG + WBIG) { s = w1; d = w1r; off = i - 4*WSEG; }
        else                 { s = w2; d = w2r; off = i - 4*WSEG - WBIG; }
        float4 v = s[off];
        v.x = f2tf(v.x); v.y = f2tf(v.y); v.z = f2tf(v.z); v.w = f2tf(v.w);
        d[off] = v;
    }
}

// ======================= Tensor-core TF32 GEMM ============================
#define GBM 128
#define GBN 256
#define GBK 32
#define GPITCH 36
#define A_FLOATS (GBM*GPITCH)
#define B_FLOATS (GBN*GPITCH)
#define STG_FLOATS (A_FLOATS + B_FLOATS)
#define NSTAGE 3
#define GEMM_SMEM (NSTAGE*STG_FLOATS*4)

// EPI: 0 = round-store (QKV), 1 = bias+relu+round, 2 = bias+residual, 3 = residual
template<int EPI>
__global__ void __launch_bounds__(256, 1) tcgemm(
    const float* __restrict__ A,
    const float* __restrict__ B0, const float* __restrict__ B1, const float* __restrict__ B2,
    float* __restrict__ C0, float* __restrict__ C1, float* __restrict__ C2,
    const float* __restrict__ bias, const float* __restrict__ res,
    int M, int N, int K)
{
    extern __shared__ float sm[];
    uint32_t sbase = smem_u32(sm);

    const float* Bm = B0; float* Cm = C0;
    if (blockIdx.z == 1) { Bm = B1; Cm = C1; }
    else if (blockIdx.z == 2) { Bm = B2; Cm = C2; }

    int tid  = threadIdx.x;
    int lane = tid & 31, wid = tid >> 5;
    int warp_m = (wid >> 2) * 64;
    int warp_n = (wid & 3) * 64;
    int rowBase = blockIdx.y * GBM;
    int colBase = blockIdx.x * GBN;
    int r4 = lane >> 2, c4 = lane & 3;

    const float* Ag[4]; uint32_t aOff[4];
    #pragma unroll
    for (int j = 0; j < 4; j++) {
        int slot = tid + 256 * j;
        int r = slot >> 3, c = (slot & 7) * 4;
        Ag[j] = A + (size_t)(rowBase + r) * K + c;
        aOff[j] = (uint32_t)(r * GPITCH + c) * 4u;
    }
    const float* Bg[8]; uint32_t bOff[8];
    #pragma unroll
    for (int j = 0; j < 8; j++) {
        int slot = tid + 256 * j;
        int r = slot >> 3, c = (slot & 7) * 4;
        Bg[j] = Bm + (size_t)(colBase + r) * K + c;
        bOff[j] = (uint32_t)(r * GPITCH + c) * 4u;
    }

    auto issue_tile = [&](int tt, int stage) {
        int k0 = tt * GBK;
        uint32_t sA = sbase + (uint32_t)stage * (STG_FLOATS * 4u);
        uint32_t sB = sA + A_FLOATS * 4u;
        #pragma unroll
        for (int j = 0; j < 4; j++) CP_ASYNC16(sA + aOff[j], Ag[j] + k0);
        #pragma unroll
        for (int j = 0; j < 8; j++) CP_ASYNC16(sB + bOff[j], Bg[j] + k0);
    };

    float acc[4][8][4];
    #pragma unroll
    for (int i = 0; i < 4; i++)
        #pragma unroll
        for (int j = 0; j < 8; j++)
            #pragma unroll
            for (int e = 0; e < 4; e++) acc[i][j][e] = 0.f;

    int T = K / GBK;
    issue_tile(0, 0);
    asm volatile("cp.async.commit_group;");
    issue_tile(1, 1);
    asm volatile("cp.async.commit_group;");

    int st_c = 0, st_l = 2;
    for (int t = 0; t < T; t++) {
        asm volatile("cp.async.wait_group 1;");
        __syncthreads();

        int nt = t + 2;
        int tt = (nt >= T) ? nt - T : nt;
        issue_tile(tt, st_l);
        asm volatile("cp.async.commit_group;");
        st_l = (st_l == 2) ? 0 : st_l + 1;

        const float* As = sm + st_c * STG_FLOATS;
        const float* Bs = As + A_FLOATS;
        st_c = (st_c == 2) ? 0 : st_c + 1;

        #pragma unroll
        for (int kk = 0; kk < 4; kk++) {
            int k8 = kk * 8;
            uint32_t af[4][4], bf[8][2];
            #pragma unroll
            for (int i = 0; i < 4; i++) {
                const float* ap = As + (warp_m + 16 * i) * GPITCH + k8;
                af[i][0] = __float_as_uint(ap[(r4    ) * GPITCH + c4    ]);
                af[i][1] = __float_as_uint(ap[(r4 + 8) * GPITCH + c4    ]);
                af[i][2] = __float_as_uint(ap[(r4    ) * GPITCH + c4 + 4]);
                af[i][3] = __float_as_uint(ap[(r4 + 8) * GPITCH + c4 + 4]);
            }
            #pragma unroll
            for (int j = 0; j < 8; j++) {
                const float* bp = Bs + (warp_n + 8 * j) * GPITCH + k8;
                bf[j][0] = __float_as_uint(bp[r4 * GPITCH + c4    ]);
                bf[j][1] = __float_as_uint(bp[r4 * GPITCH + c4 + 4]);
            }
            #pragma unroll
            for (int i = 0; i < 4; i++)
                #pragma unroll
                for (int j = 0; j < 8; j++)
                    mma_tf32(acc[i][j][0], acc[i][j][1], acc[i][j][2], acc[i][j][3],
                             af[i][0], af[i][1], af[i][2], af[i][3],
                             bf[j][0], bf[j][1]);
        }
    }

    #pragma unroll
    for (int i = 0; i < 4; i++) {
        int row = rowBase + warp_m + i * 16 + r4;
        #pragma unroll
        for (int j = 0; j < 8; j++) {
            int col = colBase + warp_n + j * 8 + c4 * 2;
            float2 lo = make_float2(acc[i][j][0], acc[i][j][1]);
            float2 hi = make_float2(acc[i][j][2], acc[i][j][3]);
            if (EPI == 0) {
                lo.x = f2tf(lo.x); lo.y = f2tf(lo.y);
                hi.x = f2tf(hi.x); hi.y = f2tf(hi.y);
            } else if (EPI == 1) {
                float2 bi = *(const float2*)&bias[col];
                lo.x = f2tf(fmaxf(lo.x + bi.x, 0.f)); lo.y = f2tf(fmaxf(lo.y + bi.y, 0.f));
                hi.x = f2tf(fmaxf(hi.x + bi.x, 0.f)); hi.y = f2tf(fmaxf(hi.y + bi.y, 0.f));
            } else if (EPI == 2) {
                float2 bi = *(const float2*)&bias[col];
                float2 r0 = *(const float2*)&res[(size_t)row * N + col];
                float2 r1 = *(const float2*)&res[(size_t)(row + 8) * N + col];
                lo.x += bi.x + r0.x; lo.y += bi.y + r0.y;
                hi.x += bi.x + r1.x; hi.y += bi.y + r1.y;
            } else if (EPI == 3) {
                float2 r0 = *(const float2*)&res[(size_t)row * N + col];
                float2 r1 = *(const float2*)&res[(size_t)(row + 8) * N + col];
                lo.x += r0.x; lo.y += r0.y;
                hi.x += r1.x; hi.y += r1.y;
            }
            *(float2*)&Cm[(size_t)row * N + col]       = lo;
            *(float2*)&Cm[(size_t)(row + 8) * N + col] = hi;
        }
    }
}

// ---------------- LayerNorm (torch: ddof=1, eps added to std) --------------
__global__ void __launch_bounds__(256) ln_kernel(
    const float* __restrict__ x, float* __restrict__ y,
    const float* __restrict__ alpha, const float* __restrict__ beta)
{
    int row = blockIdx.x;
    const float4* xr = (const float4*)(x + (size_t)row * D_MODEL);
    float4 v = xr[threadIdx.x];
    float s  = v.x + v.y + v.z + v.w;
    float sq = v.x*v.x + v.y*v.y + v.z*v.z + v.w*v.w;

    __shared__ float red[18];
    #pragma unroll
    for (int o = 16; o; o >>= 1) {
        s  += __shfl_xor_sync(0xffffffffu, s,  o);
        sq += __shfl_xor_sync(0xffffffffu, sq, o);
    }
    int w = threadIdx.x >> 5;
    if ((threadIdx.x & 31) == 0) { red[w] = s; red[8 + w] = sq; }
    __syncthreads();
    if (threadIdx.x == 0) {
        float ts = 0.f, tq = 0.f;
        #pragma unroll
        for (int i = 0; i < 8; i++) { ts += red[i]; tq += red[8 + i]; }
        red[16] = ts; red[17] = tq;
    }
    __syncthreads();
    float ts = red[16], tq = red[17];

    float mean = ts * (1.0f / D_MODEL);
    float var  = (tq - ts * mean) * (1.0f / (D_MODEL - 1));
    var = fmaxf(var, 0.0f);
    float denom = sqrtf(var) + 1e-6f;
    float a  = alpha[0], be = beta[0];
    float r  = a / denom;

    float4 o;
    o.x = f2tf((v.x - mean) * r + be);
    o.y = f2tf((v.y - mean) * r + be);
    o.z = f2tf((v.z - mean) * r + be);
    o.w = f2tf((v.w - mean) * r + be);
    ((float4*)(y + (size_t)row * D_MODEL))[threadIdx.x] = o;
}

// ============== Flash attention with tf32 mma.sync ========================
// CTA: 128 q-rows x 1 head. 8 warps, 16 q-rows each. KV tile 64, 2-stage cp.async.
#define BQ  128
#define BKV 64
#define QP  68
#define KP  68
#define VP  72
#define PP  68
#define ATTN_SMEM ((BQ*QP + 2*BKV*KP + 2*BKV*VP + BQ*PP)*4 + 2*64*4)

__global__ void __launch_bounds__(256, 1) attn_mma(
    const float* __restrict__ q, const float* __restrict__ k,
    const float* __restrict__ v, const int* __restrict__ mask,
    float* __restrict__ ctx)
{
    extern __shared__ float sm[];
    float* Qs = sm;                       // [128][68]
    float* Ks = Qs + BQ*QP;               // 2 x [64][68]
    float* Vs = Ks + 2*BKV*KP;            // 2 x [64][72]  raw [kv][d]
    float* Ps = Vs + 2*BKV*VP;            // [128][68]
    int*   ms = (int*)(Ps + BQ*PP);       // 2 x [64]

    int tid = threadIdx.x, lane = tid & 31, wid = tid >> 5;
    int r4 = lane >> 2, c4 = lane & 3;
    int qt = blockIdx.x, h = blockIdx.y, b = blockIdx.z;
    int qbase = qt * BQ;
    int wq = wid * 16;

    const float* qp = q + (size_t)(b * SEQ) * D_MODEL + h * DK;
    const float* kp = k + (size_t)(b * SEQ) * D_MODEL + h * DK;
    const float* vp = v + (size_t)(b * SEQ) * D_MODEL + h * DK;
    const int* maskb = mask + b * SEQ;

    // Q tile (already tf32-rounded by the QKV GEMM)
    #pragma unroll
    for (int i = 0; i < 8; i++) {
        int slot = tid + i * 256;           // 2048 float4 slots
        int r = slot >> 4, c = (slot & 15) * 4;
        *(float4*)&Qs[r * QP + c] =
            *(const float4*)(qp + (size_t)(qbase + r) * D_MODEL + c);
    }

    uint32_t ksb = smem_u32(Ks), vsb = smem_u32(Vs);
    auto issue = [&](int tt) {
        int buf = tt & 1, kv0 = tt * BKV;
        #pragma unroll
        for (int i = 0; i < 4; i++) {
            int slot = tid + i * 256;       // 1024 chunks
            int r = slot >> 4, c = (slot & 15) * 4;
            CP_ASYNC16(ksb + (uint32_t)(buf*BKV*KP + r*KP + c)*4u,
                       kp + (size_t)(kv0 + r) * D_MODEL + c);
            CP_ASYNC16(vsb + (uint32_t)(buf*BKV*VP + r*VP + c)*4u,
                       vp + (size_t)(kv0 + r) * D_MODEL + c);
        }
        asm volatile("cp.async.commit_group;");
    };

    issue(0);
    issue(1);
    if (tid < 64)       ms[tid] = maskb[tid];
    else if (tid < 128) ms[tid] = maskb[tid];   // ms[64..127] = tile 1

    float m0 = -1e30f, m1 = -1e30f, l0 = 0.f, l1 = 0.f;
    float oacc[8][4];
    #pragma unroll
    for (int j = 0; j < 8; j++)
        #pragma unroll
        for (int e = 0; e < 4; e++) oacc[j][e] = 0.f;

    const int T = SEQ / BKV;   // 32
    for (int t = 0; t < T; t++) {
        int buf = t & 1;
        asm volatile("cp.async.wait_group 1;");
        __syncthreads();

        const float* Kb = Ks + buf * BKV * KP;
        const float* Vb = Vs + buf * BKV * VP;
        const int*   mb = ms + buf * 64;

        // ---- S = Q @ K^T (16 x 64 per warp) ----
        float sacc[8][4];
        #pragma unroll
        for (int j = 0; j < 8; j++)
            #pragma unroll
            for (int e = 0; e < 4; e++) sacc[j][e] = 0.f;

        const float* qrow = Qs + wq * QP;
        #pragma unroll
        for (int kk = 0; kk < 8; kk++) {
            int k8 = kk * 8;
            uint32_t a0 = __float_as_uint(qrow[(r4    ) * QP + k8 + c4    ]);
            uint32_t a1 = __float_as_uint(qrow[(r4 + 8) * QP + k8 + c4    ]);
            uint32_t a2 = __float_as_uint(qrow[(r4    ) * QP + k8 + c4 + 4]);
            uint32_t a3 = __float_as_uint(qrow[(r4 + 8) * QP + k8 + c4 + 4]);
            #pragma unroll
            for (int j = 0; j < 8; j++) {
                uint32_t b0 = __float_as_uint(Kb[(j*8 + r4) * KP + k8 + c4    ]);
                uint32_t b1 = __float_as_uint(Kb[(j*8 + r4) * KP + k8 + c4 + 4]);
                mma_tf32(sacc[j][0], sacc[j][1], sacc[j][2], sacc[j][3],
                         a0, a1, a2, a3, b0, b1);
            }
        }

        // ---- mask + scale; row max ----
        float rmax0 = -1e30f, rmax1 = -1e30f;
        #pragma unroll
        for (int j = 0; j < 8; j++) {
            int col = j * 8 + 2 * c4;
            int mk0 = mb[col], mk1 = mb[col + 1];
            sacc[j][0] = mk0 ? sacc[j][0] * 0.125f : -1e9f;
            sacc[j][1] = mk1 ? sacc[j][1] * 0.125f : -1e9f;
            sacc[j][2] = mk0 ? sacc[j][2] * 0.125f : -1e9f;
            sacc[j][3] = mk1 ? sacc[j][3] * 0.125f : -1e9f;
            rmax0 = fmaxf(rmax0, fmaxf(sacc[j][0], sacc[j][1]));
            rmax1 = fmaxf(rmax1, fmaxf(sacc[j][2], sacc[j][3]));
        }
        rmax0 = fmaxf(rmax0, __shfl_xor_sync(0xffffffffu, rmax0, 1));
        rmax0 = fmaxf(rmax0, __shfl_xor_sync(0xffffffffu, rmax0, 2));
        rmax1 = fmaxf(rmax1, __shfl_xor_sync(0xffffffffu, rmax1, 1));
        rmax1 = fmaxf(rmax1, __shfl_xor_sync(0xffffffffu, rmax1, 2));

        float mnew0 = fmaxf(m0, rmax0), mnew1 = fmaxf(m1, rmax1);
        float sc0 = __expf(m0 - mnew0), sc1 = __expf(m1 - mnew1);

        // ---- exp, write P to smem (tf32-rounded), row sums ----
        float rsum0 = 0.f, rsum1 = 0.f;
        float* prow = Ps + wq * PP;
        #pragma unroll
        for (int j = 0; j < 8; j++) {
            float p0 = __expf(sacc[j][0] - mnew0);
            float p1 = __expf(sacc[j][1] - mnew0);
            float p2 = __expf(sacc[j][2] - mnew1);
            float p3 = __expf(sacc[j][3] - mnew1);
            rsum0 += p0 + p1; rsum1 += p2 + p3;
            int col = j * 8 + 2 * c4;
            *(float2*)&prow[(r4    ) * PP + col] = make_float2(f2tf(p0), f2tf(p1));
            *(float2*)&prow[(r4 + 8) * PP + col] = make_float2(f2tf(p2), f2tf(p3));
        }
        rsum0 += __shfl_xor_sync(0xffffffffu, rsum0, 1);
        rsum0 += __shfl_xor_sync(0xffffffffu, rsum0, 2);
        rsum1 += __shfl_xor_sync(0xffffffffu, rsum1, 1);
        rsum1 += __shfl_xor_sync(0xffffffffu, rsum1, 2);

        l0 = l0 * sc0 + rsum0; m0 = mnew0;
        l1 = l1 * sc1 + rsum1; m1 = mnew1;
        #pragma unroll
        for (int j = 0; j < 8; j++) {
            oacc[j][0] *= sc0; oacc[j][1] *= sc0;
            oacc[j][2] *= sc1; oacc[j][3] *= sc1;
        }
        __syncwarp();

        // ---- O += P @ V  (A = P[16][64], B = V^T via raw [kv][d] reads) ----
        #pragma unroll
        for (int kk = 0; kk < 8; kk++) {
            int k8 = kk * 8;
            uint32_t a0 = __float_as_uint(prow[(r4    ) * PP + k8 + c4    ]);
            uint32_t a1 = __float_as_uint(prow[(r4 + 8) * PP + k8 + c4    ]);
            uint32_t a2 = __float_as_uint(prow[(r4    ) * PP + k8 + c4 + 4]);
            uint32_t a3 = __float_as_uint(prow[(r4 + 8) * PP + k8 + c4 + 4]);
            #pragma unroll
            for (int j = 0; j < 8; j++) {
                uint32_t b0 = __float_as_uint(Vb[(k8 + c4    ) * VP + j*8 + r4]);
                uint32_t b1 = __float_as_uint(Vb[(k8 + c4 + 4) * VP + j*8 + r4]);
                mma_tf32(oacc[j][0], oacc[j][1], oacc[j][2], oacc[j][3],
                         a0, a1, a2, a3, b0, b1);
            }
        }
        __syncthreads();

        if (t + 2 < T) {
            issue(t + 2);
            if (tid < 64) ms[buf * 64 + tid] = maskb[(t + 2) * BKV + tid];
        }
    }

    // ---- finalize: O / l, round for the O-projection GEMM ----
    float inv0 = 1.0f / l0, inv1 = 1.0f / l1;
    float* op = ctx + (size_t)(b * SEQ + qbase + wq) * D_MODEL + h * DK;
    #pragma unroll
    for (int j = 0; j < 8; j++) {
        int col = j * 8 + 2 * c4;
        *(float2*)&op[(size_t)(r4    ) * D_MODEL + col] =
            make_float2(f2tf(oacc[j][0] * inv0), f2tf(oacc[j][1] * inv0));
        *(float2*)&op[(size_t)(r4 + 8) * D_MODEL + col] =
            make_float2(f2tf(oacc[j][2] * inv1), f2tf(oacc[j][3] * inv1));
    }
}

// ---------------- launch ---------------------------------------------------
extern "C" void kernel_launch(void* const* d_in, const int* in_sizes, int n_in,
                              void* d_out, int out_size)
{
    const float* src  = (const float*)d_in[0];
    const int*   mask = (const int*)  d_in[1];
    const float* wq   = (const float*)d_in[2];
    const float* wk   = (const float*)d_in[3];
    const float* wv   = (const float*)d_in[4];
    const float* wo   = (const float*)d_in[5];
    const float* w1   = (const float*)d_in[6];
    const float* b1   = (const float*)d_in[7];
    const float* w2   = (const float*)d_in[8];
    const float* b2   = (const float*)d_in[9];
    const float* a1   = (const float*)d_in[10];
    const float* be1  = (const float*)d_in[11];
    const float* a2   = (const float*)d_in[12];
    const float* be2  = (const float*)d_in[13];
    float* out = (float*)d_out;

    float *xln, *qb, *kb, *vb, *ctx, *out1, *x2, *ffh;
    float *wqr, *wkr, *wvr, *wor, *w1r, *w2r;
    cudaGetSymbolAddress((void**)&xln,  g_xln);
    cudaGetSymbolAddress((void**)&qb,   g_q);
    cudaGetSymbolAddress((void**)&kb,   g_k);
    cudaGetSymbolAddress((void**)&vb,   g_v);
    cudaGetSymbolAddress((void**)&ctx,  g_ctx);
    cudaGetSymbolAddress((void**)&out1, g_out1);
    cudaGetSymbolAddress((void**)&x2,   g_x2);
    cudaGetSymbolAddress((void**)&ffh,  g_ffh);
    cudaGetSymbolAddress((void**)&wqr,  g_wqr);
    cudaGetSymbolAddress((void**)&wkr,  g_wkr);
    cudaGetSymbolAddress((void**)&wvr,  g_wvr);
    cudaGetSymbolAddress((void**)&wor,  g_wor);
    cudaGetSymbolAddress((void**)&w1r,  g_w1r);
    cudaGetSymbolAddress((void**)&w2r,  g_w2r);

    int gsm = GEMM_SMEM;
    cudaFuncSetAttribute(tcgemm<0>, cudaFuncAttributeMaxDynamicSharedMemorySize, gsm);
    cudaFuncSetAttribute(tcgemm<1>, cudaFuncAttributeMaxDynamicSharedMemorySize, gsm);
    cudaFuncSetAttribute(tcgemm<2>, cudaFuncAttributeMaxDynamicSharedMemorySize, gsm);
    cudaFuncSetAttribute(tcgemm<3>, cudaFuncAttributeMaxDynamicSharedMemorySize, gsm);
    cudaFuncSetAttribute(attn_mma, cudaFuncAttributeMaxDynamicSharedMemorySize, ATTN_SMEM);

    // 0) round weights to tf32
    round_weights<<<2048, 256>>>(
        (const float4*)wq, (const float4*)wk, (const float4*)wv, (const float4*)wo,
        (const float4*)w1, (const float4*)w2,
        (float4*)wqr, (float4*)wkr, (float4*)wvr, (float4*)wor,
        (float4*)w1r, (float4*)w2r);

    // 1) LN1
    ln_kernel<<<MROWS, 256>>>(src, xln, a1, be1);

    // 2) QKV projections (EPI 0 rounds outputs to tf32 for the attention MMAs)
    tcgemm<0><<<dim3(D_MODEL/GBN, MROWS/GBM, 3), 256, gsm>>>(
        xln, wqr, wkr, wvr, qb, kb, vb, nullptr, nullptr, MROWS, D_MODEL, D_MODEL);

    // 3) flash attention on tensor cores
    attn_mma<<<dim3(SEQ/BQ, NH, BATCH), 256, ATTN_SMEM>>>(qb, kb, vb, mask, ctx);

    // 4) output projection + residual: out1 = src + ctx @ wo^T
    tcgemm<3><<<dim3(D_MODEL/GBN, MROWS/GBM, 1), 256, gsm>>>(
        ctx, wor, wor, wor, out1, out1, out1, nullptr, src, MROWS, D_MODEL, D_MODEL);

    // 5) LN2
    ln_kernel<<<MROWS, 256>>>(out1, x2, a2, be2);

    // 6) FFN up: ffh = round(relu(x2 @ w1^T + b1))
    tcgemm<1><<<dim3(DFF/GBN, MROWS/GBM, 1), 256, gsm>>>(
        x2, w1r, w1r, w1r, ffh, ffh, ffh, b1, nullptr, MROWS, DFF, D_MODEL);

    // 7) FFN down + residual: out = out1 + ffh @ w2^T + b2
    tcgemm<2><<<dim3(D_MODEL/GBN, MROWS/GBM, 1), 256, gsm>>>(
        ffh, w2r, w2r, w2r, out, out, out, b2, out1, MROWS, D_MODEL, DFF);
}

// round 8
// speedup vs baseline: 5.5956x; 1.7191x over previous
#include <cuda_runtime.h>
#include <cuda_fp16.h>
#include <math.h>
#include <stdint.h>

#define D_MODEL 1024
#define NH      16
#define DK      64
#define DFF     4096
#define BATCH   2
#define SEQ     2048
#define MROWS   (BATCH*SEQ)   // 4096

// ---------------- scratch (device globals; no allocation allowed) ----------
__device__ __half h_xln[MROWS*D_MODEL];
__device__ __half h_q  [MROWS*D_MODEL];
__device__ __half h_k  [MROWS*D_MODEL];
__device__ __half h_v  [MROWS*D_MODEL];
__device__ __half h_ctx[MROWS*D_MODEL];
__device__ __half h_x2 [MROWS*D_MODEL];
__device__ __half h_ffh[MROWS*DFF];
__device__ float  g_out1[MROWS*D_MODEL];
// fp16 weights
__device__ __half h_wq[D_MODEL*D_MODEL];
__device__ __half h_wk[D_MODEL*D_MODEL];
__device__ __half h_wv[D_MODEL*D_MODEL];
__device__ __half h_wo[D_MODEL*D_MODEL];
__device__ __half h_w1[DFF*D_MODEL];
__device__ __half h_w2[D_MODEL*DFF];

// ---------------- helpers --------------------------------------------------
static __device__ __forceinline__ uint32_t smem_u32(const void* p) {
    uint32_t a;
    asm("{ .reg .u64 t; cvta.to.shared.u64 t, %1; cvt.u32.u64 %0, t; }"
        : "=r"(a) : "l"(p));
    return a;
}

static __device__ __forceinline__ uint32_t h2u(__half2 h) {
    union { __half2 h; uint32_t u; } x; x.h = h; return x.u;
}

static __device__ __forceinline__ void mma_f16(
    float& c0, float& c1, float& c2, float& c3,
    uint32_t a0, uint32_t a1, uint32_t a2, uint32_t a3,
    uint32_t b0, uint32_t b1)
{
    asm volatile(
        "mma.sync.aligned.m16n8k16.row.col.f32.f16.f16.f32 "
        "{%0,%1,%2,%3}, {%4,%5,%6,%7}, {%8,%9}, {%0,%1,%2,%3};"
        : "+f"(c0), "+f"(c1), "+f"(c2), "+f"(c3)
        : "r"(a0), "r"(a1), "r"(a2), "r"(a3), "r"(b0), "r"(b1));
}

#define CP_ASYNC16(dst, src) \
    asm volatile("cp.async.cg.shared.global [%0], [%1], 16;" :: "r"(dst), "l"(src))

// ---------------- weight conversion fp32 -> fp16 ---------------------------
#define WSEG  (D_MODEL*D_MODEL/4)
#define WBIG  (DFF*D_MODEL/4)
#define WTOT  (4*WSEG + 2*WBIG)

__global__ void round_weights(
    const float4* __restrict__ wq, const float4* __restrict__ wk,
    const float4* __restrict__ wv, const float4* __restrict__ wo,
    const float4* __restrict__ w1, const float4* __restrict__ w2)
{
    for (int i = blockIdx.x * blockDim.x + threadIdx.x; i < WTOT;
         i += gridDim.x * blockDim.x) {
        const float4* s; __half* d; int off;
        if      (i < 1*WSEG) { s = wq; d = h_wq; off = i; }
        else if (i < 2*WSEG) { s = wk; d = h_wk; off = i - 1*WSEG; }
        else if (i < 3*WSEG) { s = wv; d = h_wv; off = i - 2*WSEG; }
        else if (i < 4*WSEG) { s = wo; d = h_wo; off = i - 3*WSEG; }
        else if (i < 4*WSEG + WBIG) { s = w1; d = h_w1; off = i - 4*WSEG; }
        else                 { s = w2; d = h_w2; off = i - 4*WSEG - WBIG; }
        float4 v = s[off];
        *(__half2*)(d + 4*off)     = __floats2half2_rn(v.x, v.y);
        *(__half2*)(d + 4*off + 2) = __floats2half2_rn(v.z, v.w);
    }
}

// ======================= Tensor-core FP16 GEMM ============================
// C[M,N] = A[M,K] * B[N,K]^T, half inputs, fp32 accumulate.
// CTA 128(M) x 256(N) x 32(K); 8 warps 2x4; warp tile 64x64; 3-stage cp.async.
// EPI: 0 = half store (QKV), 1 = bias+relu half store,
//      2 = bias+residual float, 3 = residual float
#define GBM 128
#define GBN 256
#define GBK 32
#define HP 40                                   // halves per row
#define A_HALVES (GBM*HP)
#define B_HALVES (GBN*HP)
#define STG_HALVES (A_HALVES + B_HALVES)        // 15360
#define NSTAGE 3
#define GEMM_SMEM (NSTAGE*STG_HALVES*2)         // 92160 B

template<int EPI>
__global__ void __launch_bounds__(256, 1) hgemm(
    const __half* __restrict__ A,
    const __half* __restrict__ B0, const __half* __restrict__ B1, const __half* __restrict__ B2,
    void* __restrict__ C0, void* __restrict__ C1, void* __restrict__ C2,
    const float* __restrict__ bias, const float* __restrict__ res,
    int M, int N, int K)
{
    extern __shared__ __half smh[];
    uint32_t sbase = smem_u32(smh);

    const __half* Bm = B0; void* Cm = C0;
    if (blockIdx.z == 1) { Bm = B1; Cm = C1; }
    else if (blockIdx.z == 2) { Bm = B2; Cm = C2; }

    int tid  = threadIdx.x;
    int lane = tid & 31, wid = tid >> 5;
    int warp_m = (wid >> 2) * 64;
    int warp_n = (wid & 3) * 64;
    int rowBase = blockIdx.y * GBM;
    int colBase = blockIdx.x * GBN;
    int r4 = lane >> 2, c4 = lane & 3;

    // A: 512 chunks (8 halves), 2/thread; B: 1024 chunks, 4/thread
    const __half* Ag[2]; uint32_t aOff[2];
    #pragma unroll
    for (int j = 0; j < 2; j++) {
        int slot = tid + 256 * j;
        int r = slot >> 2, c = (slot & 3) * 8;
        Ag[j] = A + (size_t)(rowBase + r) * K + c;
        aOff[j] = (uint32_t)(r * HP + c) * 2u;
    }
    const __half* Bg[4]; uint32_t bOff[4];
    #pragma unroll
    for (int j = 0; j < 4; j++) {
        int slot = tid + 256 * j;
        int r = slot >> 2, c = (slot & 3) * 8;
        Bg[j] = Bm + (size_t)(colBase + r) * K + c;
        bOff[j] = (uint32_t)(r * HP + c) * 2u;
    }

    auto issue_tile = [&](int tt, int stage) {
        int k0 = tt * GBK;
        uint32_t sA = sbase + (uint32_t)stage * (STG_HALVES * 2u);
        uint32_t sB = sA + A_HALVES * 2u;
        #pragma unroll
        for (int j = 0; j < 2; j++) CP_ASYNC16(sA + aOff[j], Ag[j] + k0);
        #pragma unroll
        for (int j = 0; j < 4; j++) CP_ASYNC16(sB + bOff[j], Bg[j] + k0);
    };

    float acc[4][8][4];
    #pragma unroll
    for (int i = 0; i < 4; i++)
        #pragma unroll
        for (int j = 0; j < 8; j++)
            #pragma unroll
            for (int e = 0; e < 4; e++) acc[i][j][e] = 0.f;

    int T = K / GBK;
    issue_tile(0, 0);
    asm volatile("cp.async.commit_group;");
    issue_tile(1, 1);
    asm volatile("cp.async.commit_group;");

    int st_c = 0, st_l = 2;
    for (int t = 0; t < T; t++) {
        asm volatile("cp.async.wait_group 1;");
        __syncthreads();

        int nt = t + 2;
        int tt = (nt >= T) ? nt - T : nt;
        issue_tile(tt, st_l);
        asm volatile("cp.async.commit_group;");
        st_l = (st_l == 2) ? 0 : st_l + 1;

        const __half* As = smh + st_c * STG_HALVES;
        const __half* Bs = As + A_HALVES;
        st_c = (st_c == 2) ? 0 : st_c + 1;

        #pragma unroll
        for (int kk = 0; kk < 2; kk++) {
            int k16 = kk * 16;
            uint32_t af[4][4], bf[8][2];
            #pragma unroll
            for (int i = 0; i < 4; i++) {
                const __half* ap = As + (warp_m + 16 * i) * HP + k16 + 2 * c4;
                af[i][0] = h2u(*(const __half2*)(ap + (r4    ) * HP));
                af[i][1] = h2u(*(const __half2*)(ap + (r4 + 8) * HP));
                af[i][2] = h2u(*(const __half2*)(ap + (r4    ) * HP + 8));
                af[i][3] = h2u(*(const __half2*)(ap + (r4 + 8) * HP + 8));
            }
            #pragma unroll
            for (int j = 0; j < 8; j++) {
                const __half* bp = Bs + (warp_n + 8 * j + r4) * HP + k16 + 2 * c4;
                bf[j][0] = h2u(*(const __half2*)(bp));
                bf[j][1] = h2u(*(const __half2*)(bp + 8));
            }
            #pragma unroll
            for (int i = 0; i < 4; i++)
                #pragma unroll
                for (int j = 0; j < 8; j++)
                    mma_f16(acc[i][j][0], acc[i][j][1], acc[i][j][2], acc[i][j][3],
                            af[i][0], af[i][1], af[i][2], af[i][3],
                            bf[j][0], bf[j][1]);
        }
    }

    #pragma unroll
    for (int i = 0; i < 4; i++) {
        int row = rowBase + warp_m + i * 16 + r4;
        #pragma unroll
        for (int j = 0; j < 8; j++) {
            int col = colBase + warp_n + j * 8 + c4 * 2;
            float2 lo = make_float2(acc[i][j][0], acc[i][j][1]);
            float2 hi = make_float2(acc[i][j][2], acc[i][j][3]);
            if (EPI == 0) {
                __half* Ch = (__half*)Cm;
                *(__half2*)&Ch[(size_t)row * N + col]       = __floats2half2_rn(lo.x, lo.y);
                *(__half2*)&Ch[(size_t)(row + 8) * N + col] = __floats2half2_rn(hi.x, hi.y);
            } else if (EPI == 1) {
                float2 bi = *(const float2*)&bias[col];
                __half* Ch = (__half*)Cm;
                *(__half2*)&Ch[(size_t)row * N + col] =
                    __floats2half2_rn(fmaxf(lo.x + bi.x, 0.f), fmaxf(lo.y + bi.y, 0.f));
                *(__half2*)&Ch[(size_t)(row + 8) * N + col] =
                    __floats2half2_rn(fmaxf(hi.x + bi.x, 0.f), fmaxf(hi.y + bi.y, 0.f));
            } else if (EPI == 2) {
                float2 bi = *(const float2*)&bias[col];
                float2 r0 = *(const float2*)&res[(size_t)row * N + col];
                float2 r1 = *(const float2*)&res[(size_t)(row + 8) * N + col];
                float* Cf = (float*)Cm;
                *(float2*)&Cf[(size_t)row * N + col] =
                    make_float2(lo.x + bi.x + r0.x, lo.y + bi.y + r0.y);
                *(float2*)&Cf[(size_t)(row + 8) * N + col] =
                    make_float2(hi.x + bi.x + r1.x, hi.y + bi.y + r1.y);
            } else {
                float2 r0 = *(const float2*)&res[(size_t)row * N + col];
                float2 r1 = *(const float2*)&res[(size_t)(row + 8) * N + col];
                float* Cf = (float*)Cm;
                *(float2*)&Cf[(size_t)row * N + col]       = make_float2(lo.x + r0.x, lo.y + r0.y);
                *(float2*)&Cf[(size_t)(row + 8) * N + col] = make_float2(hi.x + r1.x, hi.y + r1.y);
            }
        }
    }
}

// ---------------- LayerNorm (torch: ddof=1, eps added to std) --------------
// fp32 in, fp16 out (feeds fp16 GEMMs only)
__global__ void __launch_bounds__(256) ln_kernel(
    const float* __restrict__ x, __half* __restrict__ y,
    const float* __restrict__ alpha, const float* __restrict__ beta)
{
    int row = blockIdx.x;
    const float4* xr = (const float4*)(x + (size_t)row * D_MODEL);
    float4 v = xr[threadIdx.x];
    float s  = v.x + v.y + v.z + v.w;
    float sq = v.x*v.x + v.y*v.y + v.z*v.z + v.w*v.w;

    __shared__ float red[18];
    #pragma unroll
    for (int o = 16; o; o >>= 1) {
        s  += __shfl_xor_sync(0xffffffffu, s,  o);
        sq += __shfl_xor_sync(0xffffffffu, sq, o);
    }
    int w = threadIdx.x >> 5;
    if ((threadIdx.x & 31) == 0) { red[w] = s; red[8 + w] = sq; }
    __syncthreads();
    if (threadIdx.x == 0) {
        float ts = 0.f, tq = 0.f;
        #pragma unroll
        for (int i = 0; i < 8; i++) { ts += red[i]; tq += red[8 + i]; }
        red[16] = ts; red[17] = tq;
    }
    __syncthreads();
    float ts = red[16], tq = red[17];

    float mean = ts * (1.0f / D_MODEL);
    float var  = (tq - ts * mean) * (1.0f / (D_MODEL - 1));
    var = fmaxf(var, 0.0f);
    float denom = sqrtf(var) + 1e-6f;
    float a  = alpha[0], be = beta[0];
    float r  = a / denom;

    __half* yr = y + (size_t)row * D_MODEL + threadIdx.x * 4;
    *(__half2*)(yr)     = __floats2half2_rn((v.x - mean) * r + be, (v.y - mean) * r + be);
    *(__half2*)(yr + 2) = __floats2half2_rn((v.z - mean) * r + be, (v.w - mean) * r + be);
}

// ============== Flash attention, fp16 mma (m16n8k16) ======================
// CTA: 128 q-rows x 1 head; 8 warps x 16 rows; KV tile 64, 2-stage cp.async.
// P never hits smem: S-accumulator fragments repack directly into PV A-frags.
#define BQ  128
#define BKV 64
#define QP  72
#define KP  72
#define VP  72
#define ATTN_SMEM ((BQ*QP + 2*BKV*KP + 2*BKV*VP)*2 + 2*64*4)

__global__ void __launch_bounds__(256, 2) attn_mma(
    const __half* __restrict__ q, const __half* __restrict__ k,
    const __half* __restrict__ v, const int* __restrict__ mask,
    __half* __restrict__ ctx)
{
    extern __shared__ __half sa[];
    __half* Qs = sa;                      // [128][72]
    __half* Ks = Qs + BQ*QP;              // 2 x [64][72]
    __half* Vs = Ks + 2*BKV*KP;           // 2 x [64][72]  raw [kv][d]
    int*    ms = (int*)(Vs + 2*BKV*VP);   // 2 x [64]

    int tid = threadIdx.x, lane = tid & 31, wid = tid >> 5;
    int r4 = lane >> 2, c4 = lane & 3;
    int qt = blockIdx.x, h = blockIdx.y, b = blockIdx.z;
    int qbase = qt * BQ;
    int wq = wid * 16;

    const __half* qp = q + (size_t)(b * SEQ) * D_MODEL + h * DK;
    const __half* kp = k + (size_t)(b * SEQ) * D_MODEL + h * DK;
    const __half* vp = v + (size_t)(b * SEQ) * D_MODEL + h * DK;
    const int* maskb = mask + b * SEQ;

    // Q tile: 128 rows x 64 halves = 1024 16B chunks
    #pragma unroll
    for (int i = 0; i < 4; i++) {
        int slot = tid + i * 256;
        int r = slot >> 3, c = (slot & 7) * 8;
        *(uint4*)&Qs[r * QP + c] = *(const uint4*)(qp + (size_t)(qbase + r) * D_MODEL + c);
    }

    uint32_t ksb = smem_u32(Ks), vsb = smem_u32(Vs);
    auto issue = [&](int tt) {
        int buf = tt & 1, kv0 = tt * BKV;
        #pragma unroll
        for (int i = 0; i < 4; i++) {
            int slot = tid + i * 256;     // 1024 chunks for K+V (512 each)
            int r = (slot & 511) >> 3, c = (slot & 7) * 8;
            if (slot < 512)
                CP_ASYNC16(ksb + (uint32_t)(buf*BKV*KP + r*KP + c)*2u,
                           kp + (size_t)(kv0 + r) * D_MODEL + c);
            else
                CP_ASYNC16(vsb + (uint32_t)(buf*BKV*VP + r*VP + c)*2u,
                           vp + (size_t)(kv0 + r) * D_MODEL + c);
        }
        asm volatile("cp.async.commit_group;");
    };

    issue(0);
    issue(1);
    if (tid < 128) ms[tid] = maskb[tid];
    __syncthreads();   // Qs visible to all (frag caching below reads own rows only, but cheap)

    // cache Q fragments for the whole KV loop: 4 k16-steps x 4 regs
    uint32_t afq[4][4];
    {
        const __half* qrow = Qs + wq * QP + 2 * c4;
        #pragma unroll
        for (int kk = 0; kk < 4; kk++) {
            int k16 = kk * 16;
            afq[kk][0] = h2u(*(const __half2*)(qrow + (r4    ) * QP + k16));
            afq[kk][1] = h2u(*(const __half2*)(qrow + (r4 + 8) * QP + k16));
            afq[kk][2] = h2u(*(const __half2*)(qrow + (r4    ) * QP + k16 + 8));
            afq[kk][3] = h2u(*(const __half2*)(qrow + (r4 + 8) * QP + k16 + 8));
        }
    }

    float m0 = -1e30f, m1 = -1e30f, l0 = 0.f, l1 = 0.f;
    float oacc[8][4];
    #pragma unroll
    for (int j = 0; j < 8; j++)
        #pragma unroll
        for (int e = 0; e < 4; e++) oacc[j][e] = 0.f;

    const int T = SEQ / BKV;   // 32
    for (int t = 0; t < T; t++) {
        int buf = t & 1;
        asm volatile("cp.async.wait_group 1;");
        __syncthreads();

        const __half* Kb = Ks + buf * BKV * KP;
        const __half* Vb = Vs + buf * BKV * VP;
        const int*    mb = ms + buf * 64;

        // ---- S = Q @ K^T (16 x 64 per warp) ----
        float sacc[8][4];
        #pragma unroll
        for (int j = 0; j < 8; j++)
            #pragma unroll
            for (int e = 0; e < 4; e++) sacc[j][e] = 0.f;

        #pragma unroll
        for (int kk = 0; kk < 4; kk++) {
            int k16 = kk * 16;
            #pragma unroll
            for (int j = 0; j < 8; j++) {
                const __half* bp = Kb + (j*8 + r4) * KP + k16 + 2 * c4;
                uint32_t b0 = h2u(*(const __half2*)(bp));
                uint32_t b1 = h2u(*(const __half2*)(bp + 8));
                mma_f16(sacc[j][0], sacc[j][1], sacc[j][2], sacc[j][3],
                        afq[kk][0], afq[kk][1], afq[kk][2], afq[kk][3], b0, b1);
            }
        }

        // ---- mask + scale; row max ----
        float rmax0 = -1e30f, rmax1 = -1e30f;
        #pragma unroll
        for (int j = 0; j < 8; j++) {
            int col = j * 8 + 2 * c4;
            int mk0 = mb[col], mk1 = mb[col + 1];
            sacc[j][0] = mk0 ? sacc[j][0] * 0.125f : -1e9f;
            sacc[j][1] = mk1 ? sacc[j][1] * 0.125f : -1e9f;
            sacc[j][2] = mk0 ? sacc[j][2] * 0.125f : -1e9f;
            sacc[j][3] = mk1 ? sacc[j][3] * 0.125f : -1e9f;
            rmax0 = fmaxf(rmax0, fmaxf(sacc[j][0], sacc[j][1]));
            rmax1 = fmaxf(rmax1, fmaxf(sacc[j][2], sacc[j][3]));
        }
        rmax0 = fmaxf(rmax0, __shfl_xor_sync(0xffffffffu, rmax0, 1));
        rmax0 = fmaxf(rmax0, __shfl_xor_sync(0xffffffffu, rmax0, 2));
        rmax1 = fmaxf(rmax1, __shfl_xor_sync(0xffffffffu, rmax1, 1));
        rmax1 = fmaxf(rmax1, __shfl_xor_sync(0xffffffffu, rmax1, 2));

        float mnew0 = fmaxf(m0, rmax0), mnew1 = fmaxf(m1, rmax1);
        float sc0 = __expf(m0 - mnew0), sc1 = __expf(m1 - mnew1);

        // ---- exp; pack P into PV A-fragments directly ----
        float rsum0 = 0.f, rsum1 = 0.f;
        uint32_t ap[4][4];
        #pragma unroll
        for (int j = 0; j < 8; j++) {
            float p0 = __expf(sacc[j][0] - mnew0);
            float p1 = __expf(sacc[j][1] - mnew0);
            float p2 = __expf(sacc[j][2] - mnew1);
            float p3 = __expf(sacc[j][3] - mnew1);
            rsum0 += p0 + p1; rsum1 += p2 + p3;
            int kk = j >> 1, hi = j & 1;
            ap[kk][hi ? 2 : 0] = h2u(__floats2half2_rn(p0, p1));
            ap[kk][hi ? 3 : 1] = h2u(__floats2half2_rn(p2, p3));
        }
        rsum0 += __shfl_xor_sync(0xffffffffu, rsum0, 1);
        rsum0 += __shfl_xor_sync(0xffffffffu, rsum0, 2);
        rsum1 += __shfl_xor_sync(0xffffffffu, rsum1, 1);
        rsum1 += __shfl_xor_sync(0xffffffffu, rsum1, 2);

        l0 = l0 * sc0 + rsum0; m0 = mnew0;
        l1 = l1 * sc1 + rsum1; m1 = mnew1;
        #pragma unroll
        for (int j = 0; j < 8; j++) {
            oacc[j][0] *= sc0; oacc[j][1] *= sc0;
            oacc[j][2] *= sc1; oacc[j][3] *= sc1;
        }

        // ---- O += P @ V  (B from raw [kv][d] via scalar half pairs) ----
        #pragma unroll
        for (int kk = 0; kk < 4; kk++) {
            int k16 = kk * 16;
            #pragma unroll
            for (int j = 0; j < 8; j++) {
                int vj = j * 8 + r4;
                uint32_t b0 = h2u(__halves2half2(Vb[(k16 + 2*c4    ) * VP + vj],
                                                 Vb[(k16 + 2*c4 + 1) * VP + vj]));
                uint32_t b1 = h2u(__halves2half2(Vb[(k16 + 2*c4 + 8) * VP + vj],
                                                 Vb[(k16 + 2*c4 + 9) * VP + vj]));
                mma_f16(oacc[j][0], oacc[j][1], oacc[j][2], oacc[j][3],
                        ap[kk][0], ap[kk][1], ap[kk][2], ap[kk][3], b0, b1);
            }
        }
        __syncthreads();

        if (t + 2 < T) {
            issue(t + 2);
            if (tid < 64) ms[buf * 64 + tid] = maskb[(t + 2) * BKV + tid];
        }
    }

    // ---- finalize: O / l -> half ctx ----
    float inv0 = 1.0f / l0, inv1 = 1.0f / l1;
    __half* op = ctx + (size_t)(b * SEQ + qbase + wq) * D_MODEL + h * DK;
    #pragma unroll
    for (int j = 0; j < 8; j++) {
        int col = j * 8 + 2 * c4;
        *(__half2*)&op[(size_t)(r4    ) * D_MODEL + col] =
            __floats2half2_rn(oacc[j][0] * inv0, oacc[j][1] * inv0);
        *(__half2*)&op[(size_t)(r4 + 8) * D_MODEL + col] =
            __floats2half2_rn(oacc[j][2] * inv1, oacc[j][3] * inv1);
    }
}

// ---------------- launch ---------------------------------------------------
extern "C" void kernel_launch(void* const* d_in, const int* in_sizes, int n_in,
                              void* d_out, int out_size)
{
    const float* src  = (const float*)d_in[0];
    const int*   mask = (const int*)  d_in[1];
    const float* wq   = (const float*)d_in[2];
    const float* wk   = (const float*)d_in[3];
    const float* wv   = (const float*)d_in[4];
    const float* wo   = (const float*)d_in[5];
    const float* w1   = (const float*)d_in[6];
    const float* b1   = (const float*)d_in[7];
    const float* w2   = (const float*)d_in[8];
    const float* b2   = (const float*)d_in[9];
    const float* a1   = (const float*)d_in[10];
    const float* be1  = (const float*)d_in[11];
    const float* a2   = (const float*)d_in[12];
    const float* be2  = (const float*)d_in[13];
    float* out = (float*)d_out;

    __half *xln, *qb, *kb, *vb, *ctx, *x2, *ffh;
    __half *pwq, *pwk, *pwv, *pwo, *pw1, *pw2;
    float *out1;
    cudaGetSymbolAddress((void**)&xln,  h_xln);
    cudaGetSymbolAddress((void**)&qb,   h_q);
    cudaGetSymbolAddress((void**)&kb,   h_k);
    cudaGetSymbolAddress((void**)&vb,   h_v);
    cudaGetSymbolAddress((void**)&ctx,  h_ctx);
    cudaGetSymbolAddress((void**)&x2,   h_x2);
    cudaGetSymbolAddress((void**)&ffh,  h_ffh);
    cudaGetSymbolAddress((void**)&out1, g_out1);
    cudaGetSymbolAddress((void**)&pwq,  h_wq);
    cudaGetSymbolAddress((void**)&pwk,  h_wk);
    cudaGetSymbolAddress((void**)&pwv,  h_wv);
    cudaGetSymbolAddress((void**)&pwo,  h_wo);
    cudaGetSymbolAddress((void**)&pw1,  h_w1);
    cudaGetSymbolAddress((void**)&pw2,  h_w2);

    int gsm = GEMM_SMEM;
    cudaFuncSetAttribute(hgemm<0>, cudaFuncAttributeMaxDynamicSharedMemorySize, gsm);
    cudaFuncSetAttribute(hgemm<1>, cudaFuncAttributeMaxDynamicSharedMemorySize, gsm);
    cudaFuncSetAttribute(hgemm<2>, cudaFuncAttributeMaxDynamicSharedMemorySize, gsm);
    cudaFuncSetAttribute(hgemm<3>, cudaFuncAttributeMaxDynamicSharedMemorySize, gsm);
    cudaFuncSetAttribute(attn_mma, cudaFuncAttributeMaxDynamicSharedMemorySize, ATTN_SMEM);

    // 0) weights -> fp16
    round_weights<<<2048, 256>>>(
        (const float4*)wq, (const float4*)wk, (const float4*)wv, (const float4*)wo,
        (const float4*)w1, (const float4*)w2);

    // 1) LN1 -> half
    ln_kernel<<<MROWS, 256>>>(src, xln, a1, be1);

    // 2) QKV projections (half out)
    hgemm<0><<<dim3(D_MODEL/GBN, MROWS/GBM, 3), 256, gsm>>>(
        xln, pwq, pwk, pwv, qb, kb, vb, nullptr, nullptr, MROWS, D_MODEL, D_MODEL);

    // 3) flash attention (fp16 tensor cores) -> half ctx
    attn_mma<<<dim3(SEQ/BQ, NH, BATCH), 256, ATTN_SMEM>>>(qb, kb, vb, mask, ctx);

    // 4) O projection + residual: out1 = src + ctx @ wo^T (float out)
    hgemm<3><<<dim3(D_MODEL/GBN, MROWS/GBM, 1), 256, gsm>>>(
        ctx, pwo, pwo, pwo, out1, out1, out1, nullptr, src, MROWS, D_MODEL, D_MODEL);

    // 5) LN2 -> half
    ln_kernel<<<MROWS, 256>>>(out1, x2, a2, be2);

    // 6) FFN up: ffh = relu(x2 @ w1^T + b1) (half out)
    hgemm<1><<<dim3(DFF/GBN, MROWS/GBM, 1), 256, gsm>>>(
        x2, pw1, pw1, pw1, ffh, ffh, ffh, b1, nullptr, MROWS, DFF, D_MODEL);

    // 7) FFN down + residual: out = out1 + ffh @ w2^T + b2 (float out)
    hgemm<2><<<dim3(D_MODEL/GBN, MROWS/GBM, 1), 256, gsm>>>(
        ffh, pw2, pw2, pw2, out, out, out, b2, out1, MROWS, D_MODEL, DFF);
}

// round 9
// speedup vs baseline: 6.7489x; 1.2061x over previous
#include <cuda_runtime.h>
#include <cuda_fp16.h>
#include <math.h>
#include <stdint.h>

#define D_MODEL 1024
#define NH      16
#define DK      64
#define DFF     4096
#define BATCH   2
#define SEQ     2048
#define MROWS   (BATCH*SEQ)   // 4096

// ---------------- scratch (device globals; no allocation allowed) ----------
__device__ __half h_xln[MROWS*D_MODEL];
__device__ __half h_q  [MROWS*D_MODEL];
__device__ __half h_k  [MROWS*D_MODEL];
__device__ __half h_v  [MROWS*D_MODEL];
__device__ __half h_ctx[MROWS*D_MODEL];
__device__ __half h_x2 [MROWS*D_MODEL];
__device__ __half h_ffh[MROWS*DFF];
__device__ float  g_out1[MROWS*D_MODEL];
// fp16 weights
__device__ __half h_wq[D_MODEL*D_MODEL];
__device__ __half h_wk[D_MODEL*D_MODEL];
__device__ __half h_wv[D_MODEL*D_MODEL];
__device__ __half h_wo[D_MODEL*D_MODEL];
__device__ __half h_w1[DFF*D_MODEL];
__device__ __half h_w2[D_MODEL*DFF];

// ---------------- helpers --------------------------------------------------
static __device__ __forceinline__ uint32_t smem_u32(const void* p) {
    uint32_t a;
    asm("{ .reg .u64 t; cvta.to.shared.u64 t, %1; cvt.u32.u64 %0, t; }"
        : "=r"(a) : "l"(p));
    return a;
}

static __device__ __forceinline__ uint32_t h2u(__half2 h) {
    union { __half2 h; uint32_t u; } x; x.h = h; return x.u;
}

static __device__ __forceinline__ void mma_f16(
    float& c0, float& c1, float& c2, float& c3,
    uint32_t a0, uint32_t a1, uint32_t a2, uint32_t a3,
    uint32_t b0, uint32_t b1)
{
    asm volatile(
        "mma.sync.aligned.m16n8k16.row.col.f32.f16.f16.f32 "
        "{%0,%1,%2,%3}, {%4,%5,%6,%7}, {%8,%9}, {%0,%1,%2,%3};"
        : "+f"(c0), "+f"(c1), "+f"(c2), "+f"(c3)
        : "r"(a0), "r"(a1), "r"(a2), "r"(a3), "r"(b0), "r"(b1));
}

#define LDMX4(r0,r1,r2,r3,a) \
    asm volatile("ldmatrix.sync.aligned.m8n8.x4.shared.b16 {%0,%1,%2,%3}, [%4];" \
        : "=r"(r0),"=r"(r1),"=r"(r2),"=r"(r3) : "r"(a))
#define LDMX4T(r0,r1,r2,r3,a) \
    asm volatile("ldmatrix.sync.aligned.m8n8.x4.trans.shared.b16 {%0,%1,%2,%3}, [%4];" \
        : "=r"(r0),"=r"(r1),"=r"(r2),"=r"(r3) : "r"(a))

#define CP_ASYNC16(dst, src) \
    asm volatile("cp.async.cg.shared.global [%0], [%1], 16;" :: "r"(dst), "l"(src))

// ---------------- weight conversion fp32 -> fp16 ---------------------------
#define WSEG  (D_MODEL*D_MODEL/4)
#define WBIG  (DFF*D_MODEL/4)
#define WTOT  (4*WSEG + 2*WBIG)

__global__ void round_weights(
    const float4* __restrict__ wq, const float4* __restrict__ wk,
    const float4* __restrict__ wv, const float4* __restrict__ wo,
    const float4* __restrict__ w1, const float4* __restrict__ w2)
{
    for (int i = blockIdx.x * blockDim.x + threadIdx.x; i < WTOT;
         i += gridDim.x * blockDim.x) {
        const float4* s; __half* d; int off;
        if      (i < 1*WSEG) { s = wq; d = h_wq; off = i; }
        else if (i < 2*WSEG) { s = wk; d = h_wk; off = i - 1*WSEG; }
        else if (i < 3*WSEG) { s = wv; d = h_wv; off = i - 2*WSEG; }
        else if (i < 4*WSEG) { s = wo; d = h_wo; off = i - 3*WSEG; }
        else if (i < 4*WSEG + WBIG) { s = w1; d = h_w1; off = i - 4*WSEG; }
        else                 { s = w2; d = h_w2; off = i - 4*WSEG - WBIG; }
        float4 v = s[off];
        *(__half2*)(d + 4*off)     = __floats2half2_rn(v.x, v.y);
        *(__half2*)(d + 4*off + 2) = __floats2half2_rn(v.z, v.w);
    }
}

// ======================= Tensor-core FP16 GEMM ============================
// C[M,N] = A[M,K] * B[N,K]^T, half in, fp32 accumulate; ldmatrix fragments.
// CTA 128x256x32; 8 warps 2x4; warp tile 64x64; 3-stage cp.async.
#define GBM 128
#define GBN 256
#define GBK 32
#define HP 40
#define A_HALVES (GBM*HP)
#define B_HALVES (GBN*HP)
#define STG_HALVES (A_HALVES + B_HALVES)
#define NSTAGE 3
#define GEMM_SMEM (NSTAGE*STG_HALVES*2)

// EPI: 0 = half store, 1 = bias+relu half, 2 = bias+residual float, 3 = residual float
template<int EPI>
__global__ void __launch_bounds__(256, 1) hgemm(
    const __half* __restrict__ A,
    const __half* __restrict__ B0, const __half* __restrict__ B1, const __half* __restrict__ B2,
    void* __restrict__ C0, void* __restrict__ C1, void* __restrict__ C2,
    const float* __restrict__ bias, const float* __restrict__ res,
    int M, int N, int K)
{
    extern __shared__ __half smh[];
    uint32_t sbase = smem_u32(smh);

    const __half* Bm = B0; void* Cm = C0;
    if (blockIdx.z == 1) { Bm = B1; Cm = C1; }
    else if (blockIdx.z == 2) { Bm = B2; Cm = C2; }

    int tid  = threadIdx.x;
    int lane = tid & 31, wid = tid >> 5;
    int warp_m = (wid >> 2) * 64;
    int warp_n = (wid & 3) * 64;
    int rowBase = blockIdx.y * GBM;
    int colBase = blockIdx.x * GBN;
    int r4 = lane >> 2, c4 = lane & 3;
    int lg = lane >> 3, li = lane & 7;

    // ldmatrix per-lane offsets (in halves)
    // A/V-style: row = (g&1)*8+i, col = (g>>1)*8
    uint32_t aLm = (uint32_t)(((lg & 1) * 8 + li) * HP + (lg >> 1) * 8) * 2u;
    // B/K-style: row = (g>>1)*8+i, col = (g&1)*8
    uint32_t bLm = (uint32_t)(((lg >> 1) * 8 + li) * HP + (lg & 1) * 8) * 2u;

    const __half* Ag[2]; uint32_t aOff[2];
    #pragma unroll
    for (int j = 0; j < 2; j++) {
        int slot = tid + 256 * j;
        int r = slot >> 2, c = (slot & 3) * 8;
        Ag[j] = A + (size_t)(rowBase + r) * K + c;
        aOff[j] = (uint32_t)(r * HP + c) * 2u;
    }
    const __half* Bg[4]; uint32_t bOff[4];
    #pragma unroll
    for (int j = 0; j < 4; j++) {
        int slot = tid + 256 * j;
        int r = slot >> 2, c = (slot & 3) * 8;
        Bg[j] = Bm + (size_t)(colBase + r) * K + c;
        bOff[j] = (uint32_t)(r * HP + c) * 2u;
    }

    auto issue_tile = [&](int tt, int stage) {
        int k0 = tt * GBK;
        uint32_t sA = sbase + (uint32_t)stage * (STG_HALVES * 2u);
        uint32_t sB = sA + A_HALVES * 2u;
        #pragma unroll
        for (int j = 0; j < 2; j++) CP_ASYNC16(sA + aOff[j], Ag[j] + k0);
        #pragma unroll
        for (int j = 0; j < 4; j++) CP_ASYNC16(sB + bOff[j], Bg[j] + k0);
    };

    float acc[4][8][4];
    #pragma unroll
    for (int i = 0; i < 4; i++)
        #pragma unroll
        for (int j = 0; j < 8; j++)
            #pragma unroll
            for (int e = 0; e < 4; e++) acc[i][j][e] = 0.f;

    int T = K / GBK;
    issue_tile(0, 0);
    asm volatile("cp.async.commit_group;");
    issue_tile(1, 1);
    asm volatile("cp.async.commit_group;");

    int st_c = 0, st_l = 2;
    for (int t = 0; t < T; t++) {
        asm volatile("cp.async.wait_group 1;");
        __syncthreads();

        int nt = t + 2;
        int tt = (nt >= T) ? nt - T : nt;
        issue_tile(tt, st_l);
        asm volatile("cp.async.commit_group;");
        st_l = (st_l == 2) ? 0 : st_l + 1;

        uint32_t sA = sbase + (uint32_t)st_c * (STG_HALVES * 2u);
        uint32_t sB = sA + A_HALVES * 2u;
        st_c = (st_c == 2) ? 0 : st_c + 1;

        uint32_t aBase = sA + aLm + (uint32_t)(warp_m * HP) * 2u;
        uint32_t bBase = sB + bLm + (uint32_t)(warp_n * HP) * 2u;

        #pragma unroll
        for (int kk = 0; kk < 2; kk++) {
            uint32_t kByte = (uint32_t)(kk * 16) * 2u;
            uint32_t af[4][4], bf[8][2];
            #pragma unroll
            for (int i = 0; i < 4; i++)
                LDMX4(af[i][0], af[i][1], af[i][2], af[i][3],
                      aBase + (uint32_t)(i * 16 * HP) * 2u + kByte);
            #pragma unroll
            for (int jp = 0; jp < 4; jp++)
                LDMX4(bf[2*jp][0], bf[2*jp][1], bf[2*jp+1][0], bf[2*jp+1][1],
                      bBase + (uint32_t)(jp * 16 * HP) * 2u + kByte);
            #pragma unroll
            for (int i = 0; i < 4; i++)
                #pragma unroll
                for (int j = 0; j < 8; j++)
                    mma_f16(acc[i][j][0], acc[i][j][1], acc[i][j][2], acc[i][j][3],
                            af[i][0], af[i][1], af[i][2], af[i][3],
                            bf[j][0], bf[j][1]);
        }
    }

    #pragma unroll
    for (int i = 0; i < 4; i++) {
        int row = rowBase + warp_m + i * 16 + r4;
        #pragma unroll
        for (int j = 0; j < 8; j++) {
            int col = colBase + warp_n + j * 8 + c4 * 2;
            float2 lo = make_float2(acc[i][j][0], acc[i][j][1]);
            float2 hi = make_float2(acc[i][j][2], acc[i][j][3]);
            if (EPI == 0) {
                __half* Ch = (__half*)Cm;
                *(__half2*)&Ch[(size_t)row * N + col]       = __floats2half2_rn(lo.x, lo.y);
                *(__half2*)&Ch[(size_t)(row + 8) * N + col] = __floats2half2_rn(hi.x, hi.y);
            } else if (EPI == 1) {
                float2 bi = *(const float2*)&bias[col];
                __half* Ch = (__half*)Cm;
                *(__half2*)&Ch[(size_t)row * N + col] =
                    __floats2half2_rn(fmaxf(lo.x + bi.x, 0.f), fmaxf(lo.y + bi.y, 0.f));
                *(__half2*)&Ch[(size_t)(row + 8) * N + col] =
                    __floats2half2_rn(fmaxf(hi.x + bi.x, 0.f), fmaxf(hi.y + bi.y, 0.f));
            } else if (EPI == 2) {
                float2 bi = *(const float2*)&bias[col];
                float2 r0 = *(const float2*)&res[(size_t)row * N + col];
                float2 r1 = *(const float2*)&res[(size_t)(row + 8) * N + col];
                float* Cf = (float*)Cm;
                *(float2*)&Cf[(size_t)row * N + col] =
                    make_float2(lo.x + bi.x + r0.x, lo.y + bi.y + r0.y);
                *(float2*)&Cf[(size_t)(row + 8) * N + col] =
                    make_float2(hi.x + bi.x + r1.x, hi.y + bi.y + r1.y);
            } else {
                float2 r0 = *(const float2*)&res[(size_t)row * N + col];
                float2 r1 = *(const float2*)&res[(size_t)(row + 8) * N + col];
                float* Cf = (float*)Cm;
                *(float2*)&Cf[(size_t)row * N + col]       = make_float2(lo.x + r0.x, lo.y + r0.y);
                *(float2*)&Cf[(size_t)(row + 8) * N + col] = make_float2(hi.x + r1.x, hi.y + r1.y);
            }
        }
    }
}

// ---------------- LayerNorm (torch: ddof=1, eps added to std) --------------
__global__ void __launch_bounds__(256) ln_kernel(
    const float* __restrict__ x, __half* __restrict__ y,
    const float* __restrict__ alpha, const float* __restrict__ beta)
{
    int row = blockIdx.x;
    const float4* xr = (const float4*)(x + (size_t)row * D_MODEL);
    float4 v = xr[threadIdx.x];
    float s  = v.x + v.y + v.z + v.w;
    float sq = v.x*v.x + v.y*v.y + v.z*v.z + v.w*v.w;

    __shared__ float red[18];
    #pragma unroll
    for (int o = 16; o; o >>= 1) {
        s  += __shfl_xor_sync(0xffffffffu, s,  o);
        sq += __shfl_xor_sync(0xffffffffu, sq, o);
    }
    int w = threadIdx.x >> 5;
    if ((threadIdx.x & 31) == 0) { red[w] = s; red[8 + w] = sq; }
    __syncthreads();
    if (threadIdx.x == 0) {
        float ts = 0.f, tq = 0.f;
        #pragma unroll
        for (int i = 0; i < 8; i++) { ts += red[i]; tq += red[8 + i]; }
        red[16] = ts; red[17] = tq;
    }
    __syncthreads();
    float ts = red[16], tq = red[17];

    float mean = ts * (1.0f / D_MODEL);
    float var  = (tq - ts * mean) * (1.0f / (D_MODEL - 1));
    var = fmaxf(var, 0.0f);
    float denom = sqrtf(var) + 1e-6f;
    float a  = alpha[0], be = beta[0];
    float r  = a / denom;

    __half* yr = y + (size_t)row * D_MODEL + threadIdx.x * 4;
    *(__half2*)(yr)     = __floats2half2_rn((v.x - mean) * r + be, (v.y - mean) * r + be);
    *(__half2*)(yr + 2) = __floats2half2_rn((v.z - mean) * r + be, (v.w - mean) * r + be);
}

// ============== Flash attention, fp16 mma + ldmatrix ======================
#define BQ  128
#define BKV 64
#define QP  72
#define KP  72
#define VP  72
#define ATTN_SMEM ((BQ*QP + 2*BKV*KP + 2*BKV*VP)*2 + 2*64*4)

__global__ void __launch_bounds__(256, 2) attn_mma(
    const __half* __restrict__ q, const __half* __restrict__ k,
    const __half* __restrict__ v, const int* __restrict__ mask,
    __half* __restrict__ ctx)
{
    extern __shared__ __half sa[];
    __half* Qs = sa;                      // [128][72]
    __half* Ks = Qs + BQ*QP;              // 2 x [64][72]
    __half* Vs = Ks + 2*BKV*KP;           // 2 x [64][72]  raw [kv][d]
    int*    ms = (int*)(Vs + 2*BKV*VP);   // 2 x [64]

    int tid = threadIdx.x, lane = tid & 31, wid = tid >> 5;
    int r4 = lane >> 2, c4 = lane & 3;
    int lg = lane >> 3, li = lane & 7;
    int qt = blockIdx.x, h = blockIdx.y, b = blockIdx.z;
    int qbase = qt * BQ;
    int wq = wid * 16;

    const __half* qp = q + (size_t)(b * SEQ) * D_MODEL + h * DK;
    const __half* kp = k + (size_t)(b * SEQ) * D_MODEL + h * DK;
    const __half* vp = v + (size_t)(b * SEQ) * D_MODEL + h * DK;
    const int* maskb = mask + b * SEQ;

    // ldmatrix per-lane offsets (halves)
    uint32_t kLm = (uint32_t)(((lg >> 1) * 8 + li) * KP + (lg & 1) * 8) * 2u; // B-style
    uint32_t vLm = (uint32_t)(((lg & 1) * 8 + li) * VP + (lg >> 1) * 8) * 2u; // trans-style

    // Q tile
    #pragma unroll
    for (int i = 0; i < 4; i++) {
        int slot = tid + i * 256;
        int r = slot >> 3, c = (slot & 7) * 8;
        *(uint4*)&Qs[r * QP + c] = *(const uint4*)(qp + (size_t)(qbase + r) * D_MODEL + c);
    }

    uint32_t ksb = smem_u32(Ks), vsb = smem_u32(Vs);
    auto issue = [&](int tt) {
        int buf = tt & 1, kv0 = tt * BKV;
        #pragma unroll
        for (int i = 0; i < 4; i++) {
            int slot = tid + i * 256;
            int r = (slot & 511) >> 3, c = (slot & 7) * 8;
            if (slot < 512)
                CP_ASYNC16(ksb + (uint32_t)(buf*BKV*KP + r*KP + c)*2u,
                           kp + (size_t)(kv0 + r) * D_MODEL + c);
            else
                CP_ASYNC16(vsb + (uint32_t)(buf*BKV*VP + r*VP + c)*2u,
                           vp + (size_t)(kv0 + r) * D_MODEL + c);
        }
        asm volatile("cp.async.commit_group;");
    };

    issue(0);
    issue(1);
    if (tid < 128) ms[tid] = maskb[tid];
    __syncthreads();

    // cache Q fragments
    uint32_t afq[4][4];
    {
        const __half* qrow = Qs + wq * QP + 2 * c4;
        #pragma unroll
        for (int kk = 0; kk < 4; kk++) {
            int k16 = kk * 16;
            afq[kk][0] = h2u(*(const __half2*)(qrow + (r4    ) * QP + k16));
            afq[kk][1] = h2u(*(const __half2*)(qrow + (r4 + 8) * QP + k16));
            afq[kk][2] = h2u(*(const __half2*)(qrow + (r4    ) * QP + k16 + 8));
            afq[kk][3] = h2u(*(const __half2*)(qrow + (r4 + 8) * QP + k16 + 8));
        }
    }

    float m0 = -1e30f, m1 = -1e30f, l0 = 0.f, l1 = 0.f;
    float oacc[8][4];
    #pragma unroll
    for (int j = 0; j < 8; j++)
        #pragma unroll
        for (int e = 0; e < 4; e++) oacc[j][e] = 0.f;

    const int T = SEQ / BKV;   // 32
    for (int t = 0; t < T; t++) {
        int buf = t & 1;
        asm volatile("cp.async.wait_group 1;");
        __syncthreads();

        uint32_t kb = ksb + (uint32_t)(buf * BKV * KP) * 2u + kLm;
        uint32_t vb = vsb + (uint32_t)(buf * BKV * VP) * 2u + vLm;
        const int* mb = ms + buf * 64;

        // ---- S = Q @ K^T ----
        float sacc[8][4];
        #pragma unroll
        for (int j = 0; j < 8; j++)
            #pragma unroll
            for (int e = 0; e < 4; e++) sacc[j][e] = 0.f;

        #pragma unroll
        for (int jp = 0; jp < 4; jp++) {
            uint32_t kaddr = kb + (uint32_t)(jp * 16 * KP) * 2u;
            #pragma unroll
            for (int kk = 0; kk < 4; kk++) {
                uint32_t b00, b01, b10, b11;
                LDMX4(b00, b01, b10, b11, kaddr + (uint32_t)(kk * 16) * 2u);
                mma_f16(sacc[2*jp][0], sacc[2*jp][1], sacc[2*jp][2], sacc[2*jp][3],
                        afq[kk][0], afq[kk][1], afq[kk][2], afq[kk][3], b00, b01);
                mma_f16(sacc[2*jp+1][0], sacc[2*jp+1][1], sacc[2*jp+1][2], sacc[2*jp+1][3],
                        afq[kk][0], afq[kk][1], afq[kk][2], afq[kk][3], b10, b11);
            }
        }

        // ---- mask + scale; row max ----
        float rmax0 = -1e30f, rmax1 = -1e30f;
        #pragma unroll
        for (int j = 0; j < 8; j++) {
            int col = j * 8 + 2 * c4;
            int mk0 = mb[col], mk1 = mb[col + 1];
            sacc[j][0] = mk0 ? sacc[j][0] * 0.125f : -1e9f;
            sacc[j][1] = mk1 ? sacc[j][1] * 0.125f : -1e9f;
            sacc[j][2] = mk0 ? sacc[j][2] * 0.125f : -1e9f;
            sacc[j][3] = mk1 ? sacc[j][3] * 0.125f : -1e9f;
            rmax0 = fmaxf(rmax0, fmaxf(sacc[j][0], sacc[j][1]));
            rmax1 = fmaxf(rmax1, fmaxf(sacc[j][2], sacc[j][3]));
        }
        rmax0 = fmaxf(rmax0, __shfl_xor_sync(0xffffffffu, rmax0, 1));
        rmax0 = fmaxf(rmax0, __shfl_xor_sync(0xffffffffu, rmax0, 2));
        rmax1 = fmaxf(rmax1, __shfl_xor_sync(0xffffffffu, rmax1, 1));
        rmax1 = fmaxf(rmax1, __shfl_xor_sync(0xffffffffu, rmax1, 2));

        float mnew0 = fmaxf(m0, rmax0), mnew1 = fmaxf(m1, rmax1);
        float sc0 = __expf(m0 - mnew0), sc1 = __expf(m1 - mnew1);

        // ---- exp; pack P directly into PV A-fragments ----
        float rsum0 = 0.f, rsum1 = 0.f;
        uint32_t ap[4][4];
        #pragma unroll
        for (int j = 0; j < 8; j++) {
            float p0 = __expf(sacc[j][0] - mnew0);
            float p1 = __expf(sacc[j][1] - mnew0);
            float p2 = __expf(sacc[j][2] - mnew1);
            float p3 = __expf(sacc[j][3] - mnew1);
            rsum0 += p0 + p1; rsum1 += p2 + p3;
            int kk = j >> 1, hi = j & 1;
            ap[kk][hi ? 2 : 0] = h2u(__floats2half2_rn(p0, p1));
            ap[kk][hi ? 3 : 1] = h2u(__floats2half2_rn(p2, p3));
        }
        rsum0 += __shfl_xor_sync(0xffffffffu, rsum0, 1);
        rsum0 += __shfl_xor_sync(0xffffffffu, rsum0, 2);
        rsum1 += __shfl_xor_sync(0xffffffffu, rsum1, 1);
        rsum1 += __shfl_xor_sync(0xffffffffu, rsum1, 2);

        l0 = l0 * sc0 + rsum0; m0 = mnew0;
        l1 = l1 * sc1 + rsum1; m1 = mnew1;
        #pragma unroll
        for (int j = 0; j < 8; j++) {
            oacc[j][0] *= sc0; oacc[j][1] *= sc0;
            oacc[j][2] *= sc1; oacc[j][3] *= sc1;
        }

        // ---- O += P @ V  (ldmatrix.trans on raw [kv][d] V) ----
        #pragma unroll
        for (int dp = 0; dp < 4; dp++) {
            uint32_t vaddr = vb + (uint32_t)(dp * 16) * 2u;
            #pragma unroll
            for (int kk = 0; kk < 4; kk++) {
                uint32_t b00, b01, b10, b11;
                LDMX4T(b00, b01, b10, b11, vaddr + (uint32_t)(kk * 16 * VP) * 2u);
                mma_f16(oacc[2*dp][0], oacc[2*dp][1], oacc[2*dp][2], oacc[2*dp][3],
                        ap[kk][0], ap[kk][1], ap[kk][2], ap[kk][3], b00, b01);
                mma_f16(oacc[2*dp+1][0], oacc[2*dp+1][1], oacc[2*dp+1][2], oacc[2*dp+1][3],
                        ap[kk][0], ap[kk][1], ap[kk][2], ap[kk][3], b10, b11);
            }
        }
        __syncthreads();

        if (t + 2 < T) {
            issue(t + 2);
            if (tid < 64) ms[buf * 64 + tid] = maskb[(t + 2) * BKV + tid];
        }
    }

    // ---- finalize ----
    float inv0 = 1.0f / l0, inv1 = 1.0f / l1;
    __half* op = ctx + (size_t)(b * SEQ + qbase + wq) * D_MODEL + h * DK;
    #pragma unroll
    for (int j = 0; j < 8; j++) {
        int col = j * 8 + 2 * c4;
        *(__half2*)&op[(size_t)(r4    ) * D_MODEL + col] =
            __floats2half2_rn(oacc[j][0] * inv0, oacc[j][1] * inv0);
        *(__half2*)&op[(size_t)(r4 + 8) * D_MODEL + col] =
            __floats2half2_rn(oacc[j][2] * inv1, oacc[j][3] * inv1);
    }
}

// ---------------- launch ---------------------------------------------------
extern "C" void kernel_launch(void* const* d_in, const int* in_sizes, int n_in,
                              void* d_out, int out_size)
{
    const float* src  = (const float*)d_in[0];
    const int*   mask = (const int*)  d_in[1];
    const float* wq   = (const float*)d_in[2];
    const float* wk   = (const float*)d_in[3];
    const float* wv   = (const float*)d_in[4];
    const float* wo   = (const float*)d_in[5];
    const float* w1   = (const float*)d_in[6];
    const float* b1   = (const float*)d_in[7];
    const float* w2   = (const float*)d_in[8];
    const float* b2   = (const float*)d_in[9];
    const float* a1   = (const float*)d_in[10];
    const float* be1  = (const float*)d_in[11];
    const float* a2   = (const float*)d_in[12];
    const float* be2  = (const float*)d_in[13];
    float* out = (float*)d_out;

    __half *xln, *qb, *kb, *vb, *ctx, *x2, *ffh;
    __half *pwq, *pwk, *pwv, *pwo, *pw1, *pw2;
    float *out1;
    cudaGetSymbolAddress((void**)&xln,  h_xln);
    cudaGetSymbolAddress((void**)&qb,   h_q);
    cudaGetSymbolAddress((void**)&kb,   h_k);
    cudaGetSymbolAddress((void**)&vb,   h_v);
    cudaGetSymbolAddress((void**)&ctx,  h_ctx);
    cudaGetSymbolAddress((void**)&x2,   h_x2);
    cudaGetSymbolAddress((void**)&ffh,  h_ffh);
    cudaGetSymbolAddress((void**)&out1, g_out1);
    cudaGetSymbolAddress((void**)&pwq,  h_wq);
    cudaGetSymbolAddress((void**)&pwk,  h_wk);
    cudaGetSymbolAddress((void**)&pwv,  h_wv);
    cudaGetSymbolAddress((void**)&pwo,  h_wo);
    cudaGetSymbolAddress((void**)&pw1,  h_w1);
    cudaGetSymbolAddress((void**)&pw2,  h_w2);

    int gsm = GEMM_SMEM;
    cudaFuncSetAttribute(hgemm<0>, cudaFuncAttributeMaxDynamicSharedMemorySize, gsm);
    cudaFuncSetAttribute(hgemm<1>, cudaFuncAttributeMaxDynamicSharedMemorySize, gsm);
    cudaFuncSetAttribute(hgemm<2>, cudaFuncAttributeMaxDynamicSharedMemorySize, gsm);
    cudaFuncSetAttribute(hgemm<3>, cudaFuncAttributeMaxDynamicSharedMemorySize, gsm);
    cudaFuncSetAttribute(attn_mma, cudaFuncAttributeMaxDynamicSharedMemorySize, ATTN_SMEM);

    // 0) weights -> fp16
    round_weights<<<2048, 256>>>(
        (const float4*)wq, (const float4*)wk, (const float4*)wv, (const float4*)wo,
        (const float4*)w1, (const float4*)w2);

    // 1) LN1 -> half
    ln_kernel<<<MROWS, 256>>>(src, xln, a1, be1);

    // 2) QKV projections (half out)
    hgemm<0><<<dim3(D_MODEL/GBN, MROWS/GBM, 3), 256, gsm>>>(
        xln, pwq, pwk, pwv, qb, kb, vb, nullptr, nullptr, MROWS, D_MODEL, D_MODEL);

    // 3) flash attention
    attn_mma<<<dim3(SEQ/BQ, NH, BATCH), 256, ATTN_SMEM>>>(qb, kb, vb, mask, ctx);

    // 4) O projection + residual (float out)
    hgemm<3><<<dim3(D_MODEL/GBN, MROWS/GBM, 1), 256, gsm>>>(
        ctx, pwo, pwo, pwo, out1, out1, out1, nullptr, src, MROWS, D_MODEL, D_MODEL);

    // 5) LN2 -> half
    ln_kernel<<<MROWS, 256>>>(out1, x2, a2, be2);

    // 6) FFN up (half out)
    hgemm<1><<<dim3(DFF/GBN, MROWS/GBM, 1), 256, gsm>>>(
        x2, pw1, pw1, pw1, ffh, ffh, ffh, b1, nullptr, MROWS, DFF, D_MODEL);

    // 7) FFN down + residual (float out)
    hgemm<2><<<dim3(D_MODEL/GBN, MROWS/GBM, 1), 256, gsm>>>(
        ffh, pw2, pw2, pw2, out, out, out, b2, out1, MROWS, D_MODEL, DFF);
}

// round 10
// speedup vs baseline: 6.8708x; 1.0181x over previous
#include <cuda_runtime.h>
#include <cuda_fp16.h>
#include <math.h>
#include <stdint.h>

#define D_MODEL 1024
#define NH      16
#define DK      64
#define DFF     4096
#define BATCH   2
#define SEQ     2048
#define MROWS   (BATCH*SEQ)   // 4096

// ---------------- scratch (device globals; no allocation allowed) ----------
__device__ __half h_xln[MROWS*D_MODEL];
__device__ __half h_q  [MROWS*D_MODEL];
__device__ __half h_k  [MROWS*D_MODEL];
__device__ __half h_v  [MROWS*D_MODEL];
__device__ __half h_ctx[MROWS*D_MODEL];
__device__ __half h_x2 [MROWS*D_MODEL];
__device__ __half h_ffh[MROWS*DFF];
__device__ float  g_out1[MROWS*D_MODEL];
// fp16 weights
__device__ __half h_wq[D_MODEL*D_MODEL];
__device__ __half h_wk[D_MODEL*D_MODEL];
__device__ __half h_wv[D_MODEL*D_MODEL];
__device__ __half h_wo[D_MODEL*D_MODEL];
__device__ __half h_w1[DFF*D_MODEL];
__device__ __half h_w2[D_MODEL*DFF];

// ---------------- helpers --------------------------------------------------
static __device__ __forceinline__ uint32_t smem_u32(const void* p) {
    uint32_t a;
    asm("{ .reg .u64 t; cvta.to.shared.u64 t, %1; cvt.u32.u64 %0, t; }"
        : "=r"(a) : "l"(p));
    return a;
}

static __device__ __forceinline__ uint32_t h2u(__half2 h) {
    union { __half2 h; uint32_t u; } x; x.h = h; return x.u;
}

static __device__ __forceinline__ float ex2(float x) {
    float y;
    asm("ex2.approx.ftz.f32 %0, %1;" : "=f"(y) : "f"(x));
    return y;
}

static __device__ __forceinline__ void mma_f16(
    float& c0, float& c1, float& c2, float& c3,
    uint32_t a0, uint32_t a1, uint32_t a2, uint32_t a3,
    uint32_t b0, uint32_t b1)
{
    asm volatile(
        "mma.sync.aligned.m16n8k16.row.col.f32.f16.f16.f32 "
        "{%0,%1,%2,%3}, {%4,%5,%6,%7}, {%8,%9}, {%0,%1,%2,%3};"
        : "+f"(c0), "+f"(c1), "+f"(c2), "+f"(c3)
        : "r"(a0), "r"(a1), "r"(a2), "r"(a3), "r"(b0), "r"(b1));
}

#define LDMX4(r0,r1,r2,r3,a) \
    asm volatile("ldmatrix.sync.aligned.m8n8.x4.shared.b16 {%0,%1,%2,%3}, [%4];" \
        : "=r"(r0),"=r"(r1),"=r"(r2),"=r"(r3) : "r"(a))
#define LDMX4T(r0,r1,r2,r3,a) \
    asm volatile("ldmatrix.sync.aligned.m8n8.x4.trans.shared.b16 {%0,%1,%2,%3}, [%4];" \
        : "=r"(r0),"=r"(r1),"=r"(r2),"=r"(r3) : "r"(a))

#define CP_ASYNC16(dst, src) \
    asm volatile("cp.async.cg.shared.global [%0], [%1], 16;" :: "r"(dst), "l"(src))

// 0.125 * log2(e): folded into Q so softmax is a bare ex2
#define QSCALE 0.18033688011112042f

// ---------------- weight conversion fp32 -> fp16 ---------------------------
#define WSEG  (D_MODEL*D_MODEL/4)
#define WBIG  (DFF*D_MODEL/4)
#define WTOT  (4*WSEG + 2*WBIG)

__global__ void round_weights(
    const float4* __restrict__ wq, const float4* __restrict__ wk,
    const float4* __restrict__ wv, const float4* __restrict__ wo,
    const float4* __restrict__ w1, const float4* __restrict__ w2)
{
    for (int i = blockIdx.x * blockDim.x + threadIdx.x; i < WTOT;
         i += gridDim.x * blockDim.x) {
        const float4* s; __half* d; int off;
        if      (i < 1*WSEG) { s = wq; d = h_wq; off = i; }
        else if (i < 2*WSEG) { s = wk; d = h_wk; off = i - 1*WSEG; }
        else if (i < 3*WSEG) { s = wv; d = h_wv; off = i - 2*WSEG; }
        else if (i < 4*WSEG) { s = wo; d = h_wo; off = i - 3*WSEG; }
        else if (i < 4*WSEG + WBIG) { s = w1; d = h_w1; off = i - 4*WSEG; }
        else                 { s = w2; d = h_w2; off = i - 4*WSEG - WBIG; }
        float4 v = s[off];
        *(__half2*)(d + 4*off)     = __floats2half2_rn(v.x, v.y);
        *(__half2*)(d + 4*off + 2) = __floats2half2_rn(v.z, v.w);
    }
}

// ======================= Tensor-core FP16 GEMM ============================
// C[M,N] = A[M,K] * B[N,K]^T; CTA 128x256x64; 8 warps 2x4 (warp 64x64);
// 3-stage cp.async; ldmatrix fragments.
#define GBM 128
#define GBN 256
#define GBK 64
#define HP 72
#define A_HALVES (GBM*HP)
#define B_HALVES (GBN*HP)
#define STG_HALVES (A_HALVES + B_HALVES)         // 27648
#define NSTAGE 3
#define GEMM_SMEM (NSTAGE*STG_HALVES*2)          // 165888 B

// EPI: 0 = half store (*QSCALE when z==0), 1 = bias+relu half,
//      2 = bias+residual float, 3 = residual float
template<int EPI>
__global__ void __launch_bounds__(256, 1) hgemm(
    const __half* __restrict__ A,
    const __half* __restrict__ B0, const __half* __restrict__ B1, const __half* __restrict__ B2,
    void* __restrict__ C0, void* __restrict__ C1, void* __restrict__ C2,
    const float* __restrict__ bias, const float* __restrict__ res,
    int M, int N, int K)
{
    extern __shared__ __half smh[];
    uint32_t sbase = smem_u32(smh);

    const __half* Bm = B0; void* Cm = C0;
    if (blockIdx.z == 1) { Bm = B1; Cm = C1; }
    else if (blockIdx.z == 2) { Bm = B2; Cm = C2; }

    int tid  = threadIdx.x;
    int lane = tid & 31, wid = tid >> 5;
    int warp_m = (wid >> 2) * 64;
    int warp_n = (wid & 3) * 64;
    int rowBase = blockIdx.y * GBM;
    int colBase = blockIdx.x * GBN;
    int r4 = lane >> 2, c4 = lane & 3;
    int lg = lane >> 3, li = lane & 7;

    uint32_t aLm = (uint32_t)(((lg & 1) * 8 + li) * HP + (lg >> 1) * 8) * 2u;
    uint32_t bLm = (uint32_t)(((lg >> 1) * 8 + li) * HP + (lg & 1) * 8) * 2u;

    // loaders: A 1024 chunks (4/thread), B 2048 chunks (8/thread)
    const __half* Ag[4]; uint32_t aOff[4];
    #pragma unroll
    for (int j = 0; j < 4; j++) {
        int slot = tid + 256 * j;
        int r = slot >> 3, c = (slot & 7) * 8;
        Ag[j] = A + (size_t)(rowBase + r) * K + c;
        aOff[j] = (uint32_t)(r * HP + c) * 2u;
    }
    const __half* Bg[8]; uint32_t bOff[8];
    #pragma unroll
    for (int j = 0; j < 8; j++) {
        int slot = tid + 256 * j;
        int r = slot >> 3, c = (slot & 7) * 8;
        Bg[j] = Bm + (size_t)(colBase + r) * K + c;
        bOff[j] = (uint32_t)(r * HP + c) * 2u;
    }

    auto issue_tile = [&](int tt, int stage) {
        int k0 = tt * GBK;
        uint32_t sA = sbase + (uint32_t)stage * (STG_HALVES * 2u);
        uint32_t sB = sA + A_HALVES * 2u;
        #pragma unroll
        for (int j = 0; j < 4; j++) CP_ASYNC16(sA + aOff[j], Ag[j] + k0);
        #pragma unroll
        for (int j = 0; j < 8; j++) CP_ASYNC16(sB + bOff[j], Bg[j] + k0);
    };

    float acc[4][8][4];
    #pragma unroll
    for (int i = 0; i < 4; i++)
        #pragma unroll
        for (int j = 0; j < 8; j++)
            #pragma unroll
            for (int e = 0; e < 4; e++) acc[i][j][e] = 0.f;

    int T = K / GBK;
    issue_tile(0, 0);
    asm volatile("cp.async.commit_group;");
    issue_tile(1, 1);
    asm volatile("cp.async.commit_group;");

    int st_c = 0, st_l = 2;
    for (int t = 0; t < T; t++) {
        asm volatile("cp.async.wait_group 1;");
        __syncthreads();

        int nt = t + 2;
        int tt = (nt >= T) ? nt - T : nt;
        issue_tile(tt, st_l);
        asm volatile("cp.async.commit_group;");
        st_l = (st_l == 2) ? 0 : st_l + 1;

        uint32_t sA = sbase + (uint32_t)st_c * (STG_HALVES * 2u);
        uint32_t sB = sA + A_HALVES * 2u;
        st_c = (st_c == 2) ? 0 : st_c + 1;

        uint32_t aBase = sA + aLm + (uint32_t)(warp_m * HP) * 2u;
        uint32_t bBase = sB + bLm + (uint32_t)(warp_n * HP) * 2u;

        #pragma unroll
        for (int kk = 0; kk < 4; kk++) {
            uint32_t kByte = (uint32_t)(kk * 16) * 2u;
            uint32_t af[4][4], bf[8][2];
            #pragma unroll
            for (int i = 0; i < 4; i++)
                LDMX4(af[i][0], af[i][1], af[i][2], af[i][3],
                      aBase + (uint32_t)(i * 16 * HP) * 2u + kByte);
            #pragma unroll
            for (int jp = 0; jp < 4; jp++)
                LDMX4(bf[2*jp][0], bf[2*jp][1], bf[2*jp+1][0], bf[2*jp+1][1],
                      bBase + (uint32_t)(jp * 16 * HP) * 2u + kByte);
            #pragma unroll
            for (int i = 0; i < 4; i++)
                #pragma unroll
                for (int j = 0; j < 8; j++)
                    mma_f16(acc[i][j][0], acc[i][j][1], acc[i][j][2], acc[i][j][3],
                            af[i][0], af[i][1], af[i][2], af[i][3],
                            bf[j][0], bf[j][1]);
        }
    }

    float qs = 1.0f;
    if (EPI == 0 && blockIdx.z == 0) qs = QSCALE;

    #pragma unroll
    for (int i = 0; i < 4; i++) {
        int row = rowBase + warp_m + i * 16 + r4;
        #pragma unroll
        for (int j = 0; j < 8; j++) {
            int col = colBase + warp_n + j * 8 + c4 * 2;
            float2 lo = make_float2(acc[i][j][0], acc[i][j][1]);
            float2 hi = make_float2(acc[i][j][2], acc[i][j][3]);
            if (EPI == 0) {
                __half* Ch = (__half*)Cm;
                *(__half2*)&Ch[(size_t)row * N + col] =
                    __floats2half2_rn(lo.x * qs, lo.y * qs);
                *(__half2*)&Ch[(size_t)(row + 8) * N + col] =
                    __floats2half2_rn(hi.x * qs, hi.y * qs);
            } else if (EPI == 1) {
                float2 bi = *(const float2*)&bias[col];
                __half* Ch = (__half*)Cm;
                *(__half2*)&Ch[(size_t)row * N + col] =
                    __floats2half2_rn(fmaxf(lo.x + bi.x, 0.f), fmaxf(lo.y + bi.y, 0.f));
                *(__half2*)&Ch[(size_t)(row + 8) * N + col] =
                    __floats2half2_rn(fmaxf(hi.x + bi.x, 0.f), fmaxf(hi.y + bi.y, 0.f));
            } else if (EPI == 2) {
                float2 bi = *(const float2*)&bias[col];
                float2 r0 = *(const float2*)&res[(size_t)row * N + col];
                float2 r1 = *(const float2*)&res[(size_t)(row + 8) * N + col];
                float* Cf = (float*)Cm;
                *(float2*)&Cf[(size_t)row * N + col] =
                    make_float2(lo.x + bi.x + r0.x, lo.y + bi.y + r0.y);
                *(float2*)&Cf[(size_t)(row + 8) * N + col] =
                    make_float2(hi.x + bi.x + r1.x, hi.y + bi.y + r1.y);
            } else {
                float2 r0 = *(const float2*)&res[(size_t)row * N + col];
                float2 r1 = *(const float2*)&res[(size_t)(row + 8) * N + col];
                float* Cf = (float*)Cm;
                *(float2*)&Cf[(size_t)row * N + col]       = make_float2(lo.x + r0.x, lo.y + r0.y);
                *(float2*)&Cf[(size_t)(row + 8) * N + col] = make_float2(hi.x + r1.x, hi.y + r1.y);
            }
        }
    }
}

// ---------------- LayerNorm (torch: ddof=1, eps added to std) --------------
__global__ void __launch_bounds__(256) ln_kernel(
    const float* __restrict__ x, __half* __restrict__ y,
    const float* __restrict__ alpha, const float* __restrict__ beta)
{
    int row = blockIdx.x;
    const float4* xr = (const float4*)(x + (size_t)row * D_MODEL);
    float4 v = xr[threadIdx.x];
    float s  = v.x + v.y + v.z + v.w;
    float sq = v.x*v.x + v.y*v.y + v.z*v.z + v.w*v.w;

    __shared__ float red[18];
    #pragma unroll
    for (int o = 16; o; o >>= 1) {
        s  += __shfl_xor_sync(0xffffffffu, s,  o);
        sq += __shfl_xor_sync(0xffffffffu, sq, o);
    }
    int w = threadIdx.x >> 5;
    if ((threadIdx.x & 31) == 0) { red[w] = s; red[8 + w] = sq; }
    __syncthreads();
    if (threadIdx.x == 0) {
        float ts = 0.f, tq = 0.f;
        #pragma unroll
        for (int i = 0; i < 8; i++) { ts += red[i]; tq += red[8 + i]; }
        red[16] = ts; red[17] = tq;
    }
    __syncthreads();
    float ts = red[16], tq = red[17];

    float mean = ts * (1.0f / D_MODEL);
    float var  = (tq - ts * mean) * (1.0f / (D_MODEL - 1));
    var = fmaxf(var, 0.0f);
    float denom = sqrtf(var) + 1e-6f;
    float a  = alpha[0], be = beta[0];
    float r  = a / denom;

    __half* yr = y + (size_t)row * D_MODEL + threadIdx.x * 4;
    *(__half2*)(yr)     = __floats2half2_rn((v.x - mean) * r + be, (v.y - mean) * r + be);
    *(__half2*)(yr + 2) = __floats2half2_rn((v.z - mean) * r + be, (v.w - mean) * r + be);
}

// ============== Flash attention, fp16 mma + ldmatrix ======================
// Q pre-scaled by 0.125*log2e; softmax uses bare ex2. Mask all-ones fast path.
#define BQ  128
#define BKV 64
#define QP  72
#define KP  72
#define VP  72
#define ATTN_SMEM ((BQ*QP + 2*BKV*KP + 2*BKV*VP)*2 + 2*64*4 + 16)

__global__ void __launch_bounds__(256, 2) attn_mma(
    const __half* __restrict__ q, const __half* __restrict__ k,
    const __half* __restrict__ v, const int* __restrict__ mask,
    __half* __restrict__ ctx)
{
    extern __shared__ __half sa[];
    __half* Qs = sa;                      // [128][72]
    __half* Ks = Qs + BQ*QP;              // 2 x [64][72]
    __half* Vs = Ks + 2*BKV*KP;           // 2 x [64][72]
    int*    ms = (int*)(Vs + 2*BKV*VP);   // 2 x [64]
    int*    fl = ms + 128;                // 4 all-ones flags (2 per tile)

    int tid = threadIdx.x, lane = tid & 31, wid = tid >> 5;
    int r4 = lane >> 2, c4 = lane & 3;
    int lg = lane >> 3, li = lane & 7;
    int qt = blockIdx.x, h = blockIdx.y, b = blockIdx.z;
    int qbase = qt * BQ;
    int wq = wid * 16;

    const __half* qp = q + (size_t)(b * SEQ) * D_MODEL + h * DK;
    const __half* kp = k + (size_t)(b * SEQ) * D_MODEL + h * DK;
    const __half* vp = v + (size_t)(b * SEQ) * D_MODEL + h * DK;
    const int* maskb = mask + b * SEQ;

    uint32_t kLm = (uint32_t)(((lg >> 1) * 8 + li) * KP + (lg & 1) * 8) * 2u;
    uint32_t vLm = (uint32_t)(((lg & 1) * 8 + li) * VP + (lg >> 1) * 8) * 2u;

    #pragma unroll
    for (int i = 0; i < 4; i++) {
        int slot = tid + i * 256;
        int r = slot >> 3, c = (slot & 7) * 8;
        *(uint4*)&Qs[r * QP + c] = *(const uint4*)(qp + (size_t)(qbase + r) * D_MODEL + c);
    }

    uint32_t ksb = smem_u32(Ks), vsb = smem_u32(Vs);
    auto issue = [&](int tt) {
        int buf = tt & 1, kv0 = tt * BKV;
        #pragma unroll
        for (int i = 0; i < 4; i++) {
            int slot = tid + i * 256;
            int r = (slot & 511) >> 3, c = (slot & 7) * 8;
            if (slot < 512)
                CP_ASYNC16(ksb + (uint32_t)(buf*BKV*KP + r*KP + c)*2u,
                           kp + (size_t)(kv0 + r) * D_MODEL + c);
            else
                CP_ASYNC16(vsb + (uint32_t)(buf*BKV*VP + r*VP + c)*2u,
                           vp + (size_t)(kv0 + r) * D_MODEL + c);
        }
        asm volatile("cp.async.commit_group;");
    };

    issue(0);
    issue(1);
    if (tid < 128) {
        int m = maskb[tid];
        ms[tid] = m;
        int all = __all_sync(0xffffffffu, m != 0);
        if ((tid & 31) == 0) fl[tid >> 5] = all;
    }
    __syncthreads();

    // cache Q fragments for the whole KV loop
    uint32_t afq[4][4];
    {
        const __half* qrow = Qs + wq * QP + 2 * c4;
        #pragma unroll
        for (int kk = 0; kk < 4; kk++) {
            int k16 = kk * 16;
            afq[kk][0] = h2u(*(const __half2*)(qrow + (r4    ) * QP + k16));
            afq[kk][1] = h2u(*(const __half2*)(qrow + (r4 + 8) * QP + k16));
            afq[kk][2] = h2u(*(const __half2*)(qrow + (r4    ) * QP + k16 + 8));
            afq[kk][3] = h2u(*(const __half2*)(qrow + (r4 + 8) * QP + k16 + 8));
        }
    }

    float m0 = -1e30f, m1 = -1e30f, l0 = 0.f, l1 = 0.f;
    float oacc[8][4];
    #pragma unroll
    for (int j = 0; j < 8; j++)
        #pragma unroll
        for (int e = 0; e < 4; e++) oacc[j][e] = 0.f;

    const int T = SEQ / BKV;   // 32
    for (int t = 0; t < T; t++) {
        int buf = t & 1;
        asm volatile("cp.async.wait_group 1;");
        __syncthreads();

        uint32_t kb = ksb + (uint32_t)(buf * BKV * KP) * 2u + kLm;
        uint32_t vb = vsb + (uint32_t)(buf * BKV * VP) * 2u + vLm;
        const int* mb = ms + buf * 64;
        bool allone = fl[buf * 2] && fl[buf * 2 + 1];

        // ---- S = Q @ K^T (pre-scaled: S already in log2 units) ----
        float sacc[8][4];
        #pragma unroll
        for (int j = 0; j < 8; j++)
            #pragma unroll
            for (int e = 0; e < 4; e++) sacc[j][e] = 0.f;

        #pragma unroll
        for (int jp = 0; jp < 4; jp++) {
            uint32_t kaddr = kb + (uint32_t)(jp * 16 * KP) * 2u;
            #pragma unroll
            for (int kk = 0; kk < 4; kk++) {
                uint32_t b00, b01, b10, b11;
                LDMX4(b00, b01, b10, b11, kaddr + (uint32_t)(kk * 16) * 2u);
                mma_f16(sacc[2*jp][0], sacc[2*jp][1], sacc[2*jp][2], sacc[2*jp][3],
                        afq[kk][0], afq[kk][1], afq[kk][2], afq[kk][3], b00, b01);
                mma_f16(sacc[2*jp+1][0], sacc[2*jp+1][1], sacc[2*jp+1][2], sacc[2*jp+1][3],
                        afq[kk][0], afq[kk][1], afq[kk][2], afq[kk][3], b10, b11);
            }
        }

        // ---- mask (slow path only) ----
        if (!allone) {
            #pragma unroll
            for (int j = 0; j < 8; j++) {
                int col = j * 8 + 2 * c4;
                int mk0 = mb[col], mk1 = mb[col + 1];
                if (!mk0) { sacc[j][0] = -1e9f; sacc[j][2] = -1e9f; }
                if (!mk1) { sacc[j][1] = -1e9f; sacc[j][3] = -1e9f; }
            }
        }

        // ---- row max ----
        float rmax0 = -1e30f, rmax1 = -1e30f;
        #pragma unroll
        for (int j = 0; j < 8; j++) {
            rmax0 = fmaxf(rmax0, fmaxf(sacc[j][0], sacc[j][1]));
            rmax1 = fmaxf(rmax1, fmaxf(sacc[j][2], sacc[j][3]));
        }
        rmax0 = fmaxf(rmax0, __shfl_xor_sync(0xffffffffu, rmax0, 1));
        rmax0 = fmaxf(rmax0, __shfl_xor_sync(0xffffffffu, rmax0, 2));
        rmax1 = fmaxf(rmax1, __shfl_xor_sync(0xffffffffu, rmax1, 1));
        rmax1 = fmaxf(rmax1, __shfl_xor_sync(0xffffffffu, rmax1, 2));

        float mnew0 = fmaxf(m0, rmax0), mnew1 = fmaxf(m1, rmax1);
        float sc0 = ex2(m0 - mnew0), sc1 = ex2(m1 - mnew1);

        // ---- 2^x; pack P directly into PV A-fragments ----
        float rsum0 = 0.f, rsum1 = 0.f;
        uint32_t ap[4][4];
        #pragma unroll
        for (int j = 0; j < 8; j++) {
            float p0 = ex2(sacc[j][0] - mnew0);
            float p1 = ex2(sacc[j][1] - mnew0);
            float p2 = ex2(sacc[j][2] - mnew1);
            float p3 = ex2(sacc[j][3] - mnew1);
            rsum0 += p0 + p1; rsum1 += p2 + p3;
            int kk = j >> 1, hi = j & 1;
            ap[kk][hi ? 2 : 0] = h2u(__floats2half2_rn(p0, p1));
            ap[kk][hi ? 3 : 1] = h2u(__floats2half2_rn(p2, p3));
        }
        rsum0 += __shfl_xor_sync(0xffffffffu, rsum0, 1);
        rsum0 += __shfl_xor_sync(0xffffffffu, rsum0, 2);
        rsum1 += __shfl_xor_sync(0xffffffffu, rsum1, 1);
        rsum1 += __shfl_xor_sync(0xffffffffu, rsum1, 2);

        l0 = l0 * sc0 + rsum0; m0 = mnew0;
        l1 = l1 * sc1 + rsum1; m1 = mnew1;
        #pragma unroll
        for (int j = 0; j < 8; j++) {
            oacc[j][0] *= sc0; oacc[j][1] *= sc0;
            oacc[j][2] *= sc1; oacc[j][3] *= sc1;
        }

        // ---- O += P @ V ----
        #pragma unroll
        for (int dp = 0; dp < 4; dp++) {
            uint32_t vaddr = vb + (uint32_t)(dp * 16) * 2u;
            #pragma unroll
            for (int kk = 0; kk < 4; kk++) {
                uint32_t b00, b01, b10, b11;
                LDMX4T(b00, b01, b10, b11, vaddr + (uint32_t)(kk * 16 * VP) * 2u);
                mma_f16(oacc[2*dp][0], oacc[2*dp][1], oacc[2*dp][2], oacc[2*dp][3],
                        ap[kk][0], ap[kk][1], ap[kk][2], ap[kk][3], b00, b01);
                mma_f16(oacc[2*dp+1][0], oacc[2*dp+1][1], oacc[2*dp+1][2], oacc[2*dp+1][3],
                        ap[kk][0], ap[kk][1], ap[kk][2], ap[kk][3], b10, b11);
            }
        }
        __syncthreads();

        if (t + 2 < T) {
            issue(t + 2);
            if (tid < 64) {
                int m = maskb[(t + 2) * BKV + tid];
                ms[buf * 64 + tid] = m;
                int all = __all_sync(0xffffffffu, m != 0);
                if ((tid & 31) == 0) fl[buf * 2 + (tid >> 5)] = all;
            }
        }
    }

    // ---- finalize ----
    float inv0 = 1.0f / l0, inv1 = 1.0f / l1;
    __half* op = ctx + (size_t)(b * SEQ + qbase + wq) * D_MODEL + h * DK;
    #pragma unroll
    for (int j = 0; j < 8; j++) {
        int col = j * 8 + 2 * c4;
        *(__half2*)&op[(size_t)(r4    ) * D_MODEL + col] =
            __floats2half2_rn(oacc[j][0] * inv0, oacc[j][1] * inv0);
        *(__half2*)&op[(size_t)(r4 + 8) * D_MODEL + col] =
            __floats2half2_rn(oacc[j][2] * inv1, oacc[j][3] * inv1);
    }
}

// ---------------- launch ---------------------------------------------------
extern "C" void kernel_launch(void* const* d_in, const int* in_sizes, int n_in,
                              void* d_out, int out_size)
{
    const float* src  = (const float*)d_in[0];
    const int*   mask = (const int*)  d_in[1];
    const float* wq   = (const float*)d_in[2];
    const float* wk   = (const float*)d_in[3];
    const float* wv   = (const float*)d_in[4];
    const float* wo   = (const float*)d_in[5];
    const float* w1   = (const float*)d_in[6];
    const float* b1   = (const float*)d_in[7];
    const float* w2   = (const float*)d_in[8];
    const float* b2   = (const float*)d_in[9];
    const float* a1   = (const float*)d_in[10];
    const float* be1  = (const float*)d_in[11];
    const float* a2   = (const float*)d_in[12];
    const float* be2  = (const float*)d_in[13];
    float* out = (float*)d_out;

    __half *xln, *qb, *kb, *vb, *ctx, *x2, *ffh;
    __half *pwq, *pwk, *pwv, *pwo, *pw1, *pw2;
    float *out1;
    cudaGetSymbolAddress((void**)&xln,  h_xln);
    cudaGetSymbolAddress((void**)&qb,   h_q);
    cudaGetSymbolAddress((void**)&kb,   h_k);
    cudaGetSymbolAddress((void**)&vb,   h_v);
    cudaGetSymbolAddress((void**)&ctx,  h_ctx);
    cudaGetSymbolAddress((void**)&x2,   h_x2);
    cudaGetSymbolAddress((void**)&ffh,  h_ffh);
    cudaGetSymbolAddress((void**)&out1, g_out1);
    cudaGetSymbolAddress((void**)&pwq,  h_wq);
    cudaGetSymbolAddress((void**)&pwk,  h_wk);
    cudaGetSymbolAddress((void**)&pwv,  h_wv);
    cudaGetSymbolAddress((void**)&pwo,  h_wo);
    cudaGetSymbolAddress((void**)&pw1,  h_w1);
    cudaGetSymbolAddress((void**)&pw2,  h_w2);

    int gsm = GEMM_SMEM;
    cudaFuncSetAttribute(hgemm<0>, cudaFuncAttributeMaxDynamicSharedMemorySize, gsm);
    cudaFuncSetAttribute(hgemm<1>, cudaFuncAttributeMaxDynamicSharedMemorySize, gsm);
    cudaFuncSetAttribute(hgemm<2>, cudaFuncAttributeMaxDynamicSharedMemorySize, gsm);
    cudaFuncSetAttribute(hgemm<3>, cudaFuncAttributeMaxDynamicSharedMemorySize, gsm);
    cudaFuncSetAttribute(attn_mma, cudaFuncAttributeMaxDynamicSharedMemorySize, ATTN_SMEM);

    // 0) weights -> fp16
    round_weights<<<2048, 256>>>(
        (const float4*)wq, (const float4*)wk, (const float4*)wv, (const float4*)wo,
        (const float4*)w1, (const float4*)w2);

    // 1) LN1 -> half
    ln_kernel<<<MROWS, 256>>>(src, xln, a1, be1);

    // 2) QKV projections (half out; Q scaled by 0.125*log2e)
    hgemm<0><<<dim3(D_MODEL/GBN, MROWS/GBM, 3), 256, gsm>>>(
        xln, pwq, pwk, pwv, qb, kb, vb, nullptr, nullptr, MROWS, D_MODEL, D_MODEL);

    // 3) flash attention
    attn_mma<<<dim3(SEQ/BQ, NH, BATCH), 256, ATTN_SMEM>>>(qb, kb, vb, mask, ctx);

    // 4) O projection + residual (float out)
    hgemm<3><<<dim3(D_MODEL/GBN, MROWS/GBM, 1), 256, gsm>>>(
        ctx, pwo, pwo, pwo, out1, out1, out1, nullptr, src, MROWS, D_MODEL, D_MODEL);

    // 5) LN2 -> half
    ln_kernel<<<MROWS, 256>>>(out1, x2, a2, be2);

    // 6) FFN up (half out)
    hgemm<1><<<dim3(DFF/GBN, MROWS/GBM, 1), 256, gsm>>>(
        x2, pw1, pw1, pw1, ffh, ffh, ffh, b1, nullptr, MROWS, DFF, D_MODEL);

    // 7) FFN down + residual (float out)
    hgemm<2><<<dim3(D_MODEL/GBN, MROWS/GBM, 1), 256, gsm>>>(
        ffh, pw2, pw2, pw2, out, out, out, b2, out1, MROWS, D_MODEL, DFF);
}

// round 11
// speedup vs baseline: 7.0405x; 1.0247x over previous
#include <cuda_runtime.h>
#include <cuda_fp16.h>
#include <math.h>
#include <stdint.h>

#define D_MODEL 1024
#define NH      16
#define DK      64
#define DFF     4096
#define BATCH   2
#define SEQ     2048
#define MROWS   (BATCH*SEQ)   // 4096

// ---------------- scratch (device globals; no allocation allowed) ----------
__device__ __half h_xln[MROWS*D_MODEL];
__device__ __half h_q  [MROWS*D_MODEL];
__device__ __half h_k  [MROWS*D_MODEL];
__device__ __half h_v  [MROWS*D_MODEL];
__device__ __half h_ctx[MROWS*D_MODEL];
__device__ __half h_x2 [MROWS*D_MODEL];
__device__ __half h_ffh[MROWS*DFF];
__device__ float  g_out1[MROWS*D_MODEL];
// fp16 weights
__device__ __half h_wq[D_MODEL*D_MODEL];
__device__ __half h_wk[D_MODEL*D_MODEL];
__device__ __half h_wv[D_MODEL*D_MODEL];
__device__ __half h_wo[D_MODEL*D_MODEL];
__device__ __half h_w1[DFF*D_MODEL];
__device__ __half h_w2[D_MODEL*DFF];

// ---------------- helpers --------------------------------------------------
static __device__ __forceinline__ uint32_t smem_u32(const void* p) {
    uint32_t a;
    asm("{ .reg .u64 t; cvta.to.shared.u64 t, %1; cvt.u32.u64 %0, t; }"
        : "=r"(a) : "l"(p));
    return a;
}

static __device__ __forceinline__ uint32_t h2u(__half2 h) {
    union { __half2 h; uint32_t u; } x; x.h = h; return x.u;
}

static __device__ __forceinline__ float ex2(float x) {
    float y;
    asm("ex2.approx.ftz.f32 %0, %1;" : "=f"(y) : "f"(x));
    return y;
}

static __device__ __forceinline__ void mma_f16(
    float& c0, float& c1, float& c2, float& c3,
    uint32_t a0, uint32_t a1, uint32_t a2, uint32_t a3,
    uint32_t b0, uint32_t b1)
{
    asm volatile(
        "mma.sync.aligned.m16n8k16.row.col.f32.f16.f16.f32 "
        "{%0,%1,%2,%3}, {%4,%5,%6,%7}, {%8,%9}, {%0,%1,%2,%3};"
        : "+f"(c0), "+f"(c1), "+f"(c2), "+f"(c3)
        : "r"(a0), "r"(a1), "r"(a2), "r"(a3), "r"(b0), "r"(b1));
}

#define LDMX4(r0,r1,r2,r3,a) \
    asm volatile("ldmatrix.sync.aligned.m8n8.x4.shared.b16 {%0,%1,%2,%3}, [%4];" \
        : "=r"(r0),"=r"(r1),"=r"(r2),"=r"(r3) : "r"(a))
#define LDMX4T(r0,r1,r2,r3,a) \
    asm volatile("ldmatrix.sync.aligned.m8n8.x4.trans.shared.b16 {%0,%1,%2,%3}, [%4];" \
        : "=r"(r0),"=r"(r1),"=r"(r2),"=r"(r3) : "r"(a))

#define CP_ASYNC16(dst, src) \
    asm volatile("cp.async.cg.shared.global [%0], [%1], 16;" :: "r"(dst), "l"(src))

// 0.125 * log2(e): folded into Q so softmax is a bare ex2
#define QSCALE 0.18033688011112042f

// ---------------- weight conversion fp32 -> fp16 ---------------------------
#define WSEG  (D_MODEL*D_MODEL/4)
#define WBIG  (DFF*D_MODEL/4)
#define WTOT  (4*WSEG + 2*WBIG)

__global__ void round_weights(
    const float4* __restrict__ wq, const float4* __restrict__ wk,
    const float4* __restrict__ wv, const float4* __restrict__ wo,
    const float4* __restrict__ w1, const float4* __restrict__ w2)
{
    for (int i = blockIdx.x * blockDim.x + threadIdx.x; i < WTOT;
         i += gridDim.x * blockDim.x) {
        const float4* s; __half* d; int off;
        if      (i < 1*WSEG) { s = wq; d = h_wq; off = i; }
        else if (i < 2*WSEG) { s = wk; d = h_wk; off = i - 1*WSEG; }
        else if (i < 3*WSEG) { s = wv; d = h_wv; off = i - 2*WSEG; }
        else if (i < 4*WSEG) { s = wo; d = h_wo; off = i - 3*WSEG; }
        else if (i < 4*WSEG + WBIG) { s = w1; d = h_w1; off = i - 4*WSEG; }
        else                 { s = w2; d = h_w2; off = i - 4*WSEG - WBIG; }
        float4 v = s[off];
        *(__half2*)(d + 4*off)     = __floats2half2_rn(v.x, v.y);
        *(__half2*)(d + 4*off + 2) = __floats2half2_rn(v.z, v.w);
    }
}

// ======================= Tensor-core FP16 GEMM ============================
// C[M,N] = A[M,K] * B[N,K]^T; CTA 128x256x32; 8 warps 2x4 (warp 64x64);
// 3-stage cp.async; ldmatrix fragments. (R9 measured-best config.)
#define GBM 128
#define GBN 256
#define GBK 32
#define HP 40
#define A_HALVES (GBM*HP)
#define B_HALVES (GBN*HP)
#define STG_HALVES (A_HALVES + B_HALVES)
#define NSTAGE 3
#define GEMM_SMEM (NSTAGE*STG_HALVES*2)

// EPI: 0 = half store (*QSCALE when z==0), 1 = bias+relu half,
//      2 = bias+residual float, 3 = residual float
template<int EPI>
__global__ void __launch_bounds__(256, 1) hgemm(
    const __half* __restrict__ A,
    const __half* __restrict__ B0, const __half* __restrict__ B1, const __half* __restrict__ B2,
    void* __restrict__ C0, void* __restrict__ C1, void* __restrict__ C2,
    const float* __restrict__ bias, const float* __restrict__ res,
    int M, int N, int K)
{
    extern __shared__ __half smh[];
    uint32_t sbase = smem_u32(smh);

    const __half* Bm = B0; void* Cm = C0;
    if (blockIdx.z == 1) { Bm = B1; Cm = C1; }
    else if (blockIdx.z == 2) { Bm = B2; Cm = C2; }

    int tid  = threadIdx.x;
    int lane = tid & 31, wid = tid >> 5;
    int warp_m = (wid >> 2) * 64;
    int warp_n = (wid & 3) * 64;
    int rowBase = blockIdx.y * GBM;
    int colBase = blockIdx.x * GBN;
    int r4 = lane >> 2, c4 = lane & 3;
    int lg = lane >> 3, li = lane & 7;

    uint32_t aLm = (uint32_t)(((lg & 1) * 8 + li) * HP + (lg >> 1) * 8) * 2u;
    uint32_t bLm = (uint32_t)(((lg >> 1) * 8 + li) * HP + (lg & 1) * 8) * 2u;

    const __half* Ag[2]; uint32_t aOff[2];
    #pragma unroll
    for (int j = 0; j < 2; j++) {
        int slot = tid + 256 * j;
        int r = slot >> 2, c = (slot & 3) * 8;
        Ag[j] = A + (size_t)(rowBase + r) * K + c;
        aOff[j] = (uint32_t)(r * HP + c) * 2u;
    }
    const __half* Bg[4]; uint32_t bOff[4];
    #pragma unroll
    for (int j = 0; j < 4; j++) {
        int slot = tid + 256 * j;
        int r = slot >> 2, c = (slot & 3) * 8;
        Bg[j] = Bm + (size_t)(colBase + r) * K + c;
        bOff[j] = (uint32_t)(r * HP + c) * 2u;
    }

    auto issue_tile = [&](int tt, int stage) {
        int k0 = tt * GBK;
        uint32_t sA = sbase + (uint32_t)stage * (STG_HALVES * 2u);
        uint32_t sB = sA + A_HALVES * 2u;
        #pragma unroll
        for (int j = 0; j < 2; j++) CP_ASYNC16(sA + aOff[j], Ag[j] + k0);
        #pragma unroll
        for (int j = 0; j < 4; j++) CP_ASYNC16(sB + bOff[j], Bg[j] + k0);
    };

    float acc[4][8][4];
    #pragma unroll
    for (int i = 0; i < 4; i++)
        #pragma unroll
        for (int j = 0; j < 8; j++)
            #pragma unroll
            for (int e = 0; e < 4; e++) acc[i][j][e] = 0.f;

    int T = K / GBK;
    issue_tile(0, 0);
    asm volatile("cp.async.commit_group;");
    issue_tile(1, 1);
    asm volatile("cp.async.commit_group;");

    int st_c = 0, st_l = 2;
    for (int t = 0; t < T; t++) {
        asm volatile("cp.async.wait_group 1;");
        __syncthreads();

        int nt = t + 2;
        int tt = (nt >= T) ? nt - T : nt;
        issue_tile(tt, st_l);
        asm volatile("cp.async.commit_group;");
        st_l = (st_l == 2) ? 0 : st_l + 1;

        uint32_t sA = sbase + (uint32_t)st_c * (STG_HALVES * 2u);
        uint32_t sB = sA + A_HALVES * 2u;
        st_c = (st_c == 2) ? 0 : st_c + 1;

        uint32_t aBase = sA + aLm + (uint32_t)(warp_m * HP) * 2u;
        uint32_t bBase = sB + bLm + (uint32_t)(warp_n * HP) * 2u;

        #pragma unroll
        for (int kk = 0; kk < 2; kk++) {
            uint32_t kByte = (uint32_t)(kk * 16) * 2u;
            uint32_t af[4][4], bf[8][2];
            #pragma unroll
            for (int i = 0; i < 4; i++)
                LDMX4(af[i][0], af[i][1], af[i][2], af[i][3],
                      aBase + (uint32_t)(i * 16 * HP) * 2u + kByte);
            #pragma unroll
            for (int jp = 0; jp < 4; jp++)
                LDMX4(bf[2*jp][0], bf[2*jp][1], bf[2*jp+1][0], bf[2*jp+1][1],
                      bBase + (uint32_t)(jp * 16 * HP) * 2u + kByte);
            #pragma unroll
            for (int i = 0; i < 4; i++)
                #pragma unroll
                for (int j = 0; j < 8; j++)
                    mma_f16(acc[i][j][0], acc[i][j][1], acc[i][j][2], acc[i][j][3],
                            af[i][0], af[i][1], af[i][2], af[i][3],
                            bf[j][0], bf[j][1]);
        }
    }

    float qs = 1.0f;
    if (EPI == 0 && blockIdx.z == 0) qs = QSCALE;

    #pragma unroll
    for (int i = 0; i < 4; i++) {
        int row = rowBase + warp_m + i * 16 + r4;
        #pragma unroll
        for (int j = 0; j < 8; j++) {
            int col = colBase + warp_n + j * 8 + c4 * 2;
            float2 lo = make_float2(acc[i][j][0], acc[i][j][1]);
            float2 hi = make_float2(acc[i][j][2], acc[i][j][3]);
            if (EPI == 0) {
                __half* Ch = (__half*)Cm;
                *(__half2*)&Ch[(size_t)row * N + col] =
                    __floats2half2_rn(lo.x * qs, lo.y * qs);
                *(__half2*)&Ch[(size_t)(row + 8) * N + col] =
                    __floats2half2_rn(hi.x * qs, hi.y * qs);
            } else if (EPI == 1) {
                float2 bi = *(const float2*)&bias[col];
                __half* Ch = (__half*)Cm;
                *(__half2*)&Ch[(size_t)row * N + col] =
                    __floats2half2_rn(fmaxf(lo.x + bi.x, 0.f), fmaxf(lo.y + bi.y, 0.f));
                *(__half2*)&Ch[(size_t)(row + 8) * N + col] =
                    __floats2half2_rn(fmaxf(hi.x + bi.x, 0.f), fmaxf(hi.y + bi.y, 0.f));
            } else if (EPI == 2) {
                float2 bi = *(const float2*)&bias[col];
                float2 r0 = *(const float2*)&res[(size_t)row * N + col];
                float2 r1 = *(const float2*)&res[(size_t)(row + 8) * N + col];
                float* Cf = (float*)Cm;
                *(float2*)&Cf[(size_t)row * N + col] =
                    make_float2(lo.x + bi.x + r0.x, lo.y + bi.y + r0.y);
                *(float2*)&Cf[(size_t)(row + 8) * N + col] =
                    make_float2(hi.x + bi.x + r1.x, hi.y + bi.y + r1.y);
            } else {
                float2 r0 = *(const float2*)&res[(size_t)row * N + col];
                float2 r1 = *(const float2*)&res[(size_t)(row + 8) * N + col];
                float* Cf = (float*)Cm;
                *(float2*)&Cf[(size_t)row * N + col]       = make_float2(lo.x + r0.x, lo.y + r0.y);
                *(float2*)&Cf[(size_t)(row + 8) * N + col] = make_float2(hi.x + r1.x, hi.y + r1.y);
            }
        }
    }
}

// ---------------- LayerNorm (torch: ddof=1, eps added to std) --------------
__global__ void __launch_bounds__(256) ln_kernel(
    const float* __restrict__ x, __half* __restrict__ y,
    const float* __restrict__ alpha, const float* __restrict__ beta)
{
    int row = blockIdx.x;
    const float4* xr = (const float4*)(x + (size_t)row * D_MODEL);
    float4 v = xr[threadIdx.x];
    float s  = v.x + v.y + v.z + v.w;
    float sq = v.x*v.x + v.y*v.y + v.z*v.z + v.w*v.w;

    __shared__ float red[18];
    #pragma unroll
    for (int o = 16; o; o >>= 1) {
        s  += __shfl_xor_sync(0xffffffffu, s,  o);
        sq += __shfl_xor_sync(0xffffffffu, sq, o);
    }
    int w = threadIdx.x >> 5;
    if ((threadIdx.x & 31) == 0) { red[w] = s; red[8 + w] = sq; }
    __syncthreads();
    if (threadIdx.x == 0) {
        float ts = 0.f, tq = 0.f;
        #pragma unroll
        for (int i = 0; i < 8; i++) { ts += red[i]; tq += red[8 + i]; }
        red[16] = ts; red[17] = tq;
    }
    __syncthreads();
    float ts = red[16], tq = red[17];

    float mean = ts * (1.0f / D_MODEL);
    float var  = (tq - ts * mean) * (1.0f / (D_MODEL - 1));
    var = fmaxf(var, 0.0f);
    float denom = sqrtf(var) + 1e-6f;
    float a  = alpha[0], be = beta[0];
    float r  = a / denom;

    __half* yr = y + (size_t)row * D_MODEL + threadIdx.x * 4;
    *(__half2*)(yr)     = __floats2half2_rn((v.x - mean) * r + be, (v.y - mean) * r + be);
    *(__half2*)(yr + 2) = __floats2half2_rn((v.z - mean) * r + be, (v.w - mean) * r + be);
}

// ============== Flash attention, fp16 mma + ldmatrix ======================
// 4-stage KV ring: ONE __syncthreads per tile (issue(t+3) writes the stage
// consumed two iters ago; the top barrier protects it). Q pre-scaled by
// 0.125*log2e; bare ex2 softmax; all-ones mask fast path.
#define BQ  128
#define BKV 64
#define NKV 4
#define QP  72
#define KP  72
#define VP  72
#define ATTN_SMEM ((BQ*QP + NKV*BKV*KP + NKV*BKV*VP)*2 + NKV*64*4 + 8*4)

__global__ void __launch_bounds__(256, 2) attn_mma(
    const __half* __restrict__ q, const __half* __restrict__ k,
    const __half* __restrict__ v, const int* __restrict__ mask,
    __half* __restrict__ ctx)
{
    extern __shared__ __half sa[];
    __half* Qs = sa;                       // [128][72]
    __half* Ks = Qs + BQ*QP;               // NKV x [64][72]
    __half* Vs = Ks + NKV*BKV*KP;          // NKV x [64][72]
    int*    ms = (int*)(Vs + NKV*BKV*VP);  // NKV x [64]
    int*    fl = ms + NKV*64;              // 2 flags per stage

    int tid = threadIdx.x, lane = tid & 31, wid = tid >> 5;
    int r4 = lane >> 2, c4 = lane & 3;
    int lg = lane >> 3, li = lane & 7;
    int qt = blockIdx.x, h = blockIdx.y, b = blockIdx.z;
    int qbase = qt * BQ;
    int wq = wid * 16;

    const __half* qp = q + (size_t)(b * SEQ) * D_MODEL + h * DK;
    const __half* kp = k + (size_t)(b * SEQ) * D_MODEL + h * DK;
    const __half* vp = v + (size_t)(b * SEQ) * D_MODEL + h * DK;
    const int* maskb = mask + b * SEQ;

    uint32_t kLm = (uint32_t)(((lg >> 1) * 8 + li) * KP + (lg & 1) * 8) * 2u;
    uint32_t vLm = (uint32_t)(((lg & 1) * 8 + li) * VP + (lg >> 1) * 8) * 2u;

    #pragma unroll
    for (int i = 0; i < 4; i++) {
        int slot = tid + i * 256;
        int r = slot >> 3, c = (slot & 7) * 8;
        *(uint4*)&Qs[r * QP + c] = *(const uint4*)(qp + (size_t)(qbase + r) * D_MODEL + c);
    }

    uint32_t ksb = smem_u32(Ks), vsb = smem_u32(Vs);
    auto issue = [&](int tt) {
        int buf = tt & (NKV - 1), kv0 = tt * BKV;
        #pragma unroll
        for (int i = 0; i < 4; i++) {
            int slot = tid + i * 256;
            int r = (slot & 511) >> 3, c = (slot & 7) * 8;
            if (slot < 512)
                CP_ASYNC16(ksb + (uint32_t)(buf*BKV*KP + r*KP + c)*2u,
                           kp + (size_t)(kv0 + r) * D_MODEL + c);
            else
                CP_ASYNC16(vsb + (uint32_t)(buf*BKV*VP + r*VP + c)*2u,
                           vp + (size_t)(kv0 + r) * D_MODEL + c);
        }
        asm volatile("cp.async.commit_group;");
    };

    // prologue: 3 tiles in flight
    issue(0);
    issue(1);
    issue(2);
    if (tid < 192) {
        int m = maskb[tid];                // tiles 0,1,2 masks
        ms[tid] = m;
        int all = __all_sync(0xffffffffu, m != 0);
        if ((tid & 31) == 0) fl[tid >> 5] = all;   // fl[0..5] = stage 0,0,1,1,2,2
    }
    __syncthreads();

    // cache Q fragments for the whole KV loop
    uint32_t afq[4][4];
    {
        const __half* qrow = Qs + wq * QP + 2 * c4;
        #pragma unroll
        for (int kk = 0; kk < 4; kk++) {
            int k16 = kk * 16;
            afq[kk][0] = h2u(*(const __half2*)(qrow + (r4    ) * QP + k16));
            afq[kk][1] = h2u(*(const __half2*)(qrow + (r4 + 8) * QP + k16));
            afq[kk][2] = h2u(*(const __half2*)(qrow + (r4    ) * QP + k16 + 8));
            afq[kk][3] = h2u(*(const __half2*)(qrow + (r4 + 8) * QP + k16 + 8));
        }
    }

    float m0 = -1e30f, m1 = -1e30f, l0 = 0.f, l1 = 0.f;
    float oacc[8][4];
    #pragma unroll
    for (int j = 0; j < 8; j++)
        #pragma unroll
        for (int e = 0; e < 4; e++) oacc[j][e] = 0.f;

    const int T = SEQ / BKV;   // 32
    for (int t = 0; t < T; t++) {
        int buf = t & (NKV - 1);
        asm volatile("cp.async.wait_group 2;");
        __syncthreads();   // single barrier: visibility + ring-reuse protection

        // prefetch tile t+3 into stage (t+3)&3 (consumed two iters ago)
        if (t + 3 < T) {
            issue(t + 3);
            if (tid < 64) {
                int st = (t + 3) & (NKV - 1);
                int m = maskb[(t + 3) * BKV + tid];
                ms[st * 64 + tid] = m;
                int all = __all_sync(0xffffffffu, m != 0);
                if ((tid & 31) == 0) fl[st * 2 + (tid >> 5)] = all;
            }
        }

        uint32_t kb = ksb + (uint32_t)(buf * BKV * KP) * 2u + kLm;
        uint32_t vb = vsb + (uint32_t)(buf * BKV * VP) * 2u + vLm;
        const int* mb = ms + buf * 64;
        bool allone = fl[buf * 2] && fl[buf * 2 + 1];

        // ---- S = Q @ K^T (pre-scaled: S already in log2 units) ----
        float sacc[8][4];
        #pragma unroll
        for (int j = 0; j < 8; j++)
            #pragma unroll
            for (int e = 0; e < 4; e++) sacc[j][e] = 0.f;

        #pragma unroll
        for (int jp = 0; jp < 4; jp++) {
            uint32_t kaddr = kb + (uint32_t)(jp * 16 * KP) * 2u;
            #pragma unroll
            for (int kk = 0; kk < 4; kk++) {
                uint32_t b00, b01, b10, b11;
                LDMX4(b00, b01, b10, b11, kaddr + (uint32_t)(kk * 16) * 2u);
                mma_f16(sacc[2*jp][0], sacc[2*jp][1], sacc[2*jp][2], sacc[2*jp][3],
                        afq[kk][0], afq[kk][1], afq[kk][2], afq[kk][3], b00, b01);
                mma_f16(sacc[2*jp+1][0], sacc[2*jp+1][1], sacc[2*jp+1][2], sacc[2*jp+1][3],
                        afq[kk][0], afq[kk][1], afq[kk][2], afq[kk][3], b10, b11);
            }
        }

        // ---- mask (slow path only) ----
        if (!allone) {
            #pragma unroll
            for (int j = 0; j < 8; j++) {
                int col = j * 8 + 2 * c4;
                int mk0 = mb[col], mk1 = mb[col + 1];
                if (!mk0) { sacc[j][0] = -1e9f; sacc[j][2] = -1e9f; }
                if (!mk1) { sacc[j][1] = -1e9f; sacc[j][3] = -1e9f; }
            }
        }

        // ---- row max ----
        float rmax0 = -1e30f, rmax1 = -1e30f;
        #pragma unroll
        for (int j = 0; j < 8; j++) {
            rmax0 = fmaxf(rmax0, fmaxf(sacc[j][0], sacc[j][1]));
            rmax1 = fmaxf(rmax1, fmaxf(sacc[j][2], sacc[j][3]));
        }
        rmax0 = fmaxf(rmax0, __shfl_xor_sync(0xffffffffu, rmax0, 1));
        rmax0 = fmaxf(rmax0, __shfl_xor_sync(0xffffffffu, rmax0, 2));
        rmax1 = fmaxf(rmax1, __shfl_xor_sync(0xffffffffu, rmax1, 1));
        rmax1 = fmaxf(rmax1, __shfl_xor_sync(0xffffffffu, rmax1, 2));

        float mnew0 = fmaxf(m0, rmax0), mnew1 = fmaxf(m1, rmax1);
        float sc0 = ex2(m0 - mnew0), sc1 = ex2(m1 - mnew1);

        // ---- 2^x; pack P directly into PV A-fragments ----
        float rsum0 = 0.f, rsum1 = 0.f;
        uint32_t ap[4][4];
        #pragma unroll
        for (int j = 0; j < 8; j++) {
            float p0 = ex2(sacc[j][0] - mnew0);
            float p1 = ex2(sacc[j][1] - mnew0);
            float p2 = ex2(sacc[j][2] - mnew1);
            float p3 = ex2(sacc[j][3] - mnew1);
            rsum0 += p0 + p1; rsum1 += p2 + p3;
            int kk = j >> 1, hi = j & 1;
            ap[kk][hi ? 2 : 0] = h2u(__floats2half2_rn(p0, p1));
            ap[kk][hi ? 3 : 1] = h2u(__floats2half2_rn(p2, p3));
        }
        rsum0 += __shfl_xor_sync(0xffffffffu, rsum0, 1);
        rsum0 += __shfl_xor_sync(0xffffffffu, rsum0, 2);
        rsum1 += __shfl_xor_sync(0xffffffffu, rsum1, 1);
        rsum1 += __shfl_xor_sync(0xffffffffu, rsum1, 2);

        l0 = l0 * sc0 + rsum0; m0 = mnew0;
        l1 = l1 * sc1 + rsum1; m1 = mnew1;
        #pragma unroll
        for (int j = 0; j < 8; j++) {
            oacc[j][0] *= sc0; oacc[j][1] *= sc0;
            oacc[j][2] *= sc1; oacc[j][3] *= sc1;
        }

        // ---- O += P @ V ----
        #pragma unroll
        for (int dp = 0; dp < 4; dp++) {
            uint32_t vaddr = vb + (uint32_t)(dp * 16) * 2u;
            #pragma unroll
            for (int kk = 0; kk < 4; kk++) {
                uint32_t b00, b01, b10, b11;
                LDMX4T(b00, b01, b10, b11, vaddr + (uint32_t)(kk * 16 * VP) * 2u);
                mma_f16(oacc[2*dp][0], oacc[2*dp][1], oacc[2*dp][2], oacc[2*dp][3],
                        ap[kk][0], ap[kk][1], ap[kk][2], ap[kk][3], b00, b01);
                mma_f16(oacc[2*dp+1][0], oacc[2*dp+1][1], oacc[2*dp+1][2], oacc[2*dp+1][3],
                        ap[kk][0], ap[kk][1], ap[kk][2], ap[kk][3], b10, b11);
            }
        }
    }

    // ---- finalize ----
    float inv0 = 1.0f / l0, inv1 = 1.0f / l1;
    __half* op = ctx + (size_t)(b * SEQ + qbase + wq) * D_MODEL + h * DK;
    #pragma unroll
    for (int j = 0; j < 8; j++) {
        int col = j * 8 + 2 * c4;
        *(__half2*)&op[(size_t)(r4    ) * D_MODEL + col] =
            __floats2half2_rn(oacc[j][0] * inv0, oacc[j][1] * inv0);
        *(__half2*)&op[(size_t)(r4 + 8) * D_MODEL + col] =
            __floats2half2_rn(oacc[j][2] * inv1, oacc[j][3] * inv1);
    }
}

// ---------------- launch ---------------------------------------------------
extern "C" void kernel_launch(void* const* d_in, const int* in_sizes, int n_in,
                              void* d_out, int out_size)
{
    const float* src  = (const float*)d_in[0];
    const int*   mask = (const int*)  d_in[1];
    const float* wq   = (const float*)d_in[2];
    const float* wk   = (const float*)d_in[3];
    const float* wv   = (const float*)d_in[4];
    const float* wo   = (const float*)d_in[5];
    const float* w1   = (const float*)d_in[6];
    const float* b1   = (const float*)d_in[7];
    const float* w2   = (const float*)d_in[8];
    const float* b2   = (const float*)d_in[9];
    const float* a1   = (const float*)d_in[10];
    const float* be1  = (const float*)d_in[11];
    const float* a2   = (const float*)d_in[12];
    const float* be2  = (const float*)d_in[13];
    float* out = (float*)d_out;

    __half *xln, *qb, *kb, *vb, *ctx, *x2, *ffh;
    __half *pwq, *pwk, *pwv, *pwo, *pw1, *pw2;
    float *out1;
    cudaGetSymbolAddress((void**)&xln,  h_xln);
    cudaGetSymbolAddress((void**)&qb,   h_q);
    cudaGetSymbolAddress((void**)&kb,   h_k);
    cudaGetSymbolAddress((void**)&vb,   h_v);
    cudaGetSymbolAddress((void**)&ctx,  h_ctx);
    cudaGetSymbolAddress((void**)&x2,   h_x2);
    cudaGetSymbolAddress((void**)&ffh,  h_ffh);
    cudaGetSymbolAddress((void**)&out1, g_out1);
    cudaGetSymbolAddress((void**)&pwq,  h_wq);
    cudaGetSymbolAddress((void**)&pwk,  h_wk);
    cudaGetSymbolAddress((void**)&pwv,  h_wv);
    cudaGetSymbolAddress((void**)&pwo,  h_wo);
    cudaGetSymbolAddress((void**)&pw1,  h_w1);
    cudaGetSymbolAddress((void**)&pw2,  h_w2);

    int gsm = GEMM_SMEM;
    cudaFuncSetAttribute(hgemm<0>, cudaFuncAttributeMaxDynamicSharedMemorySize, gsm);
    cudaFuncSetAttribute(hgemm<1>, cudaFuncAttributeMaxDynamicSharedMemorySize, gsm);
    cudaFuncSetAttribute(hgemm<2>, cudaFuncAttributeMaxDynamicSharedMemorySize, gsm);
    cudaFuncSetAttribute(hgemm<3>, cudaFuncAttributeMaxDynamicSharedMemorySize, gsm);
    cudaFuncSetAttribute(attn_mma, cudaFuncAttributeMaxDynamicSharedMemorySize, ATTN_SMEM);

    // 0) weights -> fp16
    round_weights<<<2048, 256>>>(
        (const float4*)wq, (const float4*)wk, (const float4*)wv, (const float4*)wo,
        (const float4*)w1, (const float4*)w2);

    // 1) LN1 -> half
    ln_kernel<<<MROWS, 256>>>(src, xln, a1, be1);

    // 2) QKV projections (half out; Q scaled by 0.125*log2e)
    hgemm<0><<<dim3(D_MODEL/GBN, MROWS/GBM, 3), 256, gsm>>>(
        xln, pwq, pwk, pwv, qb, kb, vb, nullptr, nullptr, MROWS, D_MODEL, D_MODEL);

    // 3) flash attention
    attn_mma<<<dim3(SEQ/BQ, NH, BATCH), 256, ATTN_SMEM>>>(qb, kb, vb, mask, ctx);

    // 4) O projection + residual (float out)
    hgemm<3><<<dim3(D_MODEL/GBN, MROWS/GBM, 1), 256, gsm>>>(
        ctx, pwo, pwo, pwo, out1, out1, out1, nullptr, src, MROWS, D_MODEL, D_MODEL);

    // 5) LN2 -> half
    ln_kernel<<<MROWS, 256>>>(out1, x2, a2, be2);

    // 6) FFN up (half out)
    hgemm<1><<<dim3(DFF/GBN, MROWS/GBM, 1), 256, gsm>>>(
        x2, pw1, pw1, pw1, ffh, ffh, ffh, b1, nullptr, MROWS, DFF, D_MODEL);

    // 7) FFN down + residual (float out)
    hgemm<2><<<dim3(D_MODEL/GBN, MROWS/GBM, 1), 256, gsm>>>(
        ffh, pw2, pw2, pw2, out, out, out, b2, out1, MROWS, D_MODEL, DFF);
}

// round 12
// speedup vs baseline: 7.3970x; 1.0506x over previous
#include <cuda_runtime.h>
#include <cuda_fp16.h>
#include <math.h>
#include <stdint.h>

#define D_MODEL 1024
#define NH      16
#define DK      64
#define DFF     4096
#define BATCH   2
#define SEQ     2048
#define MROWS   (BATCH*SEQ)   // 4096

// ---------------- scratch (device globals; no allocation allowed) ----------
__device__ __half h_xln[MROWS*D_MODEL];
__device__ __half h_q  [MROWS*D_MODEL];
__device__ __half h_k  [MROWS*D_MODEL];
__device__ __half h_v  [MROWS*D_MODEL];
__device__ __half h_ctx[MROWS*D_MODEL];
__device__ __half h_x2 [MROWS*D_MODEL];
__device__ __half h_ffh[MROWS*DFF];
__device__ float  g_out1[MROWS*D_MODEL];
// fp16 weights
__device__ __half h_wq[D_MODEL*D_MODEL];
__device__ __half h_wk[D_MODEL*D_MODEL];
__device__ __half h_wv[D_MODEL*D_MODEL];
__device__ __half h_wo[D_MODEL*D_MODEL];
__device__ __half h_w1[DFF*D_MODEL];
__device__ __half h_w2[D_MODEL*DFF];

// ---------------- helpers --------------------------------------------------
static __device__ __forceinline__ uint32_t smem_u32(const void* p) {
    uint32_t a;
    asm("{ .reg .u64 t; cvta.to.shared.u64 t, %1; cvt.u32.u64 %0, t; }"
        : "=r"(a) : "l"(p));
    return a;
}

static __device__ __forceinline__ uint32_t h2u(__half2 h) {
    union { __half2 h; uint32_t u; } x; x.h = h; return x.u;
}

static __device__ __forceinline__ float ex2(float x) {
    float y;
    asm("ex2.approx.ftz.f32 %0, %1;" : "=f"(y) : "f"(x));
    return y;
}

static __device__ __forceinline__ void mma_f16(
    float& c0, float& c1, float& c2, float& c3,
    uint32_t a0, uint32_t a1, uint32_t a2, uint32_t a3,
    uint32_t b0, uint32_t b1)
{
    asm volatile(
        "mma.sync.aligned.m16n8k16.row.col.f32.f16.f16.f32 "
        "{%0,%1,%2,%3}, {%4,%5,%6,%7}, {%8,%9}, {%0,%1,%2,%3};"
        : "+f"(c0), "+f"(c1), "+f"(c2), "+f"(c3)
        : "r"(a0), "r"(a1), "r"(a2), "r"(a3), "r"(b0), "r"(b1));
}

#define LDMX4(r0,r1,r2,r3,a) \
    asm volatile("ldmatrix.sync.aligned.m8n8.x4.shared.b16 {%0,%1,%2,%3}, [%4];" \
        : "=r"(r0),"=r"(r1),"=r"(r2),"=r"(r3) : "r"(a))
#define LDMX4T(r0,r1,r2,r3,a) \
    asm volatile("ldmatrix.sync.aligned.m8n8.x4.trans.shared.b16 {%0,%1,%2,%3}, [%4];" \
        : "=r"(r0),"=r"(r1),"=r"(r2),"=r"(r3) : "r"(a))

#define CP_ASYNC16(dst, src) \
    asm volatile("cp.async.cg.shared.global [%0], [%1], 16;" :: "r"(dst), "l"(src))

// 0.125 * log2(e): folded into Q so softmax is a bare ex2
#define QSCALE 0.18033688011112042f

// ---------------- weight conversion fp32 -> fp16 ---------------------------
#define WSEG  (D_MODEL*D_MODEL/4)
#define WBIG  (DFF*D_MODEL/4)
#define WTOT  (4*WSEG + 2*WBIG)

__global__ void round_weights(
    const float4* __restrict__ wq, const float4* __restrict__ wk,
    const float4* __restrict__ wv, const float4* __restrict__ wo,
    const float4* __restrict__ w1, const float4* __restrict__ w2)
{
    for (int i = blockIdx.x * blockDim.x + threadIdx.x; i < WTOT;
         i += gridDim.x * blockDim.x) {
        const float4* s; __half* d; int off;
        if      (i < 1*WSEG) { s = wq; d = h_wq; off = i; }
        else if (i < 2*WSEG) { s = wk; d = h_wk; off = i - 1*WSEG; }
        else if (i < 3*WSEG) { s = wv; d = h_wv; off = i - 2*WSEG; }
        else if (i < 4*WSEG) { s = wo; d = h_wo; off = i - 3*WSEG; }
        else if (i < 4*WSEG + WBIG) { s = w1; d = h_w1; off = i - 4*WSEG; }
        else                 { s = w2; d = h_w2; off = i - 4*WSEG - WBIG; }
        float4 v = s[off];
        *(__half2*)(d + 4*off)     = __floats2half2_rn(v.x, v.y);
        *(__half2*)(d + 4*off + 2) = __floats2half2_rn(v.z, v.w);
    }
}

// ======================= Tensor-core FP16 GEMM ============================
// C[M,N] = A[M,K] * B[N,K]^T; CTA 128x128x32; 8 warps 2x4 (warp 64x32);
// 3-stage cp.async; ldmatrix fragments; 2 CTAs/SM for latency hiding.
#define GBM 128
#define GBN 128
#define GBK 32
#define HP 40
#define A_HALVES (GBM*HP)
#define B_HALVES (GBN*HP)
#define STG_HALVES (A_HALVES + B_HALVES)         // 10240
#define NSTAGE 3
#define GEMM_SMEM (NSTAGE*STG_HALVES*2)          // 61440 B

// EPI: 0 = half store (*QSCALE when z==0), 1 = bias+relu half,
//      2 = bias+residual float, 3 = residual float
template<int EPI>
__global__ void __launch_bounds__(256, 2) hgemm(
    const __half* __restrict__ A,
    const __half* __restrict__ B0, const __half* __restrict__ B1, const __half* __restrict__ B2,
    void* __restrict__ C0, void* __restrict__ C1, void* __restrict__ C2,
    const float* __restrict__ bias, const float* __restrict__ res,
    int M, int N, int K)
{
    extern __shared__ __half smh[];
    uint32_t sbase = smem_u32(smh);

    const __half* Bm = B0; void* Cm = C0;
    if (blockIdx.z == 1) { Bm = B1; Cm = C1; }
    else if (blockIdx.z == 2) { Bm = B2; Cm = C2; }

    int tid  = threadIdx.x;
    int lane = tid & 31, wid = tid >> 5;
    int warp_m = (wid >> 2) * 64;      // 0 / 64
    int warp_n = (wid & 3) * 32;       // 0,32,64,96
    int rowBase = blockIdx.y * GBM;
    int colBase = blockIdx.x * GBN;
    int r4 = lane >> 2, c4 = lane & 3;
    int lg = lane >> 3, li = lane & 7;

    uint32_t aLm = (uint32_t)(((lg & 1) * 8 + li) * HP + (lg >> 1) * 8) * 2u;
    uint32_t bLm = (uint32_t)(((lg >> 1) * 8 + li) * HP + (lg & 1) * 8) * 2u;

    // loaders: A 512 chunks (2/thread), B 512 chunks (2/thread)
    const __half* Ag[2]; uint32_t aOff[2];
    #pragma unroll
    for (int j = 0; j < 2; j++) {
        int slot = tid + 256 * j;
        int r = slot >> 2, c = (slot & 3) * 8;
        Ag[j] = A + (size_t)(rowBase + r) * K + c;
        aOff[j] = (uint32_t)(r * HP + c) * 2u;
    }
    const __half* Bg[2]; uint32_t bOff[2];
    #pragma unroll
    for (int j = 0; j < 2; j++) {
        int slot = tid + 256 * j;
        int r = slot >> 2, c = (slot & 3) * 8;
        Bg[j] = Bm + (size_t)(colBase + r) * K + c;
        bOff[j] = (uint32_t)(r * HP + c) * 2u;
    }

    auto issue_tile = [&](int tt, int stage) {
        int k0 = tt * GBK;
        uint32_t sA = sbase + (uint32_t)stage * (STG_HALVES * 2u);
        uint32_t sB = sA + A_HALVES * 2u;
        #pragma unroll
        for (int j = 0; j < 2; j++) CP_ASYNC16(sA + aOff[j], Ag[j] + k0);
        #pragma unroll
        for (int j = 0; j < 2; j++) CP_ASYNC16(sB + bOff[j], Bg[j] + k0);
    };

    float acc[4][4][4];
    #pragma unroll
    for (int i = 0; i < 4; i++)
        #pragma unroll
        for (int j = 0; j < 4; j++)
            #pragma unroll
            for (int e = 0; e < 4; e++) acc[i][j][e] = 0.f;

    int T = K / GBK;
    issue_tile(0, 0);
    asm volatile("cp.async.commit_group;");
    issue_tile(1, 1);
    asm volatile("cp.async.commit_group;");

    int st_c = 0, st_l = 2;
    for (int t = 0; t < T; t++) {
        asm volatile("cp.async.wait_group 1;");
        __syncthreads();

        int nt = t + 2;
        int tt = (nt >= T) ? nt - T : nt;
        issue_tile(tt, st_l);
        asm volatile("cp.async.commit_group;");
        st_l = (st_l == 2) ? 0 : st_l + 1;

        uint32_t sA = sbase + (uint32_t)st_c * (STG_HALVES * 2u);
        uint32_t sB = sA + A_HALVES * 2u;
        st_c = (st_c == 2) ? 0 : st_c + 1;

        uint32_t aBase = sA + aLm + (uint32_t)(warp_m * HP) * 2u;
        uint32_t bBase = sB + bLm + (uint32_t)(warp_n * HP) * 2u;

        #pragma unroll
        for (int kk = 0; kk < 2; kk++) {
            uint32_t kByte = (uint32_t)(kk * 16) * 2u;
            uint32_t af[4][4], bf[4][2];
            #pragma unroll
            for (int i = 0; i < 4; i++)
                LDMX4(af[i][0], af[i][1], af[i][2], af[i][3],
                      aBase + (uint32_t)(i * 16 * HP) * 2u + kByte);
            #pragma unroll
            for (int jp = 0; jp < 2; jp++)
                LDMX4(bf[2*jp][0], bf[2*jp][1], bf[2*jp+1][0], bf[2*jp+1][1],
                      bBase + (uint32_t)(jp * 16 * HP) * 2u + kByte);
            #pragma unroll
            for (int i = 0; i < 4; i++)
                #pragma unroll
                for (int j = 0; j < 4; j++)
                    mma_f16(acc[i][j][0], acc[i][j][1], acc[i][j][2], acc[i][j][3],
                            af[i][0], af[i][1], af[i][2], af[i][3],
                            bf[j][0], bf[j][1]);
        }
    }

    float qs = 1.0f;
    if (EPI == 0 && blockIdx.z == 0) qs = QSCALE;

    #pragma unroll
    for (int i = 0; i < 4; i++) {
        int row = rowBase + warp_m + i * 16 + r4;
        #pragma unroll
        for (int j = 0; j < 4; j++) {
            int col = colBase + warp_n + j * 8 + c4 * 2;
            float2 lo = make_float2(acc[i][j][0], acc[i][j][1]);
            float2 hi = make_float2(acc[i][j][2], acc[i][j][3]);
            if (EPI == 0) {
                __half* Ch = (__half*)Cm;
                *(__half2*)&Ch[(size_t)row * N + col] =
                    __floats2half2_rn(lo.x * qs, lo.y * qs);
                *(__half2*)&Ch[(size_t)(row + 8) * N + col] =
                    __floats2half2_rn(hi.x * qs, hi.y * qs);
            } else if (EPI == 1) {
                float2 bi = *(const float2*)&bias[col];
                __half* Ch = (__half*)Cm;
                *(__half2*)&Ch[(size_t)row * N + col] =
                    __floats2half2_rn(fmaxf(lo.x + bi.x, 0.f), fmaxf(lo.y + bi.y, 0.f));
                *(__half2*)&Ch[(size_t)(row + 8) * N + col] =
                    __floats2half2_rn(fmaxf(hi.x + bi.x, 0.f), fmaxf(hi.y + bi.y, 0.f));
            } else if (EPI == 2) {
                float2 bi = *(const float2*)&bias[col];
                float2 r0 = *(const float2*)&res[(size_t)row * N + col];
                float2 r1 = *(const float2*)&res[(size_t)(row + 8) * N + col];
                float* Cf = (float*)Cm;
                *(float2*)&Cf[(size_t)row * N + col] =
                    make_float2(lo.x + bi.x + r0.x, lo.y + bi.y + r0.y);
                *(float2*)&Cf[(size_t)(row + 8) * N + col] =
                    make_float2(hi.x + bi.x + r1.x, hi.y + bi.y + r1.y);
            } else {
                float2 r0 = *(const float2*)&res[(size_t)row * N + col];
                float2 r1 = *(const float2*)&res[(size_t)(row + 8) * N + col];
                float* Cf = (float*)Cm;
                *(float2*)&Cf[(size_t)row * N + col]       = make_float2(lo.x + r0.x, lo.y + r0.y);
                *(float2*)&Cf[(size_t)(row + 8) * N + col] = make_float2(hi.x + r1.x, hi.y + r1.y);
            }
        }
    }
}

// ---------------- LayerNorm (torch: ddof=1, eps added to std) --------------
__global__ void __launch_bounds__(256) ln_kernel(
    const float* __restrict__ x, __half* __restrict__ y,
    const float* __restrict__ alpha, const float* __restrict__ beta)
{
    int row = blockIdx.x;
    const float4* xr = (const float4*)(x + (size_t)row * D_MODEL);
    float4 v = xr[threadIdx.x];
    float s  = v.x + v.y + v.z + v.w;
    float sq = v.x*v.x + v.y*v.y + v.z*v.z + v.w*v.w;

    __shared__ float red[18];
    #pragma unroll
    for (int o = 16; o; o >>= 1) {
        s  += __shfl_xor_sync(0xffffffffu, s,  o);
        sq += __shfl_xor_sync(0xffffffffu, sq, o);
    }
    int w = threadIdx.x >> 5;
    if ((threadIdx.x & 31) == 0) { red[w] = s; red[8 + w] = sq; }
    __syncthreads();
    if (threadIdx.x == 0) {
        float ts = 0.f, tq = 0.f;
        #pragma unroll
        for (int i = 0; i < 8; i++) { ts += red[i]; tq += red[8 + i]; }
        red[16] = ts; red[17] = tq;
    }
    __syncthreads();
    float ts = red[16], tq = red[17];

    float mean = ts * (1.0f / D_MODEL);
    float var  = (tq - ts * mean) * (1.0f / (D_MODEL - 1));
    var = fmaxf(var, 0.0f);
    float denom = sqrtf(var) + 1e-6f;
    float a  = alpha[0], be = beta[0];
    float r  = a / denom;

    __half* yr = y + (size_t)row * D_MODEL + threadIdx.x * 4;
    *(__half2*)(yr)     = __floats2half2_rn((v.x - mean) * r + be, (v.y - mean) * r + be);
    *(__half2*)(yr + 2) = __floats2half2_rn((v.z - mean) * r + be, (v.w - mean) * r + be);
}

// ============== Flash attention, fp16 mma + ldmatrix ======================
// 4-stage KV ring, single barrier per tile; Q pre-scaled; bare ex2 softmax.
#define BQ  128
#define BKV 64
#define NKV 4
#define QP  72
#define KP  72
#define VP  72
#define ATTN_SMEM ((BQ*QP + NKV*BKV*KP + NKV*BKV*VP)*2 + NKV*64*4 + 8*4)

__global__ void __launch_bounds__(256, 2) attn_mma(
    const __half* __restrict__ q, const __half* __restrict__ k,
    const __half* __restrict__ v, const int* __restrict__ mask,
    __half* __restrict__ ctx)
{
    extern __shared__ __half sa[];
    __half* Qs = sa;                       // [128][72]
    __half* Ks = Qs + BQ*QP;               // NKV x [64][72]
    __half* Vs = Ks + NKV*BKV*KP;          // NKV x [64][72]
    int*    ms = (int*)(Vs + NKV*BKV*VP);  // NKV x [64]
    int*    fl = ms + NKV*64;              // 2 flags per stage

    int tid = threadIdx.x, lane = tid & 31, wid = tid >> 5;
    int r4 = lane >> 2, c4 = lane & 3;
    int lg = lane >> 3, li = lane & 7;
    int qt = blockIdx.x, h = blockIdx.y, b = blockIdx.z;
    int qbase = qt * BQ;
    int wq = wid * 16;

    const __half* qp = q + (size_t)(b * SEQ) * D_MODEL + h * DK;
    const __half* kp = k + (size_t)(b * SEQ) * D_MODEL + h * DK;
    const __half* vp = v + (size_t)(b * SEQ) * D_MODEL + h * DK;
    const int* maskb = mask + b * SEQ;

    uint32_t kLm = (uint32_t)(((lg >> 1) * 8 + li) * KP + (lg & 1) * 8) * 2u;
    uint32_t vLm = (uint32_t)(((lg & 1) * 8 + li) * VP + (lg >> 1) * 8) * 2u;

    #pragma unroll
    for (int i = 0; i < 4; i++) {
        int slot = tid + i * 256;
        int r = slot >> 3, c = (slot & 7) * 8;
        *(uint4*)&Qs[r * QP + c] = *(const uint4*)(qp + (size_t)(qbase + r) * D_MODEL + c);
    }

    uint32_t ksb = smem_u32(Ks), vsb = smem_u32(Vs);
    auto issue = [&](int tt) {
        int buf = tt & (NKV - 1), kv0 = tt * BKV;
        #pragma unroll
        for (int i = 0; i < 4; i++) {
            int slot = tid + i * 256;
            int r = (slot & 511) >> 3, c = (slot & 7) * 8;
            if (slot < 512)
                CP_ASYNC16(ksb + (uint32_t)(buf*BKV*KP + r*KP + c)*2u,
                           kp + (size_t)(kv0 + r) * D_MODEL + c);
            else
                CP_ASYNC16(vsb + (uint32_t)(buf*BKV*VP + r*VP + c)*2u,
                           vp + (size_t)(kv0 + r) * D_MODEL + c);
        }
        asm volatile("cp.async.commit_group;");
    };

    issue(0);
    issue(1);
    issue(2);
    if (tid < 192) {
        int m = maskb[tid];
        ms[tid] = m;
        int all = __all_sync(0xffffffffu, m != 0);
        if ((tid & 31) == 0) fl[tid >> 5] = all;
    }
    __syncthreads();

    uint32_t afq[4][4];
    {
        const __half* qrow = Qs + wq * QP + 2 * c4;
        #pragma unroll
        for (int kk = 0; kk < 4; kk++) {
            int k16 = kk * 16;
            afq[kk][0] = h2u(*(const __half2*)(qrow + (r4    ) * QP + k16));
            afq[kk][1] = h2u(*(const __half2*)(qrow + (r4 + 8) * QP + k16));
            afq[kk][2] = h2u(*(const __half2*)(qrow + (r4    ) * QP + k16 + 8));
            afq[kk][3] = h2u(*(const __half2*)(qrow + (r4 + 8) * QP + k16 + 8));
        }
    }

    float m0 = -1e30f, m1 = -1e30f, l0 = 0.f, l1 = 0.f;
    float oacc[8][4];
    #pragma unroll
    for (int j = 0; j < 8; j++)
        #pragma unroll
        for (int e = 0; e < 4; e++) oacc[j][e] = 0.f;

    const int T = SEQ / BKV;   // 32
    for (int t = 0; t < T; t++) {
        int buf = t & (NKV - 1);
        asm volatile("cp.async.wait_group 2;");
        __syncthreads();

        if (t + 3 < T) {
            issue(t + 3);
            if (tid < 64) {
                int st = (t + 3) & (NKV - 1);
                int m = maskb[(t + 3) * BKV + tid];
                ms[st * 64 + tid] = m;
                int all = __all_sync(0xffffffffu, m != 0);
                if ((tid & 31) == 0) fl[st * 2 + (tid >> 5)] = all;
            }
        }

        uint32_t kb = ksb + (uint32_t)(buf * BKV * KP) * 2u + kLm;
        uint32_t vb = vsb + (uint32_t)(buf * BKV * VP) * 2u + vLm;
        const int* mb = ms + buf * 64;
        bool allone = fl[buf * 2] && fl[buf * 2 + 1];

        float sacc[8][4];
        #pragma unroll
        for (int j = 0; j < 8; j++)
            #pragma unroll
            for (int e = 0; e < 4; e++) sacc[j][e] = 0.f;

        #pragma unroll
        for (int jp = 0; jp < 4; jp++) {
            uint32_t kaddr = kb + (uint32_t)(jp * 16 * KP) * 2u;
            #pragma unroll
            for (int kk = 0; kk < 4; kk++) {
                uint32_t b00, b01, b10, b11;
                LDMX4(b00, b01, b10, b11, kaddr + (uint32_t)(kk * 16) * 2u);
                mma_f16(sacc[2*jp][0], sacc[2*jp][1], sacc[2*jp][2], sacc[2*jp][3],
                        afq[kk][0], afq[kk][1], afq[kk][2], afq[kk][3], b00, b01);
                mma_f16(sacc[2*jp+1][0], sacc[2*jp+1][1], sacc[2*jp+1][2], sacc[2*jp+1][3],
                        afq[kk][0], afq[kk][1], afq[kk][2], afq[kk][3], b10, b11);
            }
        }

        if (!allone) {
            #pragma unroll
            for (int j = 0; j < 8; j++) {
                int col = j * 8 + 2 * c4;
                int mk0 = mb[col], mk1 = mb[col + 1];
                if (!mk0) { sacc[j][0] = -1e9f; sacc[j][2] = -1e9f; }
                if (!mk1) { sacc[j][1] = -1e9f; sacc[j][3] = -1e9f; }
            }
        }

        float rmax0 = -1e30f, rmax1 = -1e30f;
        #pragma unroll
        for (int j = 0; j < 8; j++) {
            rmax0 = fmaxf(rmax0, fmaxf(sacc[j][0], sacc[j][1]));
            rmax1 = fmaxf(rmax1, fmaxf(sacc[j][2], sacc[j][3]));
        }
        rmax0 = fmaxf(rmax0, __shfl_xor_sync(0xffffffffu, rmax0, 1));
        rmax0 = fmaxf(rmax0, __shfl_xor_sync(0xffffffffu, rmax0, 2));
        rmax1 = fmaxf(rmax1, __shfl_xor_sync(0xffffffffu, rmax1, 1));
        rmax1 = fmaxf(rmax1, __shfl_xor_sync(0xffffffffu, rmax1, 2));

        float mnew0 = fmaxf(m0, rmax0), mnew1 = fmaxf(m1, rmax1);
        float sc0 = ex2(m0 - mnew0), sc1 = ex2(m1 - mnew1);

        float rsum0 = 0.f, rsum1 = 0.f;
        uint32_t ap[4][4];
        #pragma unroll
        for (int j = 0; j < 8; j++) {
            float p0 = ex2(sacc[j][0] - mnew0);
            float p1 = ex2(sacc[j][1] - mnew0);
            float p2 = ex2(sacc[j][2] - mnew1);
            float p3 = ex2(sacc[j][3] - mnew1);
            rsum0 += p0 + p1; rsum1 += p2 + p3;
            int kk = j >> 1, hi = j & 1;
            ap[kk][hi ? 2 : 0] = h2u(__floats2half2_rn(p0, p1));
            ap[kk][hi ? 3 : 1] = h2u(__floats2half2_rn(p2, p3));
        }
        rsum0 += __shfl_xor_sync(0xffffffffu, rsum0, 1);
        rsum0 += __shfl_xor_sync(0xffffffffu, rsum0, 2);
        rsum1 += __shfl_xor_sync(0xffffffffu, rsum1, 1);
        rsum1 += __shfl_xor_sync(0xffffffffu, rsum1, 2);

        l0 = l0 * sc0 + rsum0; m0 = mnew0;
        l1 = l1 * sc1 + rsum1; m1 = mnew1;
        #pragma unroll
        for (int j = 0; j < 8; j++) {
            oacc[j][0] *= sc0; oacc[j][1] *= sc0;
            oacc[j][2] *= sc1; oacc[j][3] *= sc1;
        }

        #pragma unroll
        for (int dp = 0; dp < 4; dp++) {
            uint32_t vaddr = vb + (uint32_t)(dp * 16) * 2u;
            #pragma unroll
            for (int kk = 0; kk < 4; kk++) {
                uint32_t b00, b01, b10, b11;
                LDMX4T(b00, b01, b10, b11, vaddr + (uint32_t)(kk * 16 * VP) * 2u);
                mma_f16(oacc[2*dp][0], oacc[2*dp][1], oacc[2*dp][2], oacc[2*dp][3],
                        ap[kk][0], ap[kk][1], ap[kk][2], ap[kk][3], b00, b01);
                mma_f16(oacc[2*dp+1][0], oacc[2*dp+1][1], oacc[2*dp+1][2], oacc[2*dp+1][3],
                        ap[kk][0], ap[kk][1], ap[kk][2], ap[kk][3], b10, b11);
            }
        }
    }

    float inv0 = 1.0f / l0, inv1 = 1.0f / l1;
    __half* op = ctx + (size_t)(b * SEQ + qbase + wq) * D_MODEL + h * DK;
    #pragma unroll
    for (int j = 0; j < 8; j++) {
        int col = j * 8 + 2 * c4;
        *(__half2*)&op[(size_t)(r4    ) * D_MODEL + col] =
            __floats2half2_rn(oacc[j][0] * inv0, oacc[j][1] * inv0);
        *(__half2*)&op[(size_t)(r4 + 8) * D_MODEL + col] =
            __floats2half2_rn(oacc[j][2] * inv1, oacc[j][3] * inv1);
    }
}

// ---------------- launch ---------------------------------------------------
extern "C" void kernel_launch(void* const* d_in, const int* in_sizes, int n_in,
                              void* d_out, int out_size)
{
    const float* src  = (const float*)d_in[0];
    const int*   mask = (const int*)  d_in[1];
    const float* wq   = (const float*)d_in[2];
    const float* wk   = (const float*)d_in[3];
    const float* wv   = (const float*)d_in[4];
    const float* wo   = (const float*)d_in[5];
    const float* w1   = (const float*)d_in[6];
    const float* b1   = (const float*)d_in[7];
    const float* w2   = (const float*)d_in[8];
    const float* b2   = (const float*)d_in[9];
    const float* a1   = (const float*)d_in[10];
    const float* be1  = (const float*)d_in[11];
    const float* a2   = (const float*)d_in[12];
    const float* be2  = (const float*)d_in[13];
    float* out = (float*)d_out;

    __half *xln, *qb, *kb, *vb, *ctx, *x2, *ffh;
    __half *pwq, *pwk, *pwv, *pwo, *pw1, *pw2;
    float *out1;
    cudaGetSymbolAddress((void**)&xln,  h_xln);
    cudaGetSymbolAddress((void**)&qb,   h_q);
    cudaGetSymbolAddress((void**)&kb,   h_k);
    cudaGetSymbolAddress((void**)&vb,   h_v);
    cudaGetSymbolAddress((void**)&ctx,  h_ctx);
    cudaGetSymbolAddress((void**)&x2,   h_x2);
    cudaGetSymbolAddress((void**)&ffh,  h_ffh);
    cudaGetSymbolAddress((void**)&out1, g_out1);
    cudaGetSymbolAddress((void**)&pwq,  h_wq);
    cudaGetSymbolAddress((void**)&pwk,  h_wk);
    cudaGetSymbolAddress((void**)&pwv,  h_wv);
    cudaGetSymbolAddress((void**)&pwo,  h_wo);
    cudaGetSymbolAddress((void**)&pw1,  h_w1);
    cudaGetSymbolAddress((void**)&pw2,  h_w2);

    int gsm = GEMM_SMEM;
    cudaFuncSetAttribute(hgemm<0>, cudaFuncAttributeMaxDynamicSharedMemorySize, gsm);
    cudaFuncSetAttribute(hgemm<1>, cudaFuncAttributeMaxDynamicSharedMemorySize, gsm);
    cudaFuncSetAttribute(hgemm<2>, cudaFuncAttributeMaxDynamicSharedMemorySize, gsm);
    cudaFuncSetAttribute(hgemm<3>, cudaFuncAttributeMaxDynamicSharedMemorySize, gsm);
    cudaFuncSetAttribute(attn_mma, cudaFuncAttributeMaxDynamicSharedMemorySize, ATTN_SMEM);

    // 0) weights -> fp16
    round_weights<<<2048, 256>>>(
        (const float4*)wq, (const float4*)wk, (const float4*)wv, (const float4*)wo,
        (const float4*)w1, (const float4*)w2);

    // 1) LN1 -> half
    ln_kernel<<<MROWS, 256>>>(src, xln, a1, be1);

    // 2) QKV projections (half out; Q scaled by 0.125*log2e)
    hgemm<0><<<dim3(D_MODEL/GBN, MROWS/GBM, 3), 256, gsm>>>(
        xln, pwq, pwk, pwv, qb, kb, vb, nullptr, nullptr, MROWS, D_MODEL, D_MODEL);

    // 3) flash attention
    attn_mma<<<dim3(SEQ/BQ, NH, BATCH), 256, ATTN_SMEM>>>(qb, kb, vb, mask, ctx);

    // 4) O projection + residual (float out)
    hgemm<3><<<dim3(D_MODEL/GBN, MROWS/GBM, 1), 256, gsm>>>(
        ctx, pwo, pwo, pwo, out1, out1, out1, nullptr, src, MROWS, D_MODEL, D_MODEL);

    // 5) LN2 -> half
    ln_kernel<<<MROWS, 256>>>(out1, x2, a2, be2);

    // 6) FFN up (half out)
    hgemm<1><<<dim3(DFF/GBN, MROWS/GBM, 1), 256, gsm>>>(
        x2, pw1, pw1, pw1, ffh, ffh, ffh, b1, nullptr, MROWS, DFF, D_MODEL);

    // 7) FFN down + residual (float out)
    hgemm<2><<<dim3(D_MODEL/GBN, MROWS/GBM, 1), 256, gsm>>>(
        ffh, pw2, pw2, pw2, out, out, out, b2, out1, MROWS, D_MODEL, DFF);
}